// round 8
// baseline (speedup 1.0000x reference)
#include <cuda_runtime.h>
#include <cstdint>

// ===========================================================================
// LossRecovery via mma.sync tf32. NT=64 tiles (low reg pressure), 4-stage
// cp.async pipeline, 2 CTAs/SM, consumer-side 3xTF32, split-K=4 scores.
//
// Unified NT GEMM: C[m,n] = sum_k A[m,k] * B[n,k]
//   AMODE 0: plain rows   1: spatial-transpose row gather (tk)
//   AMODE 2: v2 reshape gather (tv out-GEMM)
//   EMODE 0: plain+bias   1: transposed [c][s]+bias   2: scores (split-K)
//   EMODE 3: gamma*acc + res
// ===========================================================================

__device__ float g_xc[65536L * 256];         // compacted x_s
__device__ float g_q[16L * 256 * 4096];      // qT [z][c][s]
__device__ float g_k[16L * 256 * 4096];      // kT [z][d][s]
__device__ float g_v[16L * 4096 * 256];      // v  [z][s][d]
__device__ float g_attn[64L * 65536];        // 4 split-K partials

#define CP16(dst, src) asm volatile("cp.async.cg.shared.global [%0], [%1], 16;\n" :: "r"(dst), "l"(src))
#define CP4(dst, src)  asm volatile("cp.async.ca.shared.global [%0], [%1], 4;\n"  :: "r"(dst), "l"(src))
#define CPCOMMIT()     asm volatile("cp.async.commit_group;\n" ::: "memory")
#define CPWAIT(n)      asm volatile("cp.async.wait_group %0;\n" :: "n"(n) : "memory")

__device__ __forceinline__ void split32(float v, uint32_t& h, uint32_t& l) {
    uint32_t hu = __float_as_uint(v) & 0xFFFFE000u;
    h = hu;
    l = __float_as_uint(v - __uint_as_float(hu));
}

#define MMA_T(ac, a0, a1, a2, a3, b0, b1) \
    asm volatile("mma.sync.aligned.m16n8k8.row.col.f32.tf32.tf32.f32 " \
        "{%0,%1,%2,%3},{%4,%5,%6,%7},{%8,%9},{%0,%1,%2,%3};" \
        : "+f"((ac)[0]), "+f"((ac)[1]), "+f"((ac)[2]), "+f"((ac)[3]) \
        : "r"(a0), "r"(a1), "r"(a2), "r"(a3), "r"(b0), "r"(b1))

// 128 (M) x 64 (N) block tile, 8 warps: warp = (m 32-slab, n 32-slab)
template <bool THREE, int AMODE, int EMODE>
__global__ __launch_bounds__(256, 2) void gemm_tc(
    const float* __restrict__ A, int lda, long aZ,
    const float* __restrict__ B, int ldb, long bZ,
    int Kdim,
    const float* __restrict__ bias,
    const float* __restrict__ gammaPtr,
    const float* __restrict__ res, int ldr,
    float* __restrict__ out)
{
    extern __shared__ float sm[];
    constexpr int ALD = 36;
    constexpr int STAGE = (128 + 64) * ALD;          // 6912 floats / 27648 B
    const uint32_t sbB = (uint32_t)__cvta_generic_to_shared(sm);

    const int tid = threadIdx.x;
    const int wid = tid >> 5, lane = tid & 31;
    const int grp = lane >> 2, tig = lane & 3;
    const int row0 = blockIdx.x * 128, col0 = blockIdx.y * 64;
    const int z = blockIdx.z;
    int zA = z;
    long koff = 0;
    if (EMODE == 2) { zA = z & 15; koff = (long)(z >> 4) * Kdim; }

    const int m_base = (wid >> 1) * 32;
    const int n_base = (wid & 1) * 32;

    float acc[2][4][4];
#pragma unroll
    for (int mi = 0; mi < 2; mi++)
#pragma unroll
        for (int ni = 0; ni < 4; ni++)
#pragma unroll
            for (int e = 0; e < 4; e++) acc[mi][ni][e] = 0.f;

    // ---- A loader: row ar (0..127), 16-col half ha ----
    const int ar = tid >> 1, ha = (tid & 1) * 16;
    const float* ap = nullptr;
    const float* base0 = nullptr;
    if (AMODE == 0) {
        ap = A + (long)zA * aZ + (long)(row0 + ar) * lda + koff;
    } else if (AMODE == 1) {
        const int grow = row0 + ar;
        const int t = grow & 4095;
        const int s = ((t & 63) << 6) | (t >> 6);
        ap = A + ((long)(grow >> 12) * 4096 + s) * (long)lda;
    } else {
        const int bq = z >> 3, chHi = z & 7;
        base0 = A + ((long)(bq * 8) * 4096 + (row0 + ar)) * 256 + chHi * 32;
    }
    // ---- B loader: 64 rows, 4 threads/row, 8 floats each ----
    const int bn = tid >> 2, hb = (tid & 3) * 8;
    const float* bp = B + (long)zA * bZ + (long)(col0 + bn) * ldb + hb + koff;

    const int nCh = Kdim >> 5;

    auto load_tile = [&](int kc, int s) {
        const int kb = kc << 5;
        const uint32_t aD = sbB + (uint32_t)(s * STAGE + ar * ALD + ha) * 4u;
        if (AMODE == 2) {
#pragma unroll
            for (int i = 0; i < 16; i++) {
                const int d = kb + ha + i;
                CP4(aD + i * 4u, base0 + (long)(d & 7) * 1048576 + (d >> 3));
            }
        } else {
#pragma unroll
            for (int j = 0; j < 4; j++) CP16(aD + j * 16u, ap + kb + ha + 4 * j);
        }
        const uint32_t bD = sbB + (uint32_t)(s * STAGE + 128 * ALD + bn * ALD + hb) * 4u;
#pragma unroll
        for (int j = 0; j < 2; j++) CP16(bD + j * 16u, bp + kb + 4 * j);
    };

    // prologue: stages 0,1,2
    load_tile(0, 0); CPCOMMIT();
    load_tile(1, 1); CPCOMMIT();
    load_tile(2, 2); CPCOMMIT();

    for (int kc = 0; kc < nCh; kc++) {
        CPWAIT(2);
        __syncthreads();
        const int ld = kc + 3;
        if (ld < nCh) load_tile(ld, ld & 3);
        CPCOMMIT();

        const float* sA = sm + (kc & 3) * STAGE;
        const float* sB = sA + 128 * ALD;
#pragma unroll
        for (int ks = 0; ks < 4; ks++) {
            const int kk = ks * 8;
            uint32_t bh[4][2], blo[4][2];
#pragma unroll
            for (int ni = 0; ni < 4; ni++) {
                const int nb = n_base + ni * 8 + grp;
                const float b0 = sB[nb * ALD + kk + tig];
                const float b1 = sB[nb * ALD + kk + tig + 4];
                if (THREE) {
                    split32(b0, bh[ni][0], blo[ni][0]);
                    split32(b1, bh[ni][1], blo[ni][1]);
                } else {
                    bh[ni][0] = __float_as_uint(b0);
                    bh[ni][1] = __float_as_uint(b1);
                }
            }
#pragma unroll
            for (int mi = 0; mi < 2; mi++) {
                const int mb = m_base + mi * 16;
                const float a0 = sA[(mb + grp) * ALD + kk + tig];
                const float a1 = sA[(mb + grp + 8) * ALD + kk + tig];
                const float a2 = sA[(mb + grp) * ALD + kk + tig + 4];
                const float a3 = sA[(mb + grp + 8) * ALD + kk + tig + 4];
                uint32_t ah[4], al[4];
                if (THREE) {
                    split32(a0, ah[0], al[0]); split32(a1, ah[1], al[1]);
                    split32(a2, ah[2], al[2]); split32(a3, ah[3], al[3]);
                } else {
                    ah[0] = __float_as_uint(a0); ah[1] = __float_as_uint(a1);
                    ah[2] = __float_as_uint(a2); ah[3] = __float_as_uint(a3);
                }
#pragma unroll
                for (int ni = 0; ni < 4; ni++)
                    MMA_T(acc[mi][ni], ah[0], ah[1], ah[2], ah[3], bh[ni][0], bh[ni][1]);
                if (THREE) {
#pragma unroll
                    for (int ni = 0; ni < 4; ni++)
                        MMA_T(acc[mi][ni], ah[0], ah[1], ah[2], ah[3], blo[ni][0], blo[ni][1]);
#pragma unroll
                    for (int ni = 0; ni < 4; ni++)
                        MMA_T(acc[mi][ni], al[0], al[1], al[2], al[3], bh[ni][0], bh[ni][1]);
                }
            }
        }
    }

    // ---- epilogues ----
    if (EMODE == 1) {
        __syncthreads();                 // done reading pipeline smem
        float* sC = sm;                  // 128 x 64, stride 69 (conflict-free cols)
#pragma unroll
        for (int mi = 0; mi < 2; mi++)
#pragma unroll
            for (int ni = 0; ni < 4; ni++) {
                const int r0 = m_base + mi * 16 + grp;
                const int cb = n_base + ni * 8 + 2 * tig;
                sC[r0 * 69 + cb] = acc[mi][ni][0];
                sC[r0 * 69 + cb + 1] = acc[mi][ni][1];
                sC[(r0 + 8) * 69 + cb] = acc[mi][ni][2];
                sC[(r0 + 8) * 69 + cb + 1] = acc[mi][ni][3];
            }
        __syncthreads();
        const int rw = tid & 127, g2 = tid >> 7;
        const int bl = row0 >> 12, sb = row0 & 4095;
        for (int cp = 0; cp < 32; cp++) {
            const int col = cp * 2 + g2;
            const int ch = col0 + col;
            const float val = sC[rw * 69 + col] + __ldg(&bias[ch]);
            out[((long)bl * 256 + ch) * 4096 + sb + rw] = val;
        }
    } else {
        float gamma = 0.f;
        if (EMODE == 3) gamma = __ldg(gammaPtr);
#pragma unroll
        for (int mi = 0; mi < 2; mi++)
#pragma unroll
            for (int ni = 0; ni < 4; ni++) {
                const int r0g = m_base + mi * 16 + grp;
                const int cb = n_base + ni * 8 + 2 * tig;
                const int c = col0 + cb;
#pragma unroll
                for (int half = 0; half < 2; half++) {
                    const int r = row0 + r0g + half * 8;
                    float v0 = acc[mi][ni][2 * half];
                    float v1 = acc[mi][ni][2 * half + 1];
                    if (EMODE == 0) {
                        v0 += __ldg(&bias[c]);
                        v1 += __ldg(&bias[c + 1]);
                        float2 st = {v0, v1};
                        *(float2*)(out + (long)r * 256 + c) = st;
                    } else if (EMODE == 2) {
                        float2 st = {v0, v1};
                        *(float2*)(out + (long)z * 65536 + (long)r * 256 + c) = st;
                    } else {
                        const long rr = (long)z * 4096 + r;
                        v0 = gamma * v0 + res[rr * (long)ldr + c];
                        v1 = gamma * v1 + res[rr * (long)ldr + c + 1];
                        float2 st = {v0, v1};
                        *(float2*)(out + rr * 256 + c) = st;
                    }
                }
            }
    }
}

// ---------------- compact x[..., :256] -> aligned [65536][256] ----------------
__global__ __launch_bounds__(1024) void compact_x(const float* __restrict__ x,
                                                  float* __restrict__ xc) {
    const long i = (long)blockIdx.x * 1024 + threadIdx.x;
    const long r = i >> 8;
    const int c = (int)(i & 255);
    xc[i] = x[r * 259 + c];
}

// ---------------- softmax over 4 split-K partials ----------------
__global__ __launch_bounds__(256) void softmax_rows(float* __restrict__ data) {
    const int row = blockIdx.x * 8 + (threadIdx.x >> 5);
    const int lane = threadIdx.x & 31;
    float* p0 = data + (long)row * 256;
    float vv[8];
    float m = -1e30f;
#pragma unroll
    for (int i = 0; i < 8; i++) {
        const int c = i * 32 + lane;
        vv[i] = p0[c] + p0[c + 1048576L] + p0[c + 2097152L] + p0[c + 3145728L];
        m = fmaxf(m, vv[i]);
    }
#pragma unroll
    for (int o = 16; o; o >>= 1) m = fmaxf(m, __shfl_xor_sync(0xffffffffu, m, o));
    float s = 0.f;
#pragma unroll
    for (int i = 0; i < 8; i++) { vv[i] = __expf(vv[i] - m); s += vv[i]; }
#pragma unroll
    for (int o = 16; o; o >>= 1) s += __shfl_xor_sync(0xffffffffu, s, o);
    const float inv = 1.f / s;
#pragma unroll
    for (int i = 0; i < 8; i++) p0[i * 32 + lane] = vv[i] * inv;
}

// ---------------- launch ----------------
extern "C" void kernel_launch(void* const* d_in, const int* in_sizes, int n_in,
                              void* d_out, int out_size)
{
    const float* x    = (const float*)d_in[0];
    const float* sq_w = (const float*)d_in[3];
    const float* sq_b = (const float*)d_in[4];
    const float* sk_w = (const float*)d_in[5];
    const float* sk_b = (const float*)d_in[6];
    const float* sv_w = (const float*)d_in[7];
    const float* sv_b = (const float*)d_in[8];
    const float* tq_w = (const float*)d_in[9];
    const float* tq_b = (const float*)d_in[10];
    const float* tk_w = (const float*)d_in[11];
    const float* tk_b = (const float*)d_in[12];
    const float* tv_w = (const float*)d_in[13];
    const float* tv_b = (const float*)d_in[14];
    const float* s_gamma = (const float*)d_in[15];
    const float* t_gamma = (const float*)d_in[16];
    float* out = (float*)d_out;

    float *xc, *q, *k, *v, *attn;
    cudaGetSymbolAddress((void**)&xc, g_xc);
    cudaGetSymbolAddress((void**)&q, g_q);
    cudaGetSymbolAddress((void**)&k, g_k);
    cudaGetSymbolAddress((void**)&v, g_v);
    cudaGetSymbolAddress((void**)&attn, g_attn);

    auto convA  = gemm_tc<true, 0, 1>;    // sq, sk, tq (aligned rows)
    auto convKG = gemm_tc<true, 1, 1>;    // tk (gathered rows of xc)
    auto convV  = gemm_tc<false, 0, 0>;   // sv, tv
    auto scoreK = gemm_tc<true, 0, 2>;    // scores (split-K=4)
    auto outV1  = gemm_tc<false, 0, 3>;   // out spatial
    auto outV2  = gemm_tc<false, 2, 3>;   // out temporal (v2 gather)

    const int SMB = 4 * (128 + 64) * 36 * 4;   // 110592
    cudaFuncSetAttribute(convA,  cudaFuncAttributeMaxDynamicSharedMemorySize, SMB);
    cudaFuncSetAttribute(convKG, cudaFuncAttributeMaxDynamicSharedMemorySize, SMB);
    cudaFuncSetAttribute(convV,  cudaFuncAttributeMaxDynamicSharedMemorySize, SMB);
    cudaFuncSetAttribute(scoreK, cudaFuncAttributeMaxDynamicSharedMemorySize, SMB);
    cudaFuncSetAttribute(outV1,  cudaFuncAttributeMaxDynamicSharedMemorySize, SMB);
    cudaFuncSetAttribute(outV2,  cudaFuncAttributeMaxDynamicSharedMemorySize, SMB);

    const dim3 cg(512, 4, 1);
    const dim3 sg(2, 4, 64);    // split-K=4 -> 64 z-slices
    const dim3 og(32, 4, 16);

    compact_x<<<16384, 1024>>>(x, xc);

    // ---- spatial ----
    convA<<<cg, 256, SMB>>>(xc, 256, 0, sq_w, 256, 0, 256, sq_b, nullptr, nullptr, 0, q);
    convA<<<cg, 256, SMB>>>(xc, 256, 0, sk_w, 256, 0, 256, sk_b, nullptr, nullptr, 0, k);
    convV<<<cg, 256, SMB>>>(xc, 256, 0, sv_w, 256, 0, 256, sv_b, nullptr, nullptr, 0, v);
    scoreK<<<sg, 256, SMB>>>(q, 4096, 1048576L, k, 4096, 1048576L, 1024,
                             nullptr, nullptr, nullptr, 0, attn);
    softmax_rows<<<512, 256>>>(attn);
    outV1<<<og, 256, SMB>>>(v, 256, 1048576L, attn, 256, 65536L, 256,
                            nullptr, s_gamma, xc, 256, out);

    // ---- temporal ----
    convA<<<cg, 256, SMB>>>(out, 256, 0, tq_w, 256, 0, 256, tq_b, nullptr, nullptr, 0, q);
    convKG<<<cg, 256, SMB>>>(xc, 256, 0, tk_w, 256, 0, 256, tk_b, nullptr, nullptr, 0, k);
    convV<<<cg, 256, SMB>>>(xc, 256, 0, tv_w, 256, 0, 256, tv_b, nullptr, nullptr, 0, v);
    scoreK<<<sg, 256, SMB>>>(q, 4096, 1048576L, k, 4096, 1048576L, 1024,
                             nullptr, nullptr, nullptr, 0, attn);
    softmax_rows<<<512, 256>>>(attn);
    outV2<<<og, 256, SMB>>>(v, 0, 0, attn, 256, 65536L, 256,
                            nullptr, t_gamma, out, 256, out);
}

// round 9
// speedup vs baseline: 1.3799x; 1.3799x over previous
#include <cuda_runtime.h>
#include <cuda_bf16.h>
#include <cstdint>

// ===========================================================================
// LossRecovery via mma.sync. R7 skeleton (NT=128/64, 3-stage cp.async,
// 2 CTA/SM) with THREE paths switched from 3xTF32 (m16n8k8) to 2-term
// bf16 split (m16n8k16, 3 passes: AhBh + AhBl + AlBh) — half the tensor
// work at ~16-bit mantissa accuracy. Non-THREE paths stay 1-pass tf32.
// ===========================================================================

__device__ float g_xc[65536L * 256];         // compacted x_s
__device__ float g_q[16L * 256 * 4096];      // qT [z][c][s]
__device__ float g_k[16L * 256 * 4096];      // kT [z][d][s]
__device__ float g_v[16L * 4096 * 256];      // v  [z][s][d]
__device__ float g_attn[64L * 65536];        // 4 split-K partials

#define CP16(dst, src) asm volatile("cp.async.cg.shared.global [%0], [%1], 16;\n" :: "r"(dst), "l"(src))
#define CP4(dst, src)  asm volatile("cp.async.ca.shared.global [%0], [%1], 4;\n"  :: "r"(dst), "l"(src))
#define CPCOMMIT()     asm volatile("cp.async.commit_group;\n" ::: "memory")
#define CPWAIT(n)      asm volatile("cp.async.wait_group %0;\n" :: "n"(n) : "memory")

// pack two fp32 into bf16x2 (hi slot = v1, lo slot = v0) and produce the
// bf16x2 of the residuals.
__device__ __forceinline__ void split_bf16x2(float v0, float v1,
                                             uint32_t& h, uint32_t& l) {
    uint32_t hh;
    asm("cvt.rn.bf16x2.f32 %0, %1, %2;" : "=r"(hh) : "f"(v1), "f"(v0));
    const float h0 = __uint_as_float(hh << 16);
    const float h1 = __uint_as_float(hh & 0xFFFF0000u);
    const float r0 = v0 - h0;
    const float r1 = v1 - h1;
    asm("cvt.rn.bf16x2.f32 %0, %1, %2;" : "=r"(l) : "f"(r1), "f"(r0));
    h = hh;
}

#define MMA_TF32(ac, a0, a1, a2, a3, b0, b1) \
    asm volatile("mma.sync.aligned.m16n8k8.row.col.f32.tf32.tf32.f32 " \
        "{%0,%1,%2,%3},{%4,%5,%6,%7},{%8,%9},{%0,%1,%2,%3};" \
        : "+f"((ac)[0]), "+f"((ac)[1]), "+f"((ac)[2]), "+f"((ac)[3]) \
        : "r"(a0), "r"(a1), "r"(a2), "r"(a3), "r"(b0), "r"(b1))

#define MMA_BF16(ac, a0, a1, a2, a3, b0, b1) \
    asm volatile("mma.sync.aligned.m16n8k16.row.col.f32.bf16.bf16.f32 " \
        "{%0,%1,%2,%3},{%4,%5,%6,%7},{%8,%9},{%0,%1,%2,%3};" \
        : "+f"((ac)[0]), "+f"((ac)[1]), "+f"((ac)[2]), "+f"((ac)[3]) \
        : "r"(a0), "r"(a1), "r"(a2), "r"(a3), "r"(b0), "r"(b1))

template <bool THREE, int AMODE, int EMODE, int NT>
__global__ __launch_bounds__(256, 2) void gemm_tc(
    const float* __restrict__ A, int lda, long aZ,
    const float* __restrict__ B, int ldb, long bZ,
    int Kdim,
    const float* __restrict__ bias,
    const float* __restrict__ gammaPtr,
    const float* __restrict__ res, int ldr,
    float* __restrict__ out)
{
    extern __shared__ float sm[];
    constexpr int ALD = 36;
    constexpr int STAGE = (128 + NT) * ALD;
    const uint32_t sbB = (uint32_t)__cvta_generic_to_shared(sm);

    const int tid = threadIdx.x;
    const int wid = tid >> 5, lane = tid & 31;
    const int grp = lane >> 2, tig = lane & 3;
    const int row0 = blockIdx.x * 128, col0 = blockIdx.y * NT;
    const int z = blockIdx.z;
    int zA = z;
    long koff = 0;
    if (EMODE == 2) { zA = z & 15; koff = (long)(z >> 4) * Kdim; }

    constexpr int MI = (NT == 128) ? 4 : 2;
    const int m_base = (NT == 128) ? ((wid >> 2) * 64) : ((wid >> 1) * 32);
    const int n_base = (NT == 128) ? ((wid & 3) * 32) : ((wid & 1) * 32);

    float acc[MI][4][4];
#pragma unroll
    for (int mi = 0; mi < MI; mi++)
#pragma unroll
        for (int ni = 0; ni < 4; ni++)
#pragma unroll
            for (int e = 0; e < 4; e++) acc[mi][ni][e] = 0.f;

    // ---- A loader: row ar, 16-col half ha ----
    const int ar = tid >> 1, ha = (tid & 1) * 16;
    const float* ap = nullptr;
    const float* base0 = nullptr;
    if (AMODE == 0) {
        ap = A + (long)zA * aZ + (long)(row0 + ar) * lda + koff;
    } else if (AMODE == 1) {
        const int grow = row0 + ar;
        const int t = grow & 4095;
        const int s = ((t & 63) << 6) | (t >> 6);
        ap = A + ((long)(grow >> 12) * 4096 + s) * (long)lda;
    } else {
        const int bq = z >> 3, chHi = z & 7;
        base0 = A + ((long)(bq * 8) * 4096 + (row0 + ar)) * 256 + chHi * 32;
    }
    // ---- B loader ----
    constexpr int TPR = 256 / NT, NF = 32 / TPR;
    const int bn = tid / TPR, hb = (tid % TPR) * NF;
    const float* bp = B + (long)zA * bZ + (long)(col0 + bn) * ldb + hb + koff;

    const int nCh = Kdim >> 5;

    auto load_tile = [&](int kc, int s) {
        const int kb = kc << 5;
        const uint32_t aD = sbB + (uint32_t)(s * STAGE + ar * ALD + ha) * 4u;
        if (AMODE == 2) {
#pragma unroll
            for (int i = 0; i < 16; i++) {
                const int d = kb + ha + i;
                CP4(aD + i * 4u, base0 + (long)(d & 7) * 1048576 + (d >> 3));
            }
        } else {
#pragma unroll
            for (int j = 0; j < 4; j++) CP16(aD + j * 16u, ap + kb + ha + 4 * j);
        }
        const uint32_t bD = sbB + (uint32_t)(s * STAGE + 128 * ALD + bn * ALD + hb) * 4u;
#pragma unroll
        for (int j = 0; j < NF / 4; j++) CP16(bD + j * 16u, bp + kb + 4 * j);
    };

    load_tile(0, 0); CPCOMMIT();
    load_tile(1, 1); CPCOMMIT();

    for (int kc = 0; kc < nCh; kc++) {
        CPWAIT(1);
        __syncthreads();
        const int ld = kc + 2;
        if (ld < nCh) load_tile(ld, ld % 3);
        CPCOMMIT();

        const float* sA = sm + (kc % 3) * STAGE;
        const float* sB = sA + 128 * ALD;

        if (THREE) {
            // bf16 2-term split, K-steps of 16, 3 passes each
#pragma unroll
            for (int ks = 0; ks < 2; ks++) {
                const int kk = ks * 16;
                const int k0 = kk + 2 * tig;
                uint32_t bh[4][2], bl[4][2];
#pragma unroll
                for (int ni = 0; ni < 4; ni++) {
                    const int nb = n_base + ni * 8 + grp;
                    split_bf16x2(sB[nb * ALD + k0], sB[nb * ALD + k0 + 1],
                                 bh[ni][0], bl[ni][0]);
                    split_bf16x2(sB[nb * ALD + k0 + 8], sB[nb * ALD + k0 + 9],
                                 bh[ni][1], bl[ni][1]);
                }
#pragma unroll
                for (int mi = 0; mi < MI; mi++) {
                    const int r0 = (m_base + mi * 16 + grp) * ALD;
                    const int r1 = r0 + 8 * ALD;
                    uint32_t ah[4], al[4];
                    split_bf16x2(sA[r0 + k0], sA[r0 + k0 + 1], ah[0], al[0]);
                    split_bf16x2(sA[r1 + k0], sA[r1 + k0 + 1], ah[1], al[1]);
                    split_bf16x2(sA[r0 + k0 + 8], sA[r0 + k0 + 9], ah[2], al[2]);
                    split_bf16x2(sA[r1 + k0 + 8], sA[r1 + k0 + 9], ah[3], al[3]);
#pragma unroll
                    for (int ni = 0; ni < 4; ni++)
                        MMA_BF16(acc[mi][ni], ah[0], ah[1], ah[2], ah[3], bh[ni][0], bh[ni][1]);
#pragma unroll
                    for (int ni = 0; ni < 4; ni++)
                        MMA_BF16(acc[mi][ni], ah[0], ah[1], ah[2], ah[3], bl[ni][0], bl[ni][1]);
#pragma unroll
                    for (int ni = 0; ni < 4; ni++)
                        MMA_BF16(acc[mi][ni], al[0], al[1], al[2], al[3], bh[ni][0], bh[ni][1]);
                }
            }
        } else {
            // 1-pass tf32, K-steps of 8
#pragma unroll
            for (int ks = 0; ks < 4; ks++) {
                const int kk = ks * 8;
                uint32_t bh[4][2];
#pragma unroll
                for (int ni = 0; ni < 4; ni++) {
                    const int nb = n_base + ni * 8 + grp;
                    bh[ni][0] = __float_as_uint(sB[nb * ALD + kk + tig]);
                    bh[ni][1] = __float_as_uint(sB[nb * ALD + kk + tig + 4]);
                }
#pragma unroll
                for (int mi = 0; mi < MI; mi++) {
                    const int mb = m_base + mi * 16;
                    const uint32_t a0 = __float_as_uint(sA[(mb + grp) * ALD + kk + tig]);
                    const uint32_t a1 = __float_as_uint(sA[(mb + grp + 8) * ALD + kk + tig]);
                    const uint32_t a2 = __float_as_uint(sA[(mb + grp) * ALD + kk + tig + 4]);
                    const uint32_t a3 = __float_as_uint(sA[(mb + grp + 8) * ALD + kk + tig + 4]);
#pragma unroll
                    for (int ni = 0; ni < 4; ni++)
                        MMA_TF32(acc[mi][ni], a0, a1, a2, a3, bh[ni][0], bh[ni][1]);
                }
            }
        }
    }

    // ---- epilogues ----
    if (EMODE == 1) {
        __syncthreads();    // all compute reads of sm done before reuse as sC
        float* sC = sm;     // 128 x NT staging, stride 133 (NT=128 case)
#pragma unroll
        for (int mi = 0; mi < MI; mi++)
#pragma unroll
            for (int ni = 0; ni < 4; ni++) {
                const int r0 = m_base + mi * 16 + grp;
                const int cb = n_base + ni * 8 + 2 * tig;
                sC[r0 * 133 + cb] = acc[mi][ni][0];
                sC[r0 * 133 + cb + 1] = acc[mi][ni][1];
                sC[(r0 + 8) * 133 + cb] = acc[mi][ni][2];
                sC[(r0 + 8) * 133 + cb + 1] = acc[mi][ni][3];
            }
        __syncthreads();
        const int rw = tid & 127, g2 = tid >> 7;
        const int bl = row0 >> 12, sb = row0 & 4095;
        for (int cp = 0; cp < 64; cp++) {
            const int col = cp * 2 + g2;
            const int ch = col0 + col;
            const float val = sC[rw * 133 + col] + __ldg(&bias[ch]);
            out[((long)bl * 256 + ch) * 4096 + sb + rw] = val;
        }
    } else {
        float gamma = 0.f;
        if (EMODE == 3) gamma = __ldg(gammaPtr);
#pragma unroll
        for (int mi = 0; mi < MI; mi++)
#pragma unroll
            for (int ni = 0; ni < 4; ni++) {
                const int r0g = m_base + mi * 16 + grp;
                const int cb = n_base + ni * 8 + 2 * tig;
                const int c = col0 + cb;
#pragma unroll
                for (int half = 0; half < 2; half++) {
                    const int r = row0 + r0g + half * 8;
                    float v0 = acc[mi][ni][2 * half];
                    float v1 = acc[mi][ni][2 * half + 1];
                    if (EMODE == 0) {
                        v0 += __ldg(&bias[c]);
                        v1 += __ldg(&bias[c + 1]);
                        float2 st = {v0, v1};
                        *(float2*)(out + (long)r * 256 + c) = st;
                    } else if (EMODE == 2) {
                        float2 st = {v0, v1};
                        *(float2*)(out + (long)z * 65536 + (long)r * 256 + c) = st;
                    } else {
                        const long rr = (long)z * 4096 + r;
                        v0 = gamma * v0 + res[rr * (long)ldr + c];
                        v1 = gamma * v1 + res[rr * (long)ldr + c + 1];
                        float2 st = {v0, v1};
                        *(float2*)(out + rr * 256 + c) = st;
                    }
                }
            }
    }
}

// ---------------- compact x[..., :256] -> aligned [65536][256] ----------------
__global__ __launch_bounds__(1024) void compact_x(const float* __restrict__ x,
                                                  float* __restrict__ xc) {
    const long i = (long)blockIdx.x * 1024 + threadIdx.x;
    const long r = i >> 8;
    const int c = (int)(i & 255);
    xc[i] = x[r * 259 + c];
}

// ---------------- softmax over 4 split-K partials ----------------
__global__ __launch_bounds__(256) void softmax_rows(float* __restrict__ data) {
    const int row = blockIdx.x * 8 + (threadIdx.x >> 5);
    const int lane = threadIdx.x & 31;
    float* p0 = data + (long)row * 256;
    float vv[8];
    float m = -1e30f;
#pragma unroll
    for (int i = 0; i < 8; i++) {
        const int c = i * 32 + lane;
        vv[i] = p0[c] + p0[c + 1048576L] + p0[c + 2097152L] + p0[c + 3145728L];
        m = fmaxf(m, vv[i]);
    }
#pragma unroll
    for (int o = 16; o; o >>= 1) m = fmaxf(m, __shfl_xor_sync(0xffffffffu, m, o));
    float s = 0.f;
#pragma unroll
    for (int i = 0; i < 8; i++) { vv[i] = __expf(vv[i] - m); s += vv[i]; }
#pragma unroll
    for (int o = 16; o; o >>= 1) s += __shfl_xor_sync(0xffffffffu, s, o);
    const float inv = 1.f / s;
#pragma unroll
    for (int i = 0; i < 8; i++) p0[i * 32 + lane] = vv[i] * inv;
}

// ---------------- launch ----------------
extern "C" void kernel_launch(void* const* d_in, const int* in_sizes, int n_in,
                              void* d_out, int out_size)
{
    const float* x    = (const float*)d_in[0];
    const float* sq_w = (const float*)d_in[3];
    const float* sq_b = (const float*)d_in[4];
    const float* sk_w = (const float*)d_in[5];
    const float* sk_b = (const float*)d_in[6];
    const float* sv_w = (const float*)d_in[7];
    const float* sv_b = (const float*)d_in[8];
    const float* tq_w = (const float*)d_in[9];
    const float* tq_b = (const float*)d_in[10];
    const float* tk_w = (const float*)d_in[11];
    const float* tk_b = (const float*)d_in[12];
    const float* tv_w = (const float*)d_in[13];
    const float* tv_b = (const float*)d_in[14];
    const float* s_gamma = (const float*)d_in[15];
    const float* t_gamma = (const float*)d_in[16];
    float* out = (float*)d_out;

    float *xc, *q, *k, *v, *attn;
    cudaGetSymbolAddress((void**)&xc, g_xc);
    cudaGetSymbolAddress((void**)&q, g_q);
    cudaGetSymbolAddress((void**)&k, g_k);
    cudaGetSymbolAddress((void**)&v, g_v);
    cudaGetSymbolAddress((void**)&attn, g_attn);

    auto convA  = gemm_tc<true, 0, 1, 128>;   // sq, sk, tq (aligned rows)
    auto convKG = gemm_tc<true, 1, 1, 128>;   // tk (gathered rows of xc)
    auto convV  = gemm_tc<false, 0, 0, 128>;  // sv, tv
    auto scoreK = gemm_tc<true, 0, 2, 64>;    // scores (split-K=4)
    auto outV1  = gemm_tc<false, 0, 3, 128>;  // out spatial
    auto outV2  = gemm_tc<false, 2, 3, 128>;  // out temporal (v2 gather)

    const int SM128 = 3 * (128 + 128) * 36 * 4;   // 110592
    const int SM64  = 3 * (128 + 64) * 36 * 4;    // 82944
    cudaFuncSetAttribute(convA,  cudaFuncAttributeMaxDynamicSharedMemorySize, SM128);
    cudaFuncSetAttribute(convKG, cudaFuncAttributeMaxDynamicSharedMemorySize, SM128);
    cudaFuncSetAttribute(convV,  cudaFuncAttributeMaxDynamicSharedMemorySize, SM128);
    cudaFuncSetAttribute(scoreK, cudaFuncAttributeMaxDynamicSharedMemorySize, SM64);
    cudaFuncSetAttribute(outV1,  cudaFuncAttributeMaxDynamicSharedMemorySize, SM128);
    cudaFuncSetAttribute(outV2,  cudaFuncAttributeMaxDynamicSharedMemorySize, SM128);

    const dim3 cg(512, 2, 1);
    const dim3 sg(2, 4, 64);    // split-K=4 -> 64 z-slices
    const dim3 og(32, 2, 16);

    compact_x<<<16384, 1024>>>(x, xc);

    // ---- spatial ----
    convA<<<cg, 256, SM128>>>(xc, 256, 0, sq_w, 256, 0, 256, sq_b, nullptr, nullptr, 0, q);
    convA<<<cg, 256, SM128>>>(xc, 256, 0, sk_w, 256, 0, 256, sk_b, nullptr, nullptr, 0, k);
    convV<<<cg, 256, SM128>>>(xc, 256, 0, sv_w, 256, 0, 256, sv_b, nullptr, nullptr, 0, v);
    scoreK<<<sg, 256, SM64>>>(q, 4096, 1048576L, k, 4096, 1048576L, 1024,
                              nullptr, nullptr, nullptr, 0, attn);
    softmax_rows<<<512, 256>>>(attn);
    outV1<<<og, 256, SM128>>>(v, 256, 1048576L, attn, 256, 65536L, 256,
                              nullptr, s_gamma, xc, 256, out);

    // ---- temporal ----
    convA<<<cg, 256, SM128>>>(out, 256, 0, tq_w, 256, 0, 256, tq_b, nullptr, nullptr, 0, q);
    convKG<<<cg, 256, SM128>>>(xc, 256, 0, tk_w, 256, 0, 256, tk_b, nullptr, nullptr, 0, k);
    convV<<<cg, 256, SM128>>>(xc, 256, 0, tv_w, 256, 0, 256, tv_b, nullptr, nullptr, 0, v);
    scoreK<<<sg, 256, SM64>>>(q, 4096, 1048576L, k, 4096, 1048576L, 1024,
                              nullptr, nullptr, nullptr, 0, attn);
    softmax_rows<<<512, 256>>>(attn);
    outV2<<<og, 256, SM128>>>(v, 0, 0, attn, 256, 65536L, 256,
                              nullptr, t_gamma, out, 256, out);
}

// round 10
// speedup vs baseline: 1.7392x; 1.2603x over previous
#include <cuda_runtime.h>
#include <cuda_bf16.h>
#include <cstdint>

// ===========================================================================
// LossRecovery, packed-bf16 data path. All GEMM operands live in gmem/smem as
// u32 words = 2 k-adjacent bf16 (hi/lo planes for 2-term-split operands).
// Consumers load fragments with single LDS.32 per mma reg, zero conversions.
//   q/k convs + scores: 3-pass (AhBh+AhBl+AlBh)   v convs / outs: 2-pass
// ===========================================================================

__device__ uint32_t g_xh[65536L * 128], g_xl[65536L * 128];    // x_s planes
__device__ uint32_t g_x1h[65536L * 128], g_x1l[65536L * 128];  // x1 planes
__device__ uint32_t g_wh[6 * 32768], g_wl[6 * 32768];          // weight planes
__device__ uint32_t g_qh[16L * 256 * 2048], g_ql[16L * 256 * 2048];
__device__ uint32_t g_kh[16L * 256 * 2048], g_kl[16L * 256 * 2048];
__device__ uint32_t g_vh[16L * 4096 * 128], g_vl[16L * 4096 * 128];
__device__ float    g_attnP[64L * 65536];                      // fp32 split-K partials
__device__ uint32_t g_attnB[16L * 256 * 128];                  // packed bf16 attn

#define CP16(dst, src) asm volatile("cp.async.cg.shared.global [%0], [%1], 16;\n" :: "r"(dst), "l"(src))
#define CPCOMMIT()     asm volatile("cp.async.commit_group;\n" ::: "memory")
#define CPWAIT(n)      asm volatile("cp.async.wait_group %0;\n" :: "n"(n) : "memory")

__device__ __forceinline__ uint32_t pack_hi(float v0, float v1) {
    uint32_t h;
    asm("cvt.rn.bf16x2.f32 %0, %1, %2;" : "=r"(h) : "f"(v1), "f"(v0));
    return h;  // lo half = v0
}
__device__ __forceinline__ void pack_pair(float v0, float v1, uint32_t& h, uint32_t& l) {
    h = pack_hi(v0, v1);
    const float h0 = __uint_as_float(h << 16);
    const float h1 = __uint_as_float(h & 0xFFFF0000u);
    l = pack_hi(v0 - h0, v1 - h1);
}

#define MMA_BF16(ac, a0, a1, a2, a3, b0, b1) \
    asm volatile("mma.sync.aligned.m16n8k16.row.col.f32.bf16.bf16.f32 " \
        "{%0,%1,%2,%3},{%4,%5,%6,%7},{%8,%9},{%0,%1,%2,%3};" \
        : "+f"((ac)[0]), "+f"((ac)[1]), "+f"((ac)[2]), "+f"((ac)[3]) \
        : "r"(a0), "r"(a1), "r"(a2), "r"(a3), "r"(b0), "r"(b1))

// ---------------------------------------------------------------------------
template <int NPASS, int BPL, int AMODE, int EMODE, int NT, bool DUAL>
__global__ __launch_bounds__(256, 2) void gemm(
    const uint32_t* __restrict__ aH, const uint32_t* __restrict__ aL, int aW, long aZ,
    const uint32_t* __restrict__ bH, const uint32_t* __restrict__ bL, int bW, long bZ,
    int KdimW,
    const float* __restrict__ bias, const float* __restrict__ gammaPtr,
    const float* __restrict__ res, int ldr,
    float* __restrict__ outF, uint32_t* __restrict__ outH, uint32_t* __restrict__ outL)
{
    extern __shared__ uint32_t sm[];
    constexpr int ALD = 20;                       // 16 data words + 4 pad
    constexpr int STAGEW = 2 * 128 * ALD + BPL * NT * ALD;
    constexpr int NSTAGE = (STAGEW > 8192) ? 2 : 3;
    const uint32_t sbB = (uint32_t)__cvta_generic_to_shared(sm);

    const int tid = threadIdx.x;
    const int wid = tid >> 5, lane = tid & 31;
    const int grp = lane >> 2, tig = lane & 3;
    const int row0 = blockIdx.x * 128, col0 = blockIdx.y * NT;
    const int z = blockIdx.z;
    int zA = z;
    long koffW = 0;
    if (EMODE == 2) { zA = z & 15; koffW = (long)(z >> 4) * KdimW; }

    constexpr int MI = (NT == 128) ? 4 : 2;
    const int m_base = (NT == 128) ? ((wid >> 2) * 64) : ((wid >> 1) * 32);
    const int n_base = (NT == 128) ? ((wid & 3) * 32) : ((wid & 1) * 32);

    float acc[MI][4][4];
#pragma unroll
    for (int mi = 0; mi < MI; mi++)
#pragma unroll
        for (int ni = 0; ni < 4; ni++)
#pragma unroll
            for (int e = 0; e < 4; e++) acc[mi][ni][e] = 0.f;

    // ---- A loader: 2 threads/row, 8 words each ----
    const int ar = tid >> 1, hw = (tid & 1) * 8;
    long arow;                 // base global word index (+= kc*16 per chunk, AMODE<2)
    long astep = 16;
    if (AMODE == 0) {
        arow = (long)zA * aZ + (long)(row0 + ar) * aW + koffW + hw;
    } else if (AMODE == 1) {
        const int grow = row0 + ar;
        const int t = grow & 4095;
        const int s = ((t & 63) << 6) | (t >> 6);
        arow = ((long)(grow >> 12) * 4096 + s) * (long)aW + hw;
    } else {  // v2 gather: chunk kc -> l = kc, contiguous words
        const int bq = z >> 3, chHi = z & 7;
        arow = ((long)(bq * 8) * 4096 + (row0 + ar)) * 128 + chHi * 16 + hw;
        astep = 4096L * 128;
    }
    // ---- B loader ----
    const int bn = (NT == 128) ? (tid >> 1) : (tid >> 2);
    const int hwB = (NT == 128) ? ((tid & 1) * 8) : ((tid & 3) * 4);
    const long brow = (long)zA * bZ + (long)(col0 + bn) * bW + koffW + hwB;

    const int nCh = KdimW >> 4;
    const uint32_t AHo = 0, ALo = 128 * ALD, BHo = 256 * ALD, BLo = (256 + NT) * ALD;

    auto load_tile = [&](int kc, int s) {
        const long ka = arow + (long)kc * astep;
        const long kb = brow + (long)kc * 16;
        const uint32_t aD = sbB + (uint32_t)(s * STAGEW + ar * ALD + hw) * 4u;
        CP16(aD, aH + ka); CP16(aD + 16u, aH + ka + 4);
        const uint32_t aD2 = aD + ALo * 4u;
        CP16(aD2, aL + ka); CP16(aD2 + 16u, aL + ka + 4);
        const uint32_t bD = sbB + (uint32_t)(s * STAGEW + BHo + bn * ALD + hwB) * 4u;
        if (NT == 128) { CP16(bD, bH + kb); CP16(bD + 16u, bH + kb + 4); }
        else           { CP16(bD, bH + kb); }
        if (BPL == 2) {
            const uint32_t bD2 = sbB + (uint32_t)(s * STAGEW + BLo + bn * ALD + hwB) * 4u;
            if (NT == 128) { CP16(bD2, bL + kb); CP16(bD2 + 16u, bL + kb + 4); }
            else           { CP16(bD2, bL + kb); }
        }
    };

    auto compute = [&](int s) {
        const uint32_t* sAh = sm + s * STAGEW;
        const uint32_t* sAl = sAh + ALo;
        const uint32_t* sBh = sAh + BHo;
        const uint32_t* sBl = sAh + BLo;
#pragma unroll
        for (int ks = 0; ks < 2; ks++) {
            const int ws = ks * 8;
            uint32_t bh[4][2], bl[4][2];
#pragma unroll
            for (int ni = 0; ni < 4; ni++) {
                const int wb = (n_base + ni * 8 + grp) * ALD + ws + tig;
                bh[ni][0] = sBh[wb]; bh[ni][1] = sBh[wb + 4];
                if (BPL == 2) { bl[ni][0] = sBl[wb]; bl[ni][1] = sBl[wb + 4]; }
            }
#pragma unroll
            for (int mi = 0; mi < MI; mi++) {
                const int wa0 = (m_base + mi * 16 + grp) * ALD + ws + tig;
                const int wa1 = wa0 + 8 * ALD;
                const uint32_t ah0 = sAh[wa0], ah1 = sAh[wa1];
                const uint32_t ah2 = sAh[wa0 + 4], ah3 = sAh[wa1 + 4];
                const uint32_t al0 = sAl[wa0], al1 = sAl[wa1];
                const uint32_t al2 = sAl[wa0 + 4], al3 = sAl[wa1 + 4];
#pragma unroll
                for (int ni = 0; ni < 4; ni++)
                    MMA_BF16(acc[mi][ni], ah0, ah1, ah2, ah3, bh[ni][0], bh[ni][1]);
                if (NPASS == 3) {
#pragma unroll
                    for (int ni = 0; ni < 4; ni++)
                        MMA_BF16(acc[mi][ni], ah0, ah1, ah2, ah3, bl[ni][0], bl[ni][1]);
                }
#pragma unroll
                for (int ni = 0; ni < 4; ni++)
                    MMA_BF16(acc[mi][ni], al0, al1, al2, al3, bh[ni][0], bh[ni][1]);
            }
        }
    };

    if (NSTAGE == 2) {
        load_tile(0, 0); CPCOMMIT();
        if (nCh > 1) load_tile(1, 1);
        CPCOMMIT();
        for (int kc = 0; kc < nCh; kc++) {
            CPWAIT(1);
            __syncthreads();
            compute(kc & 1);
            __syncthreads();
            if (kc + 2 < nCh) { load_tile(kc + 2, kc & 1); CPCOMMIT(); }
        }
    } else {
        load_tile(0, 0); CPCOMMIT();
        if (nCh > 1) load_tile(1, 1);
        CPCOMMIT();
        for (int kc = 0; kc < nCh; kc++) {
            CPWAIT(1);
            __syncthreads();
            const int ld = kc + 2;
            if (ld < nCh) load_tile(ld, ld % 3);
            CPCOMMIT();
            compute(kc % 3);
        }
    }

    // ---- epilogues ----
    if (EMODE == 1) {
        // stage fp32, then packed transposed planes [z][ch][s/2]
        float* sC = (float*)sm;
#pragma unroll
        for (int mi = 0; mi < MI; mi++)
#pragma unroll
            for (int ni = 0; ni < 4; ni++) {
                const int r0 = m_base + mi * 16 + grp;
                const int cb = n_base + ni * 8 + 2 * tig;
                sC[r0 * 133 + cb] = acc[mi][ni][0];
                sC[r0 * 133 + cb + 1] = acc[mi][ni][1];
                sC[(r0 + 8) * 133 + cb] = acc[mi][ni][2];
                sC[(r0 + 8) * 133 + cb + 1] = acc[mi][ni][3];
            }
        __syncthreads();
        const int p = tid & 63, colg = tid >> 6;
        const int bl2 = row0 >> 12, sb = row0 & 4095;
        for (int cp = 0; cp < 32; cp++) {
            const int col = cp * 4 + colg;
            const int ch = col0 + col;
            const float bv = __ldg(&bias[ch]);
            const float v0 = sC[(2 * p) * 133 + col] + bv;
            const float v1 = sC[(2 * p + 1) * 133 + col] + bv;
            uint32_t h, l;
            pack_pair(v0, v1, h, l);
            const long w = ((long)(bl2 * 256 + ch)) * 2048 + (sb >> 1) + p;
            outH[w] = h; outL[w] = l;
        }
    } else {
        float gamma = 0.f;
        if (EMODE == 3) gamma = __ldg(gammaPtr);
#pragma unroll
        for (int mi = 0; mi < MI; mi++)
#pragma unroll
            for (int ni = 0; ni < 4; ni++) {
                const int r0g = m_base + mi * 16 + grp;
                const int cb = n_base + ni * 8 + 2 * tig;
                const int c = col0 + cb;
#pragma unroll
                for (int half = 0; half < 2; half++) {
                    const int r = row0 + r0g + half * 8;
                    float v0 = acc[mi][ni][2 * half];
                    float v1 = acc[mi][ni][2 * half + 1];
                    if (EMODE == 0) {
                        v0 += __ldg(&bias[c]);
                        v1 += __ldg(&bias[c + 1]);
                        uint32_t h, l;
                        pack_pair(v0, v1, h, l);
                        const long w = (long)r * 128 + (c >> 1);   // rows span z*4096+s
                        outH[w] = h; outL[w] = l;
                    } else if (EMODE == 2) {
                        float2 st = {v0, v1};
                        *(float2*)(outF + (long)z * 65536 + (long)r * 256 + c) = st;
                    } else {
                        const long rr = (long)z * 4096 + r;
                        v0 = gamma * v0 + res[rr * (long)ldr + c];
                        v1 = gamma * v1 + res[rr * (long)ldr + c + 1];
                        float2 st = {v0, v1};
                        *(float2*)(outF + rr * 256 + c) = st;
                        if (DUAL) {
                            uint32_t h, l;
                            pack_pair(v0, v1, h, l);
                            const long w = rr * 128 + (c >> 1);
                            outH[w] = h; outL[w] = l;
                        }
                    }
                }
            }
    }
}

// ---------------- split x[..., :256] into bf16 hi/lo packed planes ----------
__global__ __launch_bounds__(256) void split_x(const float* __restrict__ x) {
    const long i = (long)blockIdx.x * 256 + threadIdx.x;   // pair index
    const long r = i >> 7;
    const int c = (int)(i & 127) * 2;
    const float v0 = x[r * 259 + c], v1 = x[r * 259 + c + 1];
    uint32_t h, l;
    pack_pair(v0, v1, h, l);
    g_xh[i] = h; g_xl[i] = l;
}

// ---------------- weights -> planes ----------------------------------------
__global__ __launch_bounds__(256) void prep_w(const float* w0, const float* w1,
                                              const float* w2, const float* w3,
                                              const float* w4, const float* w5) {
    const int id = blockIdx.x * 256 + threadIdx.x;         // 6*32768
    const int m = id >> 15, rc = id & 32767;
    const float* w = (m == 0) ? w0 : (m == 1) ? w1 : (m == 2) ? w2
                   : (m == 3) ? w3 : (m == 4) ? w4 : w5;
    const float v0 = w[rc * 2], v1 = w[rc * 2 + 1];
    uint32_t h, l;
    pack_pair(v0, v1, h, l);
    g_wh[id] = h; g_wl[id] = l;
}

// ---------------- softmax: sum 4 partials, normalize, pack (opt. permuted) --
template <bool PERM>
__global__ __launch_bounds__(256) void softmax_pack(const float* __restrict__ P,
                                                    uint32_t* __restrict__ O) {
    __shared__ float srow[8][256];
    const int wid = threadIdx.x >> 5, lane = threadIdx.x & 31;
    const int row = blockIdx.x * 8 + wid;
    const float* p = P + (long)row * 256 + lane * 8;
    float vv[8];
    float mx = -1e30f;
#pragma unroll
    for (int j = 0; j < 8; j++) {
        vv[j] = p[j] + p[j + 1048576L] + p[j + 2097152L] + p[j + 3145728L];
        mx = fmaxf(mx, vv[j]);
    }
#pragma unroll
    for (int o = 16; o; o >>= 1) mx = fmaxf(mx, __shfl_xor_sync(0xffffffffu, mx, o));
    float s = 0.f;
#pragma unroll
    for (int j = 0; j < 8; j++) { vv[j] = __expf(vv[j] - mx); s += vv[j]; }
#pragma unroll
    for (int o = 16; o; o >>= 1) s += __shfl_xor_sync(0xffffffffu, s, o);
    const float inv = 1.f / s;
#pragma unroll
    for (int j = 0; j < 8; j++) srow[wid][lane * 8 + j] = vv[j] * inv;
    __syncwarp();
#pragma unroll
    for (int t = 0; t < 4; t++) {
        const int m = lane * 4 + t;
        int d0 = 2 * m, d1 = 2 * m + 1;
        if (PERM) {                      // k -> d2: d2 = (k&31)*8 + (k>>5)
            d0 = ((d0 & 31) << 3) | (d0 >> 5);
            d1 = ((d1 & 31) << 3) | (d1 >> 5);
        }
        O[(long)row * 128 + m] = pack_hi(srow[wid][d0], srow[wid][d1]);
    }
}

// ---------------- launch ----------------------------------------------------
extern "C" void kernel_launch(void* const* d_in, const int* in_sizes, int n_in,
                              void* d_out, int out_size)
{
    const float* x    = (const float*)d_in[0];
    const float* sq_w = (const float*)d_in[3];
    const float* sq_b = (const float*)d_in[4];
    const float* sk_w = (const float*)d_in[5];
    const float* sk_b = (const float*)d_in[6];
    const float* sv_w = (const float*)d_in[7];
    const float* sv_b = (const float*)d_in[8];
    const float* tq_w = (const float*)d_in[9];
    const float* tq_b = (const float*)d_in[10];
    const float* tk_w = (const float*)d_in[11];
    const float* tk_b = (const float*)d_in[12];
    const float* tv_w = (const float*)d_in[13];
    const float* tv_b = (const float*)d_in[14];
    const float* s_gamma = (const float*)d_in[15];
    const float* t_gamma = (const float*)d_in[16];
    float* out = (float*)d_out;

    uint32_t *xh, *xl, *x1h, *x1l, *wh, *wl, *qh, *ql, *kh, *kl, *vh, *vl, *attnB;
    float* attnP;
    cudaGetSymbolAddress((void**)&xh, g_xh);   cudaGetSymbolAddress((void**)&xl, g_xl);
    cudaGetSymbolAddress((void**)&x1h, g_x1h); cudaGetSymbolAddress((void**)&x1l, g_x1l);
    cudaGetSymbolAddress((void**)&wh, g_wh);   cudaGetSymbolAddress((void**)&wl, g_wl);
    cudaGetSymbolAddress((void**)&qh, g_qh);   cudaGetSymbolAddress((void**)&ql, g_ql);
    cudaGetSymbolAddress((void**)&kh, g_kh);   cudaGetSymbolAddress((void**)&kl, g_kl);
    cudaGetSymbolAddress((void**)&vh, g_vh);   cudaGetSymbolAddress((void**)&vl, g_vl);
    cudaGetSymbolAddress((void**)&attnP, g_attnP);
    cudaGetSymbolAddress((void**)&attnB, g_attnB);

    auto convQK  = gemm<3, 2, 0, 1, 128, false>;   // sq, sk, tq
    auto convTK  = gemm<3, 2, 1, 1, 128, false>;   // tk (row gather)
    auto convV   = gemm<2, 1, 0, 0, 128, false>;   // sv, tv
    auto scoreK  = gemm<3, 2, 0, 2, 64, false>;    // scores split-K=4
    auto outV1   = gemm<2, 1, 0, 3, 128, true>;    // spatial out (+x1 planes)
    auto outV2   = gemm<2, 1, 2, 3, 128, false>;   // temporal out (v2 gather)

    const int SMQ = 2 * (2 * 128 * 20 + 2 * 128 * 20) * 4;   // 81920
    const int SM3 = 3 * (2 * 128 * 20 + 1 * 128 * 20) * 4;   // 92160 (convV/outs)
    const int SMS = 3 * (2 * 128 * 20 + 2 * 64 * 20) * 4;    // 92160 (scores)
    cudaFuncSetAttribute(convQK, cudaFuncAttributeMaxDynamicSharedMemorySize, SMQ);
    cudaFuncSetAttribute(convTK, cudaFuncAttributeMaxDynamicSharedMemorySize, SMQ);
    cudaFuncSetAttribute(convV,  cudaFuncAttributeMaxDynamicSharedMemorySize, SM3);
    cudaFuncSetAttribute(scoreK, cudaFuncAttributeMaxDynamicSharedMemorySize, SMS);
    cudaFuncSetAttribute(outV1,  cudaFuncAttributeMaxDynamicSharedMemorySize, SM3);
    cudaFuncSetAttribute(outV2,  cudaFuncAttributeMaxDynamicSharedMemorySize, SM3);

    const dim3 cg(512, 2, 1);
    const dim3 sg(2, 4, 64);
    const dim3 og(32, 2, 16);

    split_x<<<32768, 256>>>(x);
    prep_w<<<768, 256>>>(sq_w, sk_w, sv_w, tq_w, tk_w, tv_w);

    // ---- spatial ----
    convQK<<<cg, 256, SMQ>>>(xh, xl, 128, 0, wh + 0 * 32768, wl + 0 * 32768, 128, 0, 128,
                             sq_b, nullptr, nullptr, 0, nullptr, qh, ql);
    convQK<<<cg, 256, SMQ>>>(xh, xl, 128, 0, wh + 1 * 32768, wl + 1 * 32768, 128, 0, 128,
                             sk_b, nullptr, nullptr, 0, nullptr, kh, kl);
    convV<<<cg, 256, SM3>>>(xh, xl, 128, 0, wh + 2 * 32768, nullptr, 128, 0, 128,
                            sv_b, nullptr, nullptr, 0, nullptr, vh, vl);
    scoreK<<<sg, 256, SMS>>>(qh, ql, 2048, 524288L, kh, kl, 2048, 524288L, 512,
                             nullptr, nullptr, nullptr, 0, attnP, nullptr, nullptr);
    softmax_pack<false><<<512, 256>>>(attnP, attnB);
    outV1<<<og, 256, SM3>>>(vh, vl, 128, 524288L, attnB, nullptr, 128, 32768L, 128,
                            nullptr, s_gamma, x, 259, out, x1h, x1l);

    // ---- temporal ----
    convQK<<<cg, 256, SMQ>>>(x1h, x1l, 128, 0, wh + 3 * 32768, wl + 3 * 32768, 128, 0, 128,
                             tq_b, nullptr, nullptr, 0, nullptr, qh, ql);
    convTK<<<cg, 256, SMQ>>>(xh, xl, 128, 0, wh + 4 * 32768, wl + 4 * 32768, 128, 0, 128,
                             tk_b, nullptr, nullptr, 0, nullptr, kh, kl);
    convV<<<cg, 256, SM3>>>(xh, xl, 128, 0, wh + 5 * 32768, nullptr, 128, 0, 128,
                            tv_b, nullptr, nullptr, 0, nullptr, vh, vl);
    scoreK<<<sg, 256, SMS>>>(qh, ql, 2048, 524288L, kh, kl, 2048, 524288L, 512,
                             nullptr, nullptr, nullptr, 0, attnP, nullptr, nullptr);
    softmax_pack<true><<<512, 256>>>(attnP, attnB);
    outV2<<<og, 256, SM3>>>(vh, vl, 128, 0, attnB, nullptr, 128, 32768L, 128,
                            nullptr, t_gamma, out, 256, out, nullptr, nullptr);
}

// round 11
// speedup vs baseline: 1.8720x; 1.0764x over previous
#include <cuda_runtime.h>
#include <cuda_bf16.h>
#include <cstdint>

// ===========================================================================
// LossRecovery, packed-bf16 data path + ldmatrix fragment loads.
// u32 words = 2 k-adjacent bf16 (hi/lo planes for 2-term-split operands).
//   q/k convs + scores: 3-pass (AhBh+AhBl+AlBh)   v convs / outs: 2-pass
// Fragments loaded via ldmatrix.m8n8.x4.b16 (4x fewer shared-load instrs).
// ===========================================================================

__device__ uint32_t g_xh[65536L * 128], g_xl[65536L * 128];    // x_s planes
__device__ uint32_t g_x1h[65536L * 128], g_x1l[65536L * 128];  // x1 planes
__device__ uint32_t g_wh[6 * 32768], g_wl[6 * 32768];          // weight planes
__device__ uint32_t g_qh[16L * 256 * 2048], g_ql[16L * 256 * 2048];
__device__ uint32_t g_kh[16L * 256 * 2048], g_kl[16L * 256 * 2048];
__device__ uint32_t g_vh[16L * 4096 * 128], g_vl[16L * 4096 * 128];
__device__ float    g_attnP[64L * 65536];                      // fp32 split-K partials
__device__ uint32_t g_attnB[16L * 256 * 128];                  // packed bf16 attn

#define CP16(dst, src) asm volatile("cp.async.cg.shared.global [%0], [%1], 16;\n" :: "r"(dst), "l"(src))
#define CPCOMMIT()     asm volatile("cp.async.commit_group;\n" ::: "memory")
#define CPWAIT(n)      asm volatile("cp.async.wait_group %0;\n" :: "n"(n) : "memory")

#define LDSM4(d0, d1, d2, d3, a) \
    asm volatile("ldmatrix.sync.aligned.m8n8.x4.shared.b16 {%0,%1,%2,%3}, [%4];" \
        : "=r"(d0), "=r"(d1), "=r"(d2), "=r"(d3) : "r"(a))

__device__ __forceinline__ uint32_t pack_hi(float v0, float v1) {
    uint32_t h;
    asm("cvt.rn.bf16x2.f32 %0, %1, %2;" : "=r"(h) : "f"(v1), "f"(v0));
    return h;  // lo half = v0
}
__device__ __forceinline__ void pack_pair(float v0, float v1, uint32_t& h, uint32_t& l) {
    h = pack_hi(v0, v1);
    const float h0 = __uint_as_float(h << 16);
    const float h1 = __uint_as_float(h & 0xFFFF0000u);
    l = pack_hi(v0 - h0, v1 - h1);
}

#define MMA_BF16(ac, a0, a1, a2, a3, b0, b1) \
    asm volatile("mma.sync.aligned.m16n8k16.row.col.f32.bf16.bf16.f32 " \
        "{%0,%1,%2,%3},{%4,%5,%6,%7},{%8,%9},{%0,%1,%2,%3};" \
        : "+f"((ac)[0]), "+f"((ac)[1]), "+f"((ac)[2]), "+f"((ac)[3]) \
        : "r"(a0), "r"(a1), "r"(a2), "r"(a3), "r"(b0), "r"(b1))

// ---------------------------------------------------------------------------
template <int NPASS, int BPL, int AMODE, int EMODE, int NT, bool DUAL>
__global__ __launch_bounds__(256, 2) void gemm(
    const uint32_t* __restrict__ aH, const uint32_t* __restrict__ aL, int aW, long aZ,
    const uint32_t* __restrict__ bH, const uint32_t* __restrict__ bL, int bW, long bZ,
    int KdimW,
    const float* __restrict__ bias, const float* __restrict__ gammaPtr,
    const float* __restrict__ res, int ldr,
    float* __restrict__ outF, uint32_t* __restrict__ outH, uint32_t* __restrict__ outL)
{
    extern __shared__ uint32_t sm[];
    constexpr int ALD = 20;                       // 16 data words + 4 pad (80B rows:
                                                  // 16B-aligned, ldmatrix conflict-free)
    constexpr int STAGEW = 2 * 128 * ALD + BPL * NT * ALD;
    constexpr int NSTAGE = (STAGEW > 8192) ? 2 : 3;
    const uint32_t sbB = (uint32_t)__cvta_generic_to_shared(sm);

    const int tid = threadIdx.x;
    const int wid = tid >> 5, lane = tid & 31;
    const int grp = lane >> 2, tig = lane & 3;
    const int row0 = blockIdx.x * 128, col0 = blockIdx.y * NT;
    const int z = blockIdx.z;
    int zA = z;
    long koffW = 0;
    if (EMODE == 2) { zA = z & 15; koffW = (long)(z >> 4) * KdimW; }

    constexpr int MI = (NT == 128) ? 4 : 2;
    const int m_base = (NT == 128) ? ((wid >> 2) * 64) : ((wid >> 1) * 32);
    const int n_base = (NT == 128) ? ((wid & 3) * 32) : ((wid & 1) * 32);

    float acc[MI][4][4];
#pragma unroll
    for (int mi = 0; mi < MI; mi++)
#pragma unroll
        for (int ni = 0; ni < 4; ni++)
#pragma unroll
            for (int e = 0; e < 4; e++) acc[mi][ni][e] = 0.f;

    // ---- A loader: 2 threads/row, 8 words each ----
    const int ar = tid >> 1, hw = (tid & 1) * 8;
    long arow;
    long astep = 16;
    if (AMODE == 0) {
        arow = (long)zA * aZ + (long)(row0 + ar) * aW + koffW + hw;
    } else if (AMODE == 1) {
        const int grow = row0 + ar;
        const int t = grow & 4095;
        const int s = ((t & 63) << 6) | (t >> 6);
        arow = ((long)(grow >> 12) * 4096 + s) * (long)aW + hw;
    } else {  // v2 gather: chunk kc -> l = kc, contiguous words
        const int bq = z >> 3, chHi = z & 7;
        arow = ((long)(bq * 8) * 4096 + (row0 + ar)) * 128 + chHi * 16 + hw;
        astep = 4096L * 128;
    }
    // ---- B loader ----
    const int bn = (NT == 128) ? (tid >> 1) : (tid >> 2);
    const int hwB = (NT == 128) ? ((tid & 1) * 8) : ((tid & 3) * 4);
    const long brow = (long)zA * bZ + (long)(col0 + bn) * bW + koffW + hwB;

    const int nCh = KdimW >> 4;
    const uint32_t ALo = 128 * ALD, BHo = 256 * ALD, BLo = (256 + NT) * ALD;

    auto load_tile = [&](int kc, int s) {
        const long ka = arow + (long)kc * astep;
        const long kb = brow + (long)kc * 16;
        const uint32_t aD = sbB + (uint32_t)(s * STAGEW + ar * ALD + hw) * 4u;
        CP16(aD, aH + ka); CP16(aD + 16u, aH + ka + 4);
        const uint32_t aD2 = aD + ALo * 4u;
        CP16(aD2, aL + ka); CP16(aD2 + 16u, aL + ka + 4);
        const uint32_t bD = sbB + (uint32_t)(s * STAGEW + BHo + bn * ALD + hwB) * 4u;
        if (NT == 128) { CP16(bD, bH + kb); CP16(bD + 16u, bH + kb + 4); }
        else           { CP16(bD, bH + kb); }
        if (BPL == 2) {
            const uint32_t bD2 = sbB + (uint32_t)(s * STAGEW + BLo + bn * ALD + hwB) * 4u;
            if (NT == 128) { CP16(bD2, bL + kb); CP16(bD2 + 16u, bL + kb + 4); }
            else           { CP16(bD2, bL + kb); }
        }
    };

    // ldmatrix lane-address components
    const int la7 = lane & 7, lg = lane >> 3;
    const uint32_t aoff = (uint32_t)(((m_base + la7 + ((lg & 1) << 3)) * ALD
                                      + ((lg >> 1) << 2)) * 4);
    const uint32_t boff = (uint32_t)(((n_base + la7 + ((lg >> 1) << 3)) * ALD
                                      + ((lg & 1) << 2)) * 4);

    auto compute = [&](int s) {
        const uint32_t stB = sbB + (uint32_t)(s * STAGEW) * 4u;
#pragma unroll
        for (int ks = 0; ks < 2; ks++) {
            const uint32_t kby = (uint32_t)(ks * 32);
            uint32_t bh[4][2], bl[4][2];
#pragma unroll
            for (int p = 0; p < 2; p++) {
                const uint32_t ba = stB + BHo * 4u + boff + (uint32_t)(p * 16 * ALD * 4) + kby;
                LDSM4(bh[2 * p][0], bh[2 * p][1], bh[2 * p + 1][0], bh[2 * p + 1][1], ba);
                if (BPL == 2) {
                    const uint32_t ba2 = stB + BLo * 4u + boff + (uint32_t)(p * 16 * ALD * 4) + kby;
                    LDSM4(bl[2 * p][0], bl[2 * p][1], bl[2 * p + 1][0], bl[2 * p + 1][1], ba2);
                }
            }
#pragma unroll
            for (int mi = 0; mi < MI; mi++) {
                const uint32_t aa = stB + aoff + (uint32_t)(mi * 16 * ALD * 4) + kby;
                uint32_t ah0, ah1, ah2, ah3, al0, al1, al2, al3;
                LDSM4(ah0, ah1, ah2, ah3, aa);
                LDSM4(al0, al1, al2, al3, aa + ALo * 4u);
#pragma unroll
                for (int ni = 0; ni < 4; ni++)
                    MMA_BF16(acc[mi][ni], ah0, ah1, ah2, ah3, bh[ni][0], bh[ni][1]);
                if (NPASS == 3) {
#pragma unroll
                    for (int ni = 0; ni < 4; ni++)
                        MMA_BF16(acc[mi][ni], ah0, ah1, ah2, ah3, bl[ni][0], bl[ni][1]);
                }
#pragma unroll
                for (int ni = 0; ni < 4; ni++)
                    MMA_BF16(acc[mi][ni], al0, al1, al2, al3, bh[ni][0], bh[ni][1]);
            }
        }
    };

    if (NSTAGE == 2) {
        load_tile(0, 0); CPCOMMIT();
        if (nCh > 1) load_tile(1, 1);
        CPCOMMIT();
        for (int kc = 0; kc < nCh; kc++) {
            CPWAIT(1);
            __syncthreads();
            compute(kc & 1);
            __syncthreads();
            if (kc + 2 < nCh) { load_tile(kc + 2, kc & 1); CPCOMMIT(); }
        }
    } else {
        load_tile(0, 0); CPCOMMIT();
        if (nCh > 1) load_tile(1, 1);
        CPCOMMIT();
        for (int kc = 0; kc < nCh; kc++) {
            CPWAIT(1);
            __syncthreads();
            const int ld = kc + 2;
            if (ld < nCh) load_tile(ld, ld % 3);
            CPCOMMIT();
            compute(kc % 3);
        }
    }

    // ---- epilogues ----
    if (EMODE == 1) {
        // stage fp32, then packed transposed planes [z][ch][s/2]
        float* sC = (float*)sm;
#pragma unroll
        for (int mi = 0; mi < MI; mi++)
#pragma unroll
            for (int ni = 0; ni < 4; ni++) {
                const int r0 = m_base + mi * 16 + grp;
                const int cb = n_base + ni * 8 + 2 * tig;
                sC[r0 * 133 + cb] = acc[mi][ni][0];
                sC[r0 * 133 + cb + 1] = acc[mi][ni][1];
                sC[(r0 + 8) * 133 + cb] = acc[mi][ni][2];
                sC[(r0 + 8) * 133 + cb + 1] = acc[mi][ni][3];
            }
        __syncthreads();
        const int p = tid & 63, colg = tid >> 6;
        const int bl2 = row0 >> 12, sb = row0 & 4095;
        for (int cp = 0; cp < 32; cp++) {
            const int col = cp * 4 + colg;
            const int ch = col0 + col;
            const float bv = __ldg(&bias[ch]);
            const float v0 = sC[(2 * p) * 133 + col] + bv;
            const float v1 = sC[(2 * p + 1) * 133 + col] + bv;
            uint32_t h, l;
            pack_pair(v0, v1, h, l);
            const long w = ((long)(bl2 * 256 + ch)) * 2048 + (sb >> 1) + p;
            outH[w] = h; outL[w] = l;
        }
    } else {
        float gamma = 0.f;
        if (EMODE == 3) gamma = __ldg(gammaPtr);
#pragma unroll
        for (int mi = 0; mi < MI; mi++)
#pragma unroll
            for (int ni = 0; ni < 4; ni++) {
                const int r0g = m_base + mi * 16 + grp;
                const int cb = n_base + ni * 8 + 2 * tig;
                const int c = col0 + cb;
#pragma unroll
                for (int half = 0; half < 2; half++) {
                    const int r = row0 + r0g + half * 8;
                    float v0 = acc[mi][ni][2 * half];
                    float v1 = acc[mi][ni][2 * half + 1];
                    if (EMODE == 0) {
                        v0 += __ldg(&bias[c]);
                        v1 += __ldg(&bias[c + 1]);
                        uint32_t h, l;
                        pack_pair(v0, v1, h, l);
                        const long w = (long)r * 128 + (c >> 1);   // rows span z*4096+s
                        outH[w] = h; outL[w] = l;
                    } else if (EMODE == 2) {
                        float2 st = {v0, v1};
                        *(float2*)(outF + (long)z * 65536 + (long)r * 256 + c) = st;
                    } else {
                        const long rr = (long)z * 4096 + r;
                        v0 = gamma * v0 + res[rr * (long)ldr + c];
                        v1 = gamma * v1 + res[rr * (long)ldr + c + 1];
                        float2 st = {v0, v1};
                        *(float2*)(outF + rr * 256 + c) = st;
                        if (DUAL) {
                            uint32_t h, l;
                            pack_pair(v0, v1, h, l);
                            const long w = rr * 128 + (c >> 1);
                            outH[w] = h; outL[w] = l;
                        }
                    }
                }
            }
    }
}

// ---------------- split x[..., :256] into bf16 hi/lo packed planes ----------
__global__ __launch_bounds__(256) void split_x(const float* __restrict__ x) {
    const long i = (long)blockIdx.x * 256 + threadIdx.x;   // pair index
    const long r = i >> 7;
    const int c = (int)(i & 127) * 2;
    const float v0 = x[r * 259 + c], v1 = x[r * 259 + c + 1];
    uint32_t h, l;
    pack_pair(v0, v1, h, l);
    g_xh[i] = h; g_xl[i] = l;
}

// ---------------- weights -> planes ----------------------------------------
__global__ __launch_bounds__(256) void prep_w(const float* w0, const float* w1,
                                              const float* w2, const float* w3,
                                              const float* w4, const float* w5) {
    const int id = blockIdx.x * 256 + threadIdx.x;         // 6*32768
    const int m = id >> 15, rc = id & 32767;
    const float* w = (m == 0) ? w0 : (m == 1) ? w1 : (m == 2) ? w2
                   : (m == 3) ? w3 : (m == 4) ? w4 : w5;
    const float v0 = w[rc * 2], v1 = w[rc * 2 + 1];
    uint32_t h, l;
    pack_pair(v0, v1, h, l);
    g_wh[id] = h; g_wl[id] = l;
}

// ---------------- softmax: sum 4 partials, normalize, pack (opt. permuted) --
template <bool PERM>
__global__ __launch_bounds__(256) void softmax_pack(const float* __restrict__ P,
                                                    uint32_t* __restrict__ O) {
    __shared__ float srow[8][256];
    const int wid = threadIdx.x >> 5, lane = threadIdx.x & 31;
    const int row = blockIdx.x * 8 + wid;
    const float* p = P + (long)row * 256 + lane * 8;
    float vv[8];
    float mx = -1e30f;
#pragma unroll
    for (int j = 0; j < 8; j++) {
        vv[j] = p[j] + p[j + 1048576L] + p[j + 2097152L] + p[j + 3145728L];
        mx = fmaxf(mx, vv[j]);
    }
#pragma unroll
    for (int o = 16; o; o >>= 1) mx = fmaxf(mx, __shfl_xor_sync(0xffffffffu, mx, o));
    float s = 0.f;
#pragma unroll
    for (int j = 0; j < 8; j++) { vv[j] = __expf(vv[j] - mx); s += vv[j]; }
#pragma unroll
    for (int o = 16; o; o >>= 1) s += __shfl_xor_sync(0xffffffffu, s, o);
    const float inv = 1.f / s;
#pragma unroll
    for (int j = 0; j < 8; j++) srow[wid][lane * 8 + j] = vv[j] * inv;
    __syncwarp();
#pragma unroll
    for (int t = 0; t < 4; t++) {
        const int m = lane * 4 + t;
        int d0 = 2 * m, d1 = 2 * m + 1;
        if (PERM) {                      // k -> d2: d2 = (k&31)*8 + (k>>5)
            d0 = ((d0 & 31) << 3) | (d0 >> 5);
            d1 = ((d1 & 31) << 3) | (d1 >> 5);
        }
        O[(long)row * 128 + m] = pack_hi(srow[wid][d0], srow[wid][d1]);
    }
}

// ---------------- launch ----------------------------------------------------
extern "C" void kernel_launch(void* const* d_in, const int* in_sizes, int n_in,
                              void* d_out, int out_size)
{
    const float* x    = (const float*)d_in[0];
    const float* sq_w = (const float*)d_in[3];
    const float* sq_b = (const float*)d_in[4];
    const float* sk_w = (const float*)d_in[5];
    const float* sk_b = (const float*)d_in[6];
    const float* sv_w = (const float*)d_in[7];
    const float* sv_b = (const float*)d_in[8];
    const float* tq_w = (const float*)d_in[9];
    const float* tq_b = (const float*)d_in[10];
    const float* tk_w = (const float*)d_in[11];
    const float* tk_b = (const float*)d_in[12];
    const float* tv_w = (const float*)d_in[13];
    const float* tv_b = (const float*)d_in[14];
    const float* s_gamma = (const float*)d_in[15];
    const float* t_gamma = (const float*)d_in[16];
    float* out = (float*)d_out;

    uint32_t *xh, *xl, *x1h, *x1l, *wh, *wl, *qh, *ql, *kh, *kl, *vh, *vl, *attnB;
    float* attnP;
    cudaGetSymbolAddress((void**)&xh, g_xh);   cudaGetSymbolAddress((void**)&xl, g_xl);
    cudaGetSymbolAddress((void**)&x1h, g_x1h); cudaGetSymbolAddress((void**)&x1l, g_x1l);
    cudaGetSymbolAddress((void**)&wh, g_wh);   cudaGetSymbolAddress((void**)&wl, g_wl);
    cudaGetSymbolAddress((void**)&qh, g_qh);   cudaGetSymbolAddress((void**)&ql, g_ql);
    cudaGetSymbolAddress((void**)&kh, g_kh);   cudaGetSymbolAddress((void**)&kl, g_kl);
    cudaGetSymbolAddress((void**)&vh, g_vh);   cudaGetSymbolAddress((void**)&vl, g_vl);
    cudaGetSymbolAddress((void**)&attnP, g_attnP);
    cudaGetSymbolAddress((void**)&attnB, g_attnB);

    auto convQK  = gemm<3, 2, 0, 1, 128, false>;   // sq, sk, tq
    auto convTK  = gemm<3, 2, 1, 1, 128, false>;   // tk (row gather)
    auto convV   = gemm<2, 1, 0, 0, 128, false>;   // sv, tv
    auto scoreK  = gemm<3, 2, 0, 2, 64, false>;    // scores split-K=4
    auto outV1   = gemm<2, 1, 0, 3, 128, true>;    // spatial out (+x1 planes)
    auto outV2   = gemm<2, 1, 2, 3, 128, false>;   // temporal out (v2 gather)

    const int SMQ = 2 * (2 * 128 * 20 + 2 * 128 * 20) * 4;   // 81920
    const int SM3 = 3 * (2 * 128 * 20 + 1 * 128 * 20) * 4;   // 92160 (convV/outs)
    const int SMS = 3 * (2 * 128 * 20 + 2 * 64 * 20) * 4;    // 92160 (scores)
    cudaFuncSetAttribute(convQK, cudaFuncAttributeMaxDynamicSharedMemorySize, SMQ);
    cudaFuncSetAttribute(convTK, cudaFuncAttributeMaxDynamicSharedMemorySize, SMQ);
    cudaFuncSetAttribute(convV,  cudaFuncAttributeMaxDynamicSharedMemorySize, SM3);
    cudaFuncSetAttribute(scoreK, cudaFuncAttributeMaxDynamicSharedMemorySize, SMS);
    cudaFuncSetAttribute(outV1,  cudaFuncAttributeMaxDynamicSharedMemorySize, SM3);
    cudaFuncSetAttribute(outV2,  cudaFuncAttributeMaxDynamicSharedMemorySize, SM3);

    const dim3 cg(512, 2, 1);
    const dim3 sg(2, 4, 64);
    const dim3 og(32, 2, 16);

    split_x<<<32768, 256>>>(x);
    prep_w<<<768, 256>>>(sq_w, sk_w, sv_w, tq_w, tk_w, tv_w);

    // ---- spatial ----
    convQK<<<cg, 256, SMQ>>>(xh, xl, 128, 0, wh + 0 * 32768, wl + 0 * 32768, 128, 0, 128,
                             sq_b, nullptr, nullptr, 0, nullptr, qh, ql);
    convQK<<<cg, 256, SMQ>>>(xh, xl, 128, 0, wh + 1 * 32768, wl + 1 * 32768, 128, 0, 128,
                             sk_b, nullptr, nullptr, 0, nullptr, kh, kl);
    convV<<<cg, 256, SM3>>>(xh, xl, 128, 0, wh + 2 * 32768, nullptr, 128, 0, 128,
                            sv_b, nullptr, nullptr, 0, nullptr, vh, vl);
    scoreK<<<sg, 256, SMS>>>(qh, ql, 2048, 524288L, kh, kl, 2048, 524288L, 512,
                             nullptr, nullptr, nullptr, 0, attnP, nullptr, nullptr);
    softmax_pack<false><<<512, 256>>>(attnP, attnB);
    outV1<<<og, 256, SM3>>>(vh, vl, 128, 524288L, attnB, nullptr, 128, 32768L, 128,
                            nullptr, s_gamma, x, 259, out, x1h, x1l);

    // ---- temporal ----
    convQK<<<cg, 256, SMQ>>>(x1h, x1l, 128, 0, wh + 3 * 32768, wl + 3 * 32768, 128, 0, 128,
                             tq_b, nullptr, nullptr, 0, nullptr, qh, ql);
    convTK<<<cg, 256, SMQ>>>(xh, xl, 128, 0, wh + 4 * 32768, wl + 4 * 32768, 128, 0, 128,
                             tk_b, nullptr, nullptr, 0, nullptr, kh, kl);
    convV<<<cg, 256, SM3>>>(xh, xl, 128, 0, wh + 5 * 32768, nullptr, 128, 0, 128,
                            tv_b, nullptr, nullptr, 0, nullptr, vh, vl);
    scoreK<<<sg, 256, SMS>>>(qh, ql, 2048, 524288L, kh, kl, 2048, 524288L, 512,
                             nullptr, nullptr, nullptr, 0, attnP, nullptr, nullptr);
    softmax_pack<true><<<512, 256>>>(attnP, attnB);
    outV2<<<og, 256, SM3>>>(vh, vl, 128, 0, attnB, nullptr, 128, 32768L, 128,
                            nullptr, t_gamma, out, 256, out, nullptr, nullptr);
}

// round 12
// speedup vs baseline: 2.1067x; 1.1253x over previous
#include <cuda_runtime.h>
#include <cuda_bf16.h>
#include <cstdint>

// ===========================================================================
// LossRecovery, Gram-matrix formulation.
//   E  = Wq G Wk^T + bq(Wk sx)^T + (Wq sx)bk^T + 4096 bq bk^T,  G = X^T X
//   E2 = Wq' H Wk'^T + ...,  H = X1^T Xsigma  (sigma = spatial transpose)
// Packed-bf16 planes + ldmatrix mma.sync (R11 machinery). Rank-1 terms exact
// in softmax. v convs / out GEMMs unchanged from R11.
// ===========================================================================

__device__ uint32_t g_xh[65536L * 128], g_xl[65536L * 128];      // x  [s][c]
__device__ uint32_t g_xth[16L * 256 * 2048], g_xtl[16L * 256 * 2048]; // x^T [c][s]
__device__ uint32_t g_xsh[16L * 256 * 2048], g_xsl[16L * 256 * 2048]; // x^T permuted
__device__ uint32_t g_x1th[16L * 256 * 2048], g_x1tl[16L * 256 * 2048];
__device__ uint32_t g_wh[6 * 32768], g_wl[6 * 32768];
__device__ uint32_t g_vh[16L * 4096 * 128], g_vl[16L * 4096 * 128];
__device__ float    g_attnP[64L * 65536];
__device__ uint32_t g_attnB[16L * 256 * 128];
__device__ uint32_t g_Gh[16L * 256 * 128], g_Gl[16L * 256 * 128];
__device__ uint32_t g_PTh[16L * 256 * 128], g_PTl[16L * 256 * 128];
__device__ float    g_sx[4096], g_sx1[4096];
__device__ float    g_us[4096], g_vs[4096], g_ut[4096], g_vt[4096];

#define CP16(dst, src) asm volatile("cp.async.cg.shared.global [%0], [%1], 16;\n" :: "r"(dst), "l"(src))
#define CPCOMMIT()     asm volatile("cp.async.commit_group;\n" ::: "memory")
#define CPWAIT(n)      asm volatile("cp.async.wait_group %0;\n" :: "n"(n) : "memory")

#define LDSM4(d0, d1, d2, d3, a) \
    asm volatile("ldmatrix.sync.aligned.m8n8.x4.shared.b16 {%0,%1,%2,%3}, [%4];" \
        : "=r"(d0), "=r"(d1), "=r"(d2), "=r"(d3) : "r"(a))

__device__ __forceinline__ uint32_t pack_hi(float v0, float v1) {
    uint32_t h;
    asm("cvt.rn.bf16x2.f32 %0, %1, %2;" : "=r"(h) : "f"(v1), "f"(v0));
    return h;  // lo half = v0
}
__device__ __forceinline__ void pack_pair(float v0, float v1, uint32_t& h, uint32_t& l) {
    h = pack_hi(v0, v1);
    const float h0 = __uint_as_float(h << 16);
    const float h1 = __uint_as_float(h & 0xFFFF0000u);
    l = pack_hi(v0 - h0, v1 - h1);
}

#define MMA_BF16(ac, a0, a1, a2, a3, b0, b1) \
    asm volatile("mma.sync.aligned.m16n8k16.row.col.f32.bf16.bf16.f32 " \
        "{%0,%1,%2,%3},{%4,%5,%6,%7},{%8,%9},{%0,%1,%2,%3};" \
        : "+f"((ac)[0]), "+f"((ac)[1]), "+f"((ac)[2]), "+f"((ac)[3]) \
        : "r"(a0), "r"(a1), "r"(a2), "r"(a3), "r"(b0), "r"(b1))

// ---------------------------------------------------------------------------
// NT GEMM: C[m,n] = sum_k A[m,k]B[n,k] over packed-bf16 planes.
//  AMODE 0 plain | 2 v2-gather.   EMODE 0 planes+bias | 2 fp32 scores |
//  3 gamma*acc+res (DUAL: also x1^T planes) | 4 transposed planes (P^T).
template <int NPASS, int BPL, int AMODE, int EMODE, bool DUAL>
__global__ __launch_bounds__(256, 2) void gemm(
    const uint32_t* __restrict__ aH, const uint32_t* __restrict__ aL, int aW, long aZ,
    const uint32_t* __restrict__ bH, const uint32_t* __restrict__ bL, int bW, long bZ,
    int KdimW,
    const float* __restrict__ bias, const float* __restrict__ gammaPtr,
    const float* __restrict__ res, int ldr,
    float* __restrict__ outF, uint32_t* __restrict__ outH, uint32_t* __restrict__ outL)
{
    extern __shared__ uint32_t sm[];
    constexpr int ALD = 20;
    constexpr int NT = 128;
    constexpr int STAGEW = 2 * 128 * ALD + BPL * NT * ALD;
    constexpr int NSTAGE = (STAGEW > 8192) ? 2 : 3;
    const uint32_t sbB = (uint32_t)__cvta_generic_to_shared(sm);

    const int tid = threadIdx.x;
    const int wid = tid >> 5, lane = tid & 31;
    const int grp = lane >> 2, tig = lane & 3;
    const int row0 = blockIdx.x * 128, col0 = blockIdx.y * NT;
    const int z = blockIdx.z;
    int zA = z;
    long koffW = 0;
    if (EMODE == 2) { zA = z & 15; koffW = (long)(z >> 4) * KdimW; }

    constexpr int MI = 4;
    const int m_base = (wid >> 2) * 64;
    const int n_base = (wid & 3) * 32;

    float acc[MI][4][4];
#pragma unroll
    for (int mi = 0; mi < MI; mi++)
#pragma unroll
        for (int ni = 0; ni < 4; ni++)
#pragma unroll
            for (int e = 0; e < 4; e++) acc[mi][ni][e] = 0.f;

    const int ar = tid >> 1, hw = (tid & 1) * 8;
    long arow;
    long astep = 16;
    if (AMODE == 0) {
        arow = (long)zA * aZ + (long)(row0 + ar) * aW + koffW + hw;
    } else {  // v2 gather
        const int bq = z >> 3, chHi = z & 7;
        arow = ((long)(bq * 8) * 4096 + (row0 + ar)) * 128 + chHi * 16 + hw;
        astep = 4096L * 128;
    }
    const int bn = tid >> 1, hwB = (tid & 1) * 8;
    const long brow = (long)zA * bZ + (long)(col0 + bn) * bW + koffW + hwB;

    const int nCh = KdimW >> 4;
    const uint32_t ALo = 128 * ALD, BHo = 256 * ALD, BLo = (256 + NT) * ALD;

    auto load_tile = [&](int kc, int s) {
        const long ka = arow + (long)kc * astep;
        const long kb = brow + (long)kc * 16;
        const uint32_t aD = sbB + (uint32_t)(s * STAGEW + ar * ALD + hw) * 4u;
        CP16(aD, aH + ka); CP16(aD + 16u, aH + ka + 4);
        const uint32_t aD2 = aD + ALo * 4u;
        CP16(aD2, aL + ka); CP16(aD2 + 16u, aL + ka + 4);
        const uint32_t bD = sbB + (uint32_t)(s * STAGEW + BHo + bn * ALD + hwB) * 4u;
        CP16(bD, bH + kb); CP16(bD + 16u, bH + kb + 4);
        if (BPL == 2) {
            const uint32_t bD2 = sbB + (uint32_t)(s * STAGEW + BLo + bn * ALD + hwB) * 4u;
            CP16(bD2, bL + kb); CP16(bD2 + 16u, bL + kb + 4);
        }
    };

    const int la7 = lane & 7, lg = lane >> 3;
    const uint32_t aoff = (uint32_t)(((m_base + la7 + ((lg & 1) << 3)) * ALD
                                      + ((lg >> 1) << 2)) * 4);
    const uint32_t boff = (uint32_t)(((n_base + la7 + ((lg >> 1) << 3)) * ALD
                                      + ((lg & 1) << 2)) * 4);

    auto compute = [&](int s) {
        const uint32_t stB = sbB + (uint32_t)(s * STAGEW) * 4u;
#pragma unroll
        for (int ks = 0; ks < 2; ks++) {
            const uint32_t kby = (uint32_t)(ks * 32);
            uint32_t bh[4][2], bl[4][2];
#pragma unroll
            for (int p = 0; p < 2; p++) {
                const uint32_t ba = stB + BHo * 4u + boff + (uint32_t)(p * 16 * ALD * 4) + kby;
                LDSM4(bh[2 * p][0], bh[2 * p][1], bh[2 * p + 1][0], bh[2 * p + 1][1], ba);
                if (BPL == 2) {
                    const uint32_t ba2 = stB + BLo * 4u + boff + (uint32_t)(p * 16 * ALD * 4) + kby;
                    LDSM4(bl[2 * p][0], bl[2 * p][1], bl[2 * p + 1][0], bl[2 * p + 1][1], ba2);
                }
            }
#pragma unroll
            for (int mi = 0; mi < MI; mi++) {
                const uint32_t aa = stB + aoff + (uint32_t)(mi * 16 * ALD * 4) + kby;
                uint32_t ah0, ah1, ah2, ah3, al0, al1, al2, al3;
                LDSM4(ah0, ah1, ah2, ah3, aa);
                LDSM4(al0, al1, al2, al3, aa + ALo * 4u);
#pragma unroll
                for (int ni = 0; ni < 4; ni++)
                    MMA_BF16(acc[mi][ni], ah0, ah1, ah2, ah3, bh[ni][0], bh[ni][1]);
                if (NPASS == 3) {
#pragma unroll
                    for (int ni = 0; ni < 4; ni++)
                        MMA_BF16(acc[mi][ni], ah0, ah1, ah2, ah3, bl[ni][0], bl[ni][1]);
                }
#pragma unroll
                for (int ni = 0; ni < 4; ni++)
                    MMA_BF16(acc[mi][ni], al0, al1, al2, al3, bh[ni][0], bh[ni][1]);
            }
        }
    };

    load_tile(0, 0); CPCOMMIT();
    if (nCh > 1) load_tile(1, 1);
    CPCOMMIT();
    if (NSTAGE == 2) {
        for (int kc = 0; kc < nCh; kc++) {
            CPWAIT(1);
            __syncthreads();
            compute(kc & 1);
            __syncthreads();
            if (kc + 2 < nCh) { load_tile(kc + 2, kc & 1); CPCOMMIT(); }
        }
    } else {
        for (int kc = 0; kc < nCh; kc++) {
            CPWAIT(1);
            __syncthreads();
            const int ld = kc + 2;
            if (ld < nCh) load_tile(ld, ld % 3);
            CPCOMMIT();
            compute(kc % 3);
        }
    }

    // ---- epilogues ----
    if (EMODE == 4) {
        __syncthreads();
        float* sC = (float*)sm;
#pragma unroll
        for (int mi = 0; mi < MI; mi++)
#pragma unroll
            for (int ni = 0; ni < 4; ni++) {
                const int r0 = m_base + mi * 16 + grp;
                const int cb = n_base + ni * 8 + 2 * tig;
                sC[r0 * 133 + cb] = acc[mi][ni][0];
                sC[r0 * 133 + cb + 1] = acc[mi][ni][1];
                sC[(r0 + 8) * 133 + cb] = acc[mi][ni][2];
                sC[(r0 + 8) * 133 + cb + 1] = acc[mi][ni][3];
            }
        __syncthreads();
        const int p = tid & 63, colg = tid >> 6;
        for (int cp = 0; cp < 32; cp++) {
            const int col = cp * 4 + colg;
            const float v0 = sC[(2 * p) * 133 + col];
            const float v1 = sC[(2 * p + 1) * 133 + col];
            uint32_t h, l;
            pack_pair(v0, v1, h, l);
            const long w = ((long)(z * 256 + col0 + col)) * 128 + (row0 >> 1) + p;
            outH[w] = h; outL[w] = l;
        }
    } else if (EMODE == 3 && DUAL) {
        const float gamma = __ldg(gammaPtr);
        __syncthreads();
        float* sC = (float*)sm;
#pragma unroll
        for (int mi = 0; mi < MI; mi++)
#pragma unroll
            for (int ni = 0; ni < 4; ni++) {
                const int r0g = m_base + mi * 16 + grp;
                const int cb = n_base + ni * 8 + 2 * tig;
                const int c = col0 + cb;
#pragma unroll
                for (int half = 0; half < 2; half++) {
                    const int rl = r0g + half * 8;
                    const long rr = (long)z * 4096 + row0 + rl;
                    float v0 = gamma * acc[mi][ni][2 * half]     + res[rr * (long)ldr + c];
                    float v1 = gamma * acc[mi][ni][2 * half + 1] + res[rr * (long)ldr + c + 1];
                    float2 st = {v0, v1};
                    *(float2*)(outF + rr * 256 + c) = st;
                    sC[rl * 133 + cb] = v0;
                    sC[rl * 133 + cb + 1] = v1;
                }
            }
        __syncthreads();
        const int p = tid & 63, colg = tid >> 6;
        for (int cp = 0; cp < 32; cp++) {
            const int col = cp * 4 + colg;
            const float v0 = sC[(2 * p) * 133 + col];
            const float v1 = sC[(2 * p + 1) * 133 + col];
            uint32_t h, l;
            pack_pair(v0, v1, h, l);
            const long w = ((long)(z * 256 + col0 + col)) * 2048 + (row0 >> 1) + p;
            outH[w] = h; outL[w] = l;
        }
    } else {
        float gamma = 0.f;
        if (EMODE == 3) gamma = __ldg(gammaPtr);
#pragma unroll
        for (int mi = 0; mi < MI; mi++)
#pragma unroll
            for (int ni = 0; ni < 4; ni++) {
                const int r0g = m_base + mi * 16 + grp;
                const int cb = n_base + ni * 8 + 2 * tig;
                const int c = col0 + cb;
#pragma unroll
                for (int half = 0; half < 2; half++) {
                    const int r = row0 + r0g + half * 8;
                    float v0 = acc[mi][ni][2 * half];
                    float v1 = acc[mi][ni][2 * half + 1];
                    if (EMODE == 0) {
                        v0 += __ldg(&bias[c]);
                        v1 += __ldg(&bias[c + 1]);
                        uint32_t h, l;
                        pack_pair(v0, v1, h, l);
                        const long w = (long)r * 128 + (c >> 1);
                        outH[w] = h; outL[w] = l;
                    } else if (EMODE == 2) {
                        float2 st = {v0, v1};
                        *(float2*)(outF + (long)z * 65536 + (long)r * 256 + c) = st;
                    } else {
                        const long rr = (long)z * 4096 + r;
                        v0 = gamma * v0 + res[rr * (long)ldr + c];
                        v1 = gamma * v1 + res[rr * (long)ldr + c + 1];
                        float2 st = {v0, v1};
                        *(float2*)(outF + rr * 256 + c) = st;
                    }
                }
            }
    }
}

// ---------------- x -> s-major planes ---------------------------------------
__global__ __launch_bounds__(256) void split_x(const float* __restrict__ x) {
    const long i = (long)blockIdx.x * 256 + threadIdx.x;
    const long r = i >> 7;
    const int c = (int)(i & 127) * 2;
    uint32_t h, l;
    pack_pair(x[r * 259 + c], x[r * 259 + c + 1], h, l);
    g_xh[i] = h; g_xl[i] = l;
}

// ---------------- x -> c-major planes (opt. sigma-permuted source rows) ----
template <bool PERM>
__global__ __launch_bounds__(256) void transpose_x(const float* __restrict__ x,
                                                   uint32_t* __restrict__ th,
                                                   uint32_t* __restrict__ tl) {
    __shared__ float tile[64][65];
    const int st = blockIdx.x, ct = blockIdx.y, z = blockIdx.z;
    const int t = threadIdx.x;
#pragma unroll
    for (int j = 0; j < 16; j++) {
        const int i = (t >> 6) + j * 4;
        const int col = t & 63;
        const int ssrc = PERM ? (i * 64 + st) : (st * 64 + i);
        tile[i][col] = x[((long)(z * 4096 + ssrc)) * 259 + ct * 64 + col];
    }
    __syncthreads();
#pragma unroll
    for (int j = 0; j < 8; j++) {
        const int cl = (t >> 5) + j * 8;
        const int wi = t & 31;
        uint32_t h, l;
        pack_pair(tile[2 * wi][cl], tile[2 * wi + 1][cl], h, l);
        const long w = ((long)(z * 256 + ct * 64 + cl)) * 2048 + st * 32 + wi;
        th[w] = h; tl[w] = l;
    }
}

// ---------------- weights -> planes ----------------------------------------
__global__ __launch_bounds__(256) void prep_w(const float* w0, const float* w1,
                                              const float* w2, const float* w3,
                                              const float* w4, const float* w5) {
    const int id = blockIdx.x * 256 + threadIdx.x;
    const int m = id >> 15, rc = id & 32767;
    const float* w = (m == 0) ? w0 : (m == 1) ? w1 : (m == 2) ? w2
                   : (m == 3) ? w3 : (m == 4) ? w4 : w5;
    uint32_t h, l;
    pack_pair(w[rc * 2], w[rc * 2 + 1], h, l);
    g_wh[id] = h; g_wl[id] = l;
}

// ---------------- row sums of c-major planes: sig[z,c] = sum_s -------------
__global__ __launch_bounds__(256) void rowsum(const uint32_t* __restrict__ ph,
                                              const uint32_t* __restrict__ pl,
                                              float* __restrict__ o) {
    const int row = blockIdx.x * 8 + (threadIdx.x >> 5);
    const int lane = threadIdx.x & 31;
    const uint32_t* a = ph + (long)row * 2048;
    const uint32_t* b = pl + (long)row * 2048;
    float s = 0.f;
    for (int i = lane; i < 2048; i += 32) {
        const uint32_t w = a[i], u = b[i];
        s += __uint_as_float(w << 16) + __uint_as_float(w & 0xFFFF0000u)
           + __uint_as_float(u << 16) + __uint_as_float(u & 0xFFFF0000u);
    }
#pragma unroll
    for (int ofs = 16; ofs; ofs >>= 1) s += __shfl_xor_sync(0xffffffffu, s, ofs);
    if (lane == 0) o[row] = s;
}

// ---------------- matvec: o[z,d] = sum_c W[d,c] sig[z,c] -------------------
__global__ __launch_bounds__(256) void matvec(const float* __restrict__ W,
                                              const float* __restrict__ sig,
                                              float* __restrict__ o) {
    const int z = blockIdx.x, d = threadIdx.x;
    const float* w = W + (long)d * 256;
    const float* g = sig + z * 256;
    float s = 0.f;
    for (int c = 0; c < 256; c++) s += w[c] * g[c];
    o[z * 256 + d] = s;
}

// ---------------- sum 4 split-K partials -> packed planes ------------------
__global__ __launch_bounds__(256) void combine_pack(const float* __restrict__ P,
                                                    uint32_t* __restrict__ gh,
                                                    uint32_t* __restrict__ gl) {
    const long i = (long)blockIdx.x * 256 + threadIdx.x;   // 524288 words
    const long e = i * 2;
    const float v0 = P[e] + P[e + 1048576] + P[e + 2097152] + P[e + 3145728];
    const float v1 = P[e + 1] + P[e + 1 + 1048576] + P[e + 1 + 2097152] + P[e + 1 + 3145728];
    uint32_t h, l;
    pack_pair(v0, v1, h, l);
    gh[i] = h; gl[i] = l;
}

// ---------------- softmax with rank-1 bias terms, pack (opt. permuted) -----
template <bool PERM>
__global__ __launch_bounds__(256) void softmax_rank1(
    const float* __restrict__ S, const float* __restrict__ u,
    const float* __restrict__ vvec, const float* __restrict__ bq,
    const float* __restrict__ bk, uint32_t* __restrict__ O)
{
    __shared__ float srow[8][256];
    const int wid = threadIdx.x >> 5, lane = threadIdx.x & 31;
    const int row = blockIdx.x * 8 + wid;
    const int z = row >> 8, c = row & 255;
    const float bqc = bq[c], vc = vvec[z * 256 + c];
    const float* p = S + (long)row * 256;
    float vv[8];
    float mx = -1e30f;
#pragma unroll
    for (int j = 0; j < 8; j++) {
        const int d = lane * 8 + j;
        const float bkd = bk[d];
        vv[j] = p[d] + bqc * (u[z * 256 + d] + 4096.f * bkd) + bkd * vc;
        mx = fmaxf(mx, vv[j]);
    }
#pragma unroll
    for (int o = 16; o; o >>= 1) mx = fmaxf(mx, __shfl_xor_sync(0xffffffffu, mx, o));
    float s = 0.f;
#pragma unroll
    for (int j = 0; j < 8; j++) { vv[j] = __expf(vv[j] - mx); s += vv[j]; }
#pragma unroll
    for (int o = 16; o; o >>= 1) s += __shfl_xor_sync(0xffffffffu, s, o);
    const float inv = 1.f / s;
#pragma unroll
    for (int j = 0; j < 8; j++) srow[wid][lane * 8 + j] = vv[j] * inv;
    __syncwarp();
#pragma unroll
    for (int t = 0; t < 4; t++) {
        const int m = lane * 4 + t;
        int d0 = 2 * m, d1 = 2 * m + 1;
        if (PERM) {
            d0 = ((d0 & 31) << 3) | (d0 >> 5);
            d1 = ((d1 & 31) << 3) | (d1 >> 5);
        }
        O[(long)row * 128 + m] = pack_hi(srow[wid][d0], srow[wid][d1]);
    }
}

// ---------------- launch ----------------------------------------------------
extern "C" void kernel_launch(void* const* d_in, const int* in_sizes, int n_in,
                              void* d_out, int out_size)
{
    const float* x    = (const float*)d_in[0];
    const float* sq_w = (const float*)d_in[3];
    const float* sq_b = (const float*)d_in[4];
    const float* sk_w = (const float*)d_in[5];
    const float* sk_b = (const float*)d_in[6];
    const float* sv_w = (const float*)d_in[7];
    const float* sv_b = (const float*)d_in[8];
    const float* tq_w = (const float*)d_in[9];
    const float* tq_b = (const float*)d_in[10];
    const float* tk_w = (const float*)d_in[11];
    const float* tk_b = (const float*)d_in[12];
    const float* tv_w = (const float*)d_in[13];
    const float* tv_b = (const float*)d_in[14];
    const float* s_gamma = (const float*)d_in[15];
    const float* t_gamma = (const float*)d_in[16];
    float* out = (float*)d_out;

    uint32_t *xh, *xl, *xth, *xtl, *xsh, *xsl, *x1th, *x1tl, *wh, *wl;
    uint32_t *vh, *vl, *attnB, *Gh, *Gl, *PTh, *PTl;
    float *attnP, *sx, *sx1, *us, *vs, *ut, *vt;
    cudaGetSymbolAddress((void**)&xh, g_xh);     cudaGetSymbolAddress((void**)&xl, g_xl);
    cudaGetSymbolAddress((void**)&xth, g_xth);   cudaGetSymbolAddress((void**)&xtl, g_xtl);
    cudaGetSymbolAddress((void**)&xsh, g_xsh);   cudaGetSymbolAddress((void**)&xsl, g_xsl);
    cudaGetSymbolAddress((void**)&x1th, g_x1th); cudaGetSymbolAddress((void**)&x1tl, g_x1tl);
    cudaGetSymbolAddress((void**)&wh, g_wh);     cudaGetSymbolAddress((void**)&wl, g_wl);
    cudaGetSymbolAddress((void**)&vh, g_vh);     cudaGetSymbolAddress((void**)&vl, g_vl);
    cudaGetSymbolAddress((void**)&attnP, g_attnP);
    cudaGetSymbolAddress((void**)&attnB, g_attnB);
    cudaGetSymbolAddress((void**)&Gh, g_Gh);     cudaGetSymbolAddress((void**)&Gl, g_Gl);
    cudaGetSymbolAddress((void**)&PTh, g_PTh);   cudaGetSymbolAddress((void**)&PTl, g_PTl);
    cudaGetSymbolAddress((void**)&sx, g_sx);     cudaGetSymbolAddress((void**)&sx1, g_sx1);
    cudaGetSymbolAddress((void**)&us, g_us);     cudaGetSymbolAddress((void**)&vs, g_vs);
    cudaGetSymbolAddress((void**)&ut, g_ut);     cudaGetSymbolAddress((void**)&vt, g_vt);

    auto convV = gemm<2, 1, 0, 0, false>;   // sv, tv (x planes -> v planes)
    auto bigNT = gemm<3, 2, 0, 2, false>;   // G / H (split-K=4) and S (z=16)
    auto Pk    = gemm<3, 2, 0, 4, false>;   // P -> P^T planes
    auto outV1 = gemm<2, 1, 0, 3, true>;    // spatial out (+x1^T planes)
    auto outV2 = gemm<2, 1, 2, 3, false>;   // temporal out (v2 gather)

    const int SMQ = 2 * (2 * 128 * 20 + 2 * 128 * 20) * 4;   // 81920
    const int SM3 = 3 * (2 * 128 * 20 + 1 * 128 * 20) * 4;   // 92160
    cudaFuncSetAttribute(convV, cudaFuncAttributeMaxDynamicSharedMemorySize, SM3);
    cudaFuncSetAttribute(bigNT, cudaFuncAttributeMaxDynamicSharedMemorySize, SMQ);
    cudaFuncSetAttribute(Pk,    cudaFuncAttributeMaxDynamicSharedMemorySize, SMQ);
    cudaFuncSetAttribute(outV1, cudaFuncAttributeMaxDynamicSharedMemorySize, SM3);
    cudaFuncSetAttribute(outV2, cudaFuncAttributeMaxDynamicSharedMemorySize, SM3);

    const dim3 tg(64, 4, 16);
    const dim3 cg(512, 2, 1);
    const dim3 gg(2, 2, 64);
    const dim3 pg(2, 2, 16);
    const dim3 og(32, 2, 16);

    split_x<<<32768, 256>>>(x);
    transpose_x<false><<<tg, 256>>>(x, xth, xtl);
    transpose_x<true><<<tg, 256>>>(x, xsh, xsl);
    prep_w<<<768, 256>>>(sq_w, sk_w, sv_w, tq_w, tk_w, tv_w);
    rowsum<<<512, 256>>>(xth, xtl, sx);
    matvec<<<16, 256>>>(sk_w, sx, us);
    matvec<<<16, 256>>>(sq_w, sx, vs);
    matvec<<<16, 256>>>(tk_w, sx, ut);

    // ---- spatial ----
    convV<<<cg, 256, SM3>>>(xh, xl, 128, 0, wh + 2 * 32768, nullptr, 128, 0, 128,
                            sv_b, nullptr, nullptr, 0, nullptr, vh, vl);
    bigNT<<<gg, 256, SMQ>>>(xth, xtl, 2048, 524288L, xth, xtl, 2048, 524288L, 512,
                            nullptr, nullptr, nullptr, 0, attnP, nullptr, nullptr);
    combine_pack<<<2048, 256>>>(attnP, Gh, Gl);
    Pk<<<pg, 256, SMQ>>>(Gh, Gl, 128, 32768L, wh + 1 * 32768, wl + 1 * 32768, 128, 0, 128,
                         nullptr, nullptr, nullptr, 0, nullptr, PTh, PTl);
    bigNT<<<pg, 256, SMQ>>>(wh + 0 * 32768, wl + 0 * 32768, 128, 0, PTh, PTl, 128, 32768L, 128,
                            nullptr, nullptr, nullptr, 0, attnP, nullptr, nullptr);
    softmax_rank1<false><<<512, 256>>>(attnP, us, vs, sq_b, sk_b, attnB);
    outV1<<<og, 256, SM3>>>(vh, vl, 128, 524288L, attnB, nullptr, 128, 32768L, 128,
                            nullptr, s_gamma, x, 259, out, x1th, x1tl);

    // ---- temporal ----
    rowsum<<<512, 256>>>(x1th, x1tl, sx1);
    matvec<<<16, 256>>>(tq_w, sx1, vt);
    convV<<<cg, 256, SM3>>>(xh, xl, 128, 0, wh + 5 * 32768, nullptr, 128, 0, 128,
                            tv_b, nullptr, nullptr, 0, nullptr, vh, vl);
    bigNT<<<gg, 256, SMQ>>>(x1th, x1tl, 2048, 524288L, xsh, xsl, 2048, 524288L, 512,
                            nullptr, nullptr, nullptr, 0, attnP, nullptr, nullptr);
    combine_pack<<<2048, 256>>>(attnP, Gh, Gl);
    Pk<<<pg, 256, SMQ>>>(Gh, Gl, 128, 32768L, wh + 4 * 32768, wl + 4 * 32768, 128, 0, 128,
                         nullptr, nullptr, nullptr, 0, nullptr, PTh, PTl);
    bigNT<<<pg, 256, SMQ>>>(wh + 3 * 32768, wl + 3 * 32768, 128, 0, PTh, PTl, 128, 32768L, 128,
                            nullptr, nullptr, nullptr, 0, attnP, nullptr, nullptr);
    softmax_rank1<true><<<512, 256>>>(attnP, ut, vt, tq_b, tk_b, attnB);
    outV2<<<og, 256, SM3>>>(vh, vl, 128, 0, attnB, nullptr, 128, 32768L, 128,
                            nullptr, t_gamma, out, 256, out, nullptr, nullptr);
}

// round 13
// speedup vs baseline: 2.6773x; 1.2709x over previous
#include <cuda_runtime.h>
#include <cuda_bf16.h>
#include <cstdint>

// ===========================================================================
// LossRecovery, Gram formulation + lean precision budget.
//   E  = Wq G Wk^T + rank-1 bias terms,  G = X^T X (symmetric: 3 of 4 tiles)
//   E2 = Wq' H Wk'^T + ...,              H = X1^T Xsigma
// q/k/score path: 3-pass bf16 split (exact-enough). v convs + out GEMMs:
// 1-pass bf16-hi (error lands under gamma~0.1). Residual adds stay fp32.
// ===========================================================================

__device__ uint32_t g_xh[65536L * 128];                               // x hi, s-major
__device__ uint32_t g_xth[16L * 256 * 2048], g_xtl[16L * 256 * 2048]; // x^T planes
__device__ uint32_t g_xsh[16L * 256 * 2048], g_xsl[16L * 256 * 2048]; // x^T sigma-perm
__device__ uint32_t g_x1th[16L * 256 * 2048], g_x1tl[16L * 256 * 2048];
__device__ uint32_t g_wh[6 * 32768], g_wl[6 * 32768];
__device__ uint32_t g_vh[16L * 4096 * 128];
__device__ float    g_attnP[64L * 65536];
__device__ uint32_t g_attnB[16L * 256 * 128];
__device__ uint32_t g_Gh[16L * 256 * 128], g_Gl[16L * 256 * 128];
__device__ uint32_t g_PTh[16L * 256 * 128], g_PTl[16L * 256 * 128];
__device__ float    g_sx[4096], g_sx1[4096];
__device__ float    g_us[4096], g_vs[4096], g_ut[4096], g_vt[4096];

#define CP16(dst, src) asm volatile("cp.async.cg.shared.global [%0], [%1], 16;\n" :: "r"(dst), "l"(src))
#define CPCOMMIT()     asm volatile("cp.async.commit_group;\n" ::: "memory")
#define CPWAIT(n)      asm volatile("cp.async.wait_group %0;\n" :: "n"(n) : "memory")

#define LDSM4(d0, d1, d2, d3, a) \
    asm volatile("ldmatrix.sync.aligned.m8n8.x4.shared.b16 {%0,%1,%2,%3}, [%4];" \
        : "=r"(d0), "=r"(d1), "=r"(d2), "=r"(d3) : "r"(a))

__device__ __forceinline__ uint32_t pack_hi(float v0, float v1) {
    uint32_t h;
    asm("cvt.rn.bf16x2.f32 %0, %1, %2;" : "=r"(h) : "f"(v1), "f"(v0));
    return h;  // lo half = v0
}
__device__ __forceinline__ void pack_pair(float v0, float v1, uint32_t& h, uint32_t& l) {
    h = pack_hi(v0, v1);
    const float h0 = __uint_as_float(h << 16);
    const float h1 = __uint_as_float(h & 0xFFFF0000u);
    l = pack_hi(v0 - h0, v1 - h1);
}

#define MMA_BF16(ac, a0, a1, a2, a3, b0, b1) \
    asm volatile("mma.sync.aligned.m16n8k16.row.col.f32.bf16.bf16.f32 " \
        "{%0,%1,%2,%3},{%4,%5,%6,%7},{%8,%9},{%0,%1,%2,%3};" \
        : "+f"((ac)[0]), "+f"((ac)[1]), "+f"((ac)[2]), "+f"((ac)[3]) \
        : "r"(a0), "r"(a1), "r"(a2), "r"(a3), "r"(b0), "r"(b1))

// ---------------------------------------------------------------------------
// NT GEMM over packed-bf16 planes. NPASS: 1 = AhBh; 2 = +AlBh; 3 = +AhBl.
//  AMODE 0 plain | 2 v2-gather.   EMODE 0 hi-plane+bias | 2 fp32 scores |
//  3 gamma*acc+res (DUAL: also x1^T planes) | 4 transposed planes (P^T).
//  SYMM: skip block (1,0) (symmetric score output, mirrored in combine).
template <int NPASS, int BPL, int AMODE, int EMODE, bool DUAL, bool SYMM>
__global__ __launch_bounds__(256, 2) void gemm(
    const uint32_t* __restrict__ aH, const uint32_t* __restrict__ aL, int aW, long aZ,
    const uint32_t* __restrict__ bH, const uint32_t* __restrict__ bL, int bW, long bZ,
    int KdimW,
    const float* __restrict__ bias, const float* __restrict__ gammaPtr,
    const float* __restrict__ res, int ldr,
    float* __restrict__ outF, uint32_t* __restrict__ outH, uint32_t* __restrict__ outL)
{
    if (SYMM && blockIdx.x == 1 && blockIdx.y == 0) return;

    extern __shared__ uint32_t sm[];
    constexpr int ALD = 20;
    constexpr int APL = (NPASS >= 2) ? 2 : 1;
    constexpr int STAGEW = (APL * 128 + BPL * 128) * ALD;
    constexpr int NSTAGE = (STAGEW > 8192) ? 2 : 3;
    const uint32_t sbB = (uint32_t)__cvta_generic_to_shared(sm);

    const int tid = threadIdx.x;
    const int wid = tid >> 5, lane = tid & 31;
    const int grp = lane >> 2, tig = lane & 3;
    const int row0 = blockIdx.x * 128, col0 = blockIdx.y * 128;
    const int z = blockIdx.z;
    int zA = z;
    long koffW = 0;
    if (EMODE == 2) { zA = z & 15; koffW = (long)(z >> 4) * KdimW; }

    constexpr int MI = 4;
    const int m_base = (wid >> 2) * 64;
    const int n_base = (wid & 3) * 32;

    float acc[MI][4][4];
#pragma unroll
    for (int mi = 0; mi < MI; mi++)
#pragma unroll
        for (int ni = 0; ni < 4; ni++)
#pragma unroll
            for (int e = 0; e < 4; e++) acc[mi][ni][e] = 0.f;

    const int ar = tid >> 1, hw = (tid & 1) * 8;
    long arow;
    long astep = 16;
    if (AMODE == 0) {
        arow = (long)zA * aZ + (long)(row0 + ar) * aW + koffW + hw;
    } else {  // v2 gather
        const int bq = z >> 3, chHi = z & 7;
        arow = ((long)(bq * 8) * 4096 + (row0 + ar)) * 128 + chHi * 16 + hw;
        astep = 4096L * 128;
    }
    const int bn = tid >> 1, hwB = (tid & 1) * 8;
    const long brow = (long)zA * bZ + (long)(col0 + bn) * bW + koffW + hwB;

    const int nCh = KdimW >> 4;
    const uint32_t ALo = 128 * ALD;
    const uint32_t BHo = APL * 128 * ALD;
    const uint32_t BLo = BHo + 128 * ALD;

    auto load_tile = [&](int kc, int s) {
        const long ka = arow + (long)kc * astep;
        const long kb = brow + (long)kc * 16;
        const uint32_t aD = sbB + (uint32_t)(s * STAGEW + ar * ALD + hw) * 4u;
        CP16(aD, aH + ka); CP16(aD + 16u, aH + ka + 4);
        if (APL == 2) {
            const uint32_t aD2 = aD + ALo * 4u;
            CP16(aD2, aL + ka); CP16(aD2 + 16u, aL + ka + 4);
        }
        const uint32_t bD = sbB + (uint32_t)(s * STAGEW + BHo + bn * ALD + hwB) * 4u;
        CP16(bD, bH + kb); CP16(bD + 16u, bH + kb + 4);
        if (BPL == 2) {
            const uint32_t bD2 = sbB + (uint32_t)(s * STAGEW + BLo + bn * ALD + hwB) * 4u;
            CP16(bD2, bL + kb); CP16(bD2 + 16u, bL + kb + 4);
        }
    };

    const int la7 = lane & 7, lg = lane >> 3;
    const uint32_t aoff = (uint32_t)(((m_base + la7 + ((lg & 1) << 3)) * ALD
                                      + ((lg >> 1) << 2)) * 4);
    const uint32_t boff = (uint32_t)(((n_base + la7 + ((lg >> 1) << 3)) * ALD
                                      + ((lg & 1) << 2)) * 4);

    auto compute = [&](int s) {
        const uint32_t stB = sbB + (uint32_t)(s * STAGEW) * 4u;
#pragma unroll
        for (int ks = 0; ks < 2; ks++) {
            const uint32_t kby = (uint32_t)(ks * 32);
            uint32_t bh[4][2], bl[4][2];
#pragma unroll
            for (int p = 0; p < 2; p++) {
                const uint32_t ba = stB + BHo * 4u + boff + (uint32_t)(p * 16 * ALD * 4) + kby;
                LDSM4(bh[2 * p][0], bh[2 * p][1], bh[2 * p + 1][0], bh[2 * p + 1][1], ba);
                if (BPL == 2) {
                    const uint32_t ba2 = stB + BLo * 4u + boff + (uint32_t)(p * 16 * ALD * 4) + kby;
                    LDSM4(bl[2 * p][0], bl[2 * p][1], bl[2 * p + 1][0], bl[2 * p + 1][1], ba2);
                }
            }
#pragma unroll
            for (int mi = 0; mi < MI; mi++) {
                const uint32_t aa = stB + aoff + (uint32_t)(mi * 16 * ALD * 4) + kby;
                uint32_t ah0, ah1, ah2, ah3;
                LDSM4(ah0, ah1, ah2, ah3, aa);
#pragma unroll
                for (int ni = 0; ni < 4; ni++)
                    MMA_BF16(acc[mi][ni], ah0, ah1, ah2, ah3, bh[ni][0], bh[ni][1]);
                if (NPASS == 3) {
#pragma unroll
                    for (int ni = 0; ni < 4; ni++)
                        MMA_BF16(acc[mi][ni], ah0, ah1, ah2, ah3, bl[ni][0], bl[ni][1]);
                }
                if (NPASS >= 2) {
                    uint32_t al0, al1, al2, al3;
                    LDSM4(al0, al1, al2, al3, aa + ALo * 4u);
#pragma unroll
                    for (int ni = 0; ni < 4; ni++)
                        MMA_BF16(acc[mi][ni], al0, al1, al2, al3, bh[ni][0], bh[ni][1]);
                }
            }
        }
    };

    load_tile(0, 0); CPCOMMIT();
    if (nCh > 1) load_tile(1, 1);
    CPCOMMIT();
    if (NSTAGE == 2) {
        for (int kc = 0; kc < nCh; kc++) {
            CPWAIT(1);
            __syncthreads();
            compute(kc & 1);
            __syncthreads();
            if (kc + 2 < nCh) { load_tile(kc + 2, kc & 1); CPCOMMIT(); }
        }
    } else {
        for (int kc = 0; kc < nCh; kc++) {
            CPWAIT(1);
            __syncthreads();
            const int ld = kc + 2;
            if (ld < nCh) load_tile(ld, ld % 3);
            CPCOMMIT();
            compute(kc % 3);
        }
    }

    // ---- epilogues ----
    if (EMODE == 4) {
        __syncthreads();
        float* sC = (float*)sm;
#pragma unroll
        for (int mi = 0; mi < MI; mi++)
#pragma unroll
            for (int ni = 0; ni < 4; ni++) {
                const int r0 = m_base + mi * 16 + grp;
                const int cb = n_base + ni * 8 + 2 * tig;
                sC[r0 * 133 + cb] = acc[mi][ni][0];
                sC[r0 * 133 + cb + 1] = acc[mi][ni][1];
                sC[(r0 + 8) * 133 + cb] = acc[mi][ni][2];
                sC[(r0 + 8) * 133 + cb + 1] = acc[mi][ni][3];
            }
        __syncthreads();
        const int p = tid & 63, colg = tid >> 6;
        for (int cp = 0; cp < 32; cp++) {
            const int col = cp * 4 + colg;
            uint32_t h, l;
            pack_pair(sC[(2 * p) * 133 + col], sC[(2 * p + 1) * 133 + col], h, l);
            const long w = ((long)(z * 256 + col0 + col)) * 128 + (row0 >> 1) + p;
            outH[w] = h; outL[w] = l;
        }
    } else if (EMODE == 3 && DUAL) {
        const float gamma = __ldg(gammaPtr);
        __syncthreads();
        float* sC = (float*)sm;
#pragma unroll
        for (int mi = 0; mi < MI; mi++)
#pragma unroll
            for (int ni = 0; ni < 4; ni++) {
                const int r0g = m_base + mi * 16 + grp;
                const int cb = n_base + ni * 8 + 2 * tig;
                const int c = col0 + cb;
#pragma unroll
                for (int half = 0; half < 2; half++) {
                    const int rl = r0g + half * 8;
                    const long rr = (long)z * 4096 + row0 + rl;
                    float v0 = gamma * acc[mi][ni][2 * half]     + res[rr * (long)ldr + c];
                    float v1 = gamma * acc[mi][ni][2 * half + 1] + res[rr * (long)ldr + c + 1];
                    float2 st = {v0, v1};
                    *(float2*)(outF + rr * 256 + c) = st;
                    sC[rl * 133 + cb] = v0;
                    sC[rl * 133 + cb + 1] = v1;
                }
            }
        __syncthreads();
        const int p = tid & 63, colg = tid >> 6;
        for (int cp = 0; cp < 32; cp++) {
            const int col = cp * 4 + colg;
            uint32_t h, l;
            pack_pair(sC[(2 * p) * 133 + col], sC[(2 * p + 1) * 133 + col], h, l);
            const long w = ((long)(z * 256 + col0 + col)) * 2048 + (row0 >> 1) + p;
            outH[w] = h; outL[w] = l;
        }
    } else {
        float gamma = 0.f;
        if (EMODE == 3) gamma = __ldg(gammaPtr);
#pragma unroll
        for (int mi = 0; mi < MI; mi++)
#pragma unroll
            for (int ni = 0; ni < 4; ni++) {
                const int r0g = m_base + mi * 16 + grp;
                const int cb = n_base + ni * 8 + 2 * tig;
                const int c = col0 + cb;
#pragma unroll
                for (int half = 0; half < 2; half++) {
                    const int r = row0 + r0g + half * 8;
                    float v0 = acc[mi][ni][2 * half];
                    float v1 = acc[mi][ni][2 * half + 1];
                    if (EMODE == 0) {
                        v0 += __ldg(&bias[c]);
                        v1 += __ldg(&bias[c + 1]);
                        outH[(long)r * 128 + (c >> 1)] = pack_hi(v0, v1);
                    } else if (EMODE == 2) {
                        float2 st = {v0, v1};
                        *(float2*)(outF + (long)z * 65536 + (long)r * 256 + c) = st;
                    } else {
                        const long rr = (long)z * 4096 + r;
                        v0 = gamma * v0 + res[rr * (long)ldr + c];
                        v1 = gamma * v1 + res[rr * (long)ldr + c + 1];
                        float2 st = {v0, v1};
                        *(float2*)(outF + rr * 256 + c) = st;
                    }
                }
            }
    }
}

// ---------------- fused: x -> xh (s-major hi) + xth/xtl (c-major planes) ----
__global__ __launch_bounds__(256) void prep_x(const float* __restrict__ x) {
    __shared__ float tile[128][65];
    const int st = blockIdx.x;   // 128 s rows
    const int ct = blockIdx.y;   // 64 c cols
    const int z  = blockIdx.z;
    const int t = threadIdx.x;
    const int col = t & 63, r4 = t >> 6;
    const long base = ((long)z * 4096 + st * 128) * 259 + ct * 64;
#pragma unroll
    for (int j = 0; j < 32; j++) {
        const int row = r4 + j * 4;
        tile[row][col] = x[base + (long)row * 259 + col];
    }
    __syncthreads();
#pragma unroll
    for (int k = 0; k < 16; k++) {
        const int idx = t + k * 256;
        const int row = idx >> 5, jw = idx & 31;
        g_xh[((long)z * 4096 + st * 128 + row) * 128 + ct * 32 + jw]
            = pack_hi(tile[row][2 * jw], tile[row][2 * jw + 1]);
    }
#pragma unroll
    for (int k = 0; k < 16; k++) {
        const int idx = t + k * 256;
        const int c = idx >> 6, p = idx & 63;
        uint32_t h, l;
        pack_pair(tile[2 * p][c], tile[2 * p + 1][c], h, l);
        const long w = ((long)z * 256 + ct * 64 + c) * 2048 + st * 64 + p;
        g_xth[w] = h; g_xtl[w] = l;
    }
}

// ---------------- sigma-permuted x^T planes ---------------------------------
__global__ __launch_bounds__(256) void transpose_xs(const float* __restrict__ x) {
    __shared__ float tile[64][65];
    const int st = blockIdx.x, ct = blockIdx.y, z = blockIdx.z;
    const int t = threadIdx.x;
#pragma unroll
    for (int j = 0; j < 16; j++) {
        const int i = (t >> 6) + j * 4;
        const int col = t & 63;
        tile[i][col] = x[((long)(z * 4096 + i * 64 + st)) * 259 + ct * 64 + col];
    }
    __syncthreads();
#pragma unroll
    for (int j = 0; j < 8; j++) {
        const int cl = (t >> 5) + j * 8;
        const int wi = t & 31;
        uint32_t h, l;
        pack_pair(tile[2 * wi][cl], tile[2 * wi + 1][cl], h, l);
        const long w = ((long)(z * 256 + ct * 64 + cl)) * 2048 + st * 32 + wi;
        g_xsh[w] = h; g_xsl[w] = l;
    }
}

// ---------------- weights -> planes ----------------------------------------
__global__ __launch_bounds__(256) void prep_w(const float* w0, const float* w1,
                                              const float* w2, const float* w3,
                                              const float* w4, const float* w5) {
    const int id = blockIdx.x * 256 + threadIdx.x;
    const int m = id >> 15, rc = id & 32767;
    const float* w = (m == 0) ? w0 : (m == 1) ? w1 : (m == 2) ? w2
                   : (m == 3) ? w3 : (m == 4) ? w4 : w5;
    uint32_t h, l;
    pack_pair(w[rc * 2], w[rc * 2 + 1], h, l);
    g_wh[id] = h; g_wl[id] = l;
}

// ---------------- row sums of c-major planes --------------------------------
__global__ __launch_bounds__(256) void rowsum(const uint32_t* __restrict__ ph,
                                              const uint32_t* __restrict__ pl,
                                              float* __restrict__ o) {
    const int row = blockIdx.x * 8 + (threadIdx.x >> 5);
    const int lane = threadIdx.x & 31;
    const uint32_t* a = ph + (long)row * 2048;
    const uint32_t* b = pl + (long)row * 2048;
    float s = 0.f;
    for (int i = lane; i < 2048; i += 32) {
        const uint32_t w = a[i], u = b[i];
        s += __uint_as_float(w << 16) + __uint_as_float(w & 0xFFFF0000u)
           + __uint_as_float(u << 16) + __uint_as_float(u & 0xFFFF0000u);
    }
#pragma unroll
    for (int ofs = 16; ofs; ofs >>= 1) s += __shfl_xor_sync(0xffffffffu, s, ofs);
    if (lane == 0) o[row] = s;
}

// ---------------- matvecs -------------------------------------------------
__global__ __launch_bounds__(256) void matvec3(const float* Wa, const float* Wb,
                                               const float* Wc, const float* sig,
                                               float* oa, float* ob, float* oc) {
    const int z = blockIdx.x, d = threadIdx.x, m = blockIdx.y;
    const float* W = (m == 0) ? Wa : (m == 1) ? Wb : Wc;
    float* o = (m == 0) ? oa : (m == 1) ? ob : oc;
    const float* w = W + (long)d * 256;
    const float* g = sig + z * 256;
    float s = 0.f;
    for (int c = 0; c < 256; c++) s += w[c] * g[c];
    o[z * 256 + d] = s;
}
__global__ __launch_bounds__(256) void matvec(const float* __restrict__ W,
                                              const float* __restrict__ sig,
                                              float* __restrict__ o) {
    const int z = blockIdx.x, d = threadIdx.x;
    const float* w = W + (long)d * 256;
    const float* g = sig + z * 256;
    float s = 0.f;
    for (int c = 0; c < 256; c++) s += w[c] * g[c];
    o[z * 256 + d] = s;
}

// ---------------- sum 4 split-K partials -> packed planes (opt. mirror) ----
template <bool MIRROR>
__global__ __launch_bounds__(256) void combine_pack(const float* __restrict__ P,
                                                    uint32_t* __restrict__ gh,
                                                    uint32_t* __restrict__ gl) {
    const long i = (long)blockIdx.x * 256 + threadIdx.x;   // 524288 words
    const int z = (int)(i >> 15);
    const int r = (int)(i & 32767);
    const int c = r >> 7, dw = r & 127;
    float v0, v1;
    if (MIRROR && c >= 128 && dw < 64) {
        const long e0 = (long)z * 65536 + (2 * dw) * 256 + c;
        const long e1 = e0 + 256;
        v0 = P[e0] + P[e0 + 1048576] + P[e0 + 2097152] + P[e0 + 3145728];
        v1 = P[e1] + P[e1 + 1048576] + P[e1 + 2097152] + P[e1 + 3145728];
    } else {
        const long e = (long)z * 65536 + c * 256 + 2 * dw;
        v0 = P[e] + P[e + 1048576] + P[e + 2097152] + P[e + 3145728];
        v1 = P[e + 1] + P[e + 1 + 1048576] + P[e + 1 + 2097152] + P[e + 1 + 3145728];
    }
    uint32_t h, l;
    pack_pair(v0, v1, h, l);
    gh[i] = h; gl[i] = l;
}

// ---------------- softmax with rank-1 bias terms, pack (opt. permuted) -----
template <bool PERM>
__global__ __launch_bounds__(256) void softmax_rank1(
    const float* __restrict__ S, const float* __restrict__ u,
    const float* __restrict__ vvec, const float* __restrict__ bq,
    const float* __restrict__ bk, uint32_t* __restrict__ O)
{
    __shared__ float srow[8][256];
    const int wid = threadIdx.x >> 5, lane = threadIdx.x & 31;
    const int row = blockIdx.x * 8 + wid;
    const int z = row >> 8, c = row & 255;
    const float bqc = bq[c], vc = vvec[z * 256 + c];
    const float* p = S + (long)row * 256;
    float vv[8];
    float mx = -1e30f;
#pragma unroll
    for (int j = 0; j < 8; j++) {
        const int d = lane * 8 + j;
        const float bkd = bk[d];
        vv[j] = p[d] + bqc * (u[z * 256 + d] + 4096.f * bkd) + bkd * vc;
        mx = fmaxf(mx, vv[j]);
    }
#pragma unroll
    for (int o = 16; o; o >>= 1) mx = fmaxf(mx, __shfl_xor_sync(0xffffffffu, mx, o));
    float s = 0.f;
#pragma unroll
    for (int j = 0; j < 8; j++) { vv[j] = __expf(vv[j] - mx); s += vv[j]; }
#pragma unroll
    for (int o = 16; o; o >>= 1) s += __shfl_xor_sync(0xffffffffu, s, o);
    const float inv = 1.f / s;
#pragma unroll
    for (int j = 0; j < 8; j++) srow[wid][lane * 8 + j] = vv[j] * inv;
    __syncwarp();
#pragma unroll
    for (int t = 0; t < 4; t++) {
        const int m = lane * 4 + t;
        int d0 = 2 * m, d1 = 2 * m + 1;
        if (PERM) {
            d0 = ((d0 & 31) << 3) | (d0 >> 5);
            d1 = ((d1 & 31) << 3) | (d1 >> 5);
        }
        O[(long)row * 128 + m] = pack_hi(srow[wid][d0], srow[wid][d1]);
    }
}

// ---------------- launch ----------------------------------------------------
extern "C" void kernel_launch(void* const* d_in, const int* in_sizes, int n_in,
                              void* d_out, int out_size)
{
    const float* x    = (const float*)d_in[0];
    const float* sq_w = (const float*)d_in[3];
    const float* sq_b = (const float*)d_in[4];
    const float* sk_w = (const float*)d_in[5];
    const float* sk_b = (const float*)d_in[6];
    const float* sv_w = (const float*)d_in[7];
    const float* sv_b = (const float*)d_in[8];
    const float* tq_w = (const float*)d_in[9];
    const float* tq_b = (const float*)d_in[10];
    const float* tk_w = (const float*)d_in[11];
    const float* tk_b = (const float*)d_in[12];
    const float* tv_w = (const float*)d_in[13];
    const float* tv_b = (const float*)d_in[14];
    const float* s_gamma = (const float*)d_in[15];
    const float* t_gamma = (const float*)d_in[16];
    float* out = (float*)d_out;

    uint32_t *xh, *xth, *xtl, *xsh, *xsl, *x1th, *x1tl, *wh, *wl;
    uint32_t *vh, *attnB, *Gh, *Gl, *PTh, *PTl;
    float *attnP, *sx, *sx1, *us, *vs, *ut, *vt;
    cudaGetSymbolAddress((void**)&xh, g_xh);
    cudaGetSymbolAddress((void**)&xth, g_xth);   cudaGetSymbolAddress((void**)&xtl, g_xtl);
    cudaGetSymbolAddress((void**)&xsh, g_xsh);   cudaGetSymbolAddress((void**)&xsl, g_xsl);
    cudaGetSymbolAddress((void**)&x1th, g_x1th); cudaGetSymbolAddress((void**)&x1tl, g_x1tl);
    cudaGetSymbolAddress((void**)&wh, g_wh);     cudaGetSymbolAddress((void**)&wl, g_wl);
    cudaGetSymbolAddress((void**)&vh, g_vh);
    cudaGetSymbolAddress((void**)&attnP, g_attnP);
    cudaGetSymbolAddress((void**)&attnB, g_attnB);
    cudaGetSymbolAddress((void**)&Gh, g_Gh);     cudaGetSymbolAddress((void**)&Gl, g_Gl);
    cudaGetSymbolAddress((void**)&PTh, g_PTh);   cudaGetSymbolAddress((void**)&PTl, g_PTl);
    cudaGetSymbolAddress((void**)&sx, g_sx);     cudaGetSymbolAddress((void**)&sx1, g_sx1);
    cudaGetSymbolAddress((void**)&us, g_us);     cudaGetSymbolAddress((void**)&vs, g_vs);
    cudaGetSymbolAddress((void**)&ut, g_ut);     cudaGetSymbolAddress((void**)&vt, g_vt);

    auto convV = gemm<1, 1, 0, 0, false, false>;   // sv, tv (1-pass hi)
    auto bigG  = gemm<3, 2, 0, 2, false, true>;    // G (symmetric, split-K=4)
    auto bigH  = gemm<3, 2, 0, 2, false, false>;   // H (split-K=4) and S GEMMs
    auto Pk    = gemm<3, 2, 0, 4, false, false>;   // G/H * Wk^T -> P^T planes
    auto outV1 = gemm<1, 1, 0, 3, true, false>;    // spatial out (+x1^T planes)
    auto outV2 = gemm<1, 1, 2, 3, false, false>;   // temporal out (v2 gather)

    const int SMC = 3 * (128 + 128) * 20 * 4;      // 61440 (convV/outV2)
    const int SMG = 2 * (256 + 256) * 20 * 4;      // 81920 (bigG/H/S/Pk)
    const int SMO = 69632;                         // outV1 (epilogue staging)
    cudaFuncSetAttribute(convV, cudaFuncAttributeMaxDynamicSharedMemorySize, SMC);
    cudaFuncSetAttribute(bigG,  cudaFuncAttributeMaxDynamicSharedMemorySize, SMG);
    cudaFuncSetAttribute(bigH,  cudaFuncAttributeMaxDynamicSharedMemorySize, SMG);
    cudaFuncSetAttribute(Pk,    cudaFuncAttributeMaxDynamicSharedMemorySize, SMG);
    cudaFuncSetAttribute(outV1, cudaFuncAttributeMaxDynamicSharedMemorySize, SMO);
    cudaFuncSetAttribute(outV2, cudaFuncAttributeMaxDynamicSharedMemorySize, SMC);

    const dim3 px(32, 4, 16);
    const dim3 ts(64, 4, 16);
    const dim3 cg(512, 2, 1);
    const dim3 gg(2, 2, 64);
    const dim3 pg(2, 2, 16);
    const dim3 og(32, 2, 16);

    prep_x<<<px, 256>>>(x);
    transpose_xs<<<ts, 256>>>(x);
    prep_w<<<768, 256>>>(sq_w, sk_w, sv_w, tq_w, tk_w, tv_w);
    rowsum<<<512, 256>>>(xth, xtl, sx);
    matvec3<<<dim3(16, 3), 256>>>(sk_w, sq_w, tk_w, sx, us, vs, ut);

    // ---- spatial ----
    convV<<<cg, 256, SMC>>>(xh, nullptr, 128, 0, wh + 2 * 32768, nullptr, 128, 0, 128,
                            sv_b, nullptr, nullptr, 0, nullptr, vh, nullptr);
    bigG<<<gg, 256, SMG>>>(xth, xtl, 2048, 524288L, xth, xtl, 2048, 524288L, 512,
                           nullptr, nullptr, nullptr, 0, attnP, nullptr, nullptr);
    combine_pack<true><<<2048, 256>>>(attnP, Gh, Gl);
    Pk<<<pg, 256, SMG>>>(Gh, Gl, 128, 32768L, wh + 1 * 32768, wl + 1 * 32768, 128, 0, 128,
                         nullptr, nullptr, nullptr, 0, nullptr, PTh, PTl);
    bigH<<<pg, 256, SMG>>>(wh + 0 * 32768, wl + 0 * 32768, 128, 0, PTh, PTl, 128, 32768L, 128,
                           nullptr, nullptr, nullptr, 0, attnP, nullptr, nullptr);
    softmax_rank1<false><<<512, 256>>>(attnP, us, vs, sq_b, sk_b, attnB);
    outV1<<<og, 256, SMO>>>(vh, nullptr, 128, 524288L, attnB, nullptr, 128, 32768L, 128,
                            nullptr, s_gamma, x, 259, out, x1th, x1tl);

    // ---- temporal ----
    rowsum<<<512, 256>>>(x1th, x1tl, sx1);
    matvec<<<16, 256>>>(tq_w, sx1, vt);
    convV<<<cg, 256, SMC>>>(xh, nullptr, 128, 0, wh + 5 * 32768, nullptr, 128, 0, 128,
                            tv_b, nullptr, nullptr, 0, nullptr, vh, nullptr);
    bigH<<<gg, 256, SMG>>>(x1th, x1tl, 2048, 524288L, xsh, xsl, 2048, 524288L, 512,
                           nullptr, nullptr, nullptr, 0, attnP, nullptr, nullptr);
    combine_pack<false><<<2048, 256>>>(attnP, Gh, Gl);
    Pk<<<pg, 256, SMG>>>(Gh, Gl, 128, 32768L, wh + 4 * 32768, wl + 4 * 32768, 128, 0, 128,
                         nullptr, nullptr, nullptr, 0, nullptr, PTh, PTl);
    bigH<<<pg, 256, SMG>>>(wh + 3 * 32768, wl + 3 * 32768, 128, 0, PTh, PTl, 128, 32768L, 128,
                           nullptr, nullptr, nullptr, 0, attnP, nullptr, nullptr);
    softmax_rank1<true><<<512, 256>>>(attnP, ut, vt, tq_b, tk_b, attnB);
    outV2<<<og, 256, SMC>>>(vh, nullptr, 128, 0, attnB, nullptr, 128, 32768L, 128,
                            nullptr, t_gamma, out, 256, out, nullptr, nullptr);
}

// round 14
// speedup vs baseline: 2.9053x; 1.0851x over previous
#include <cuda_runtime.h>
#include <cuda_bf16.h>
#include <cstdint>

// ===========================================================================
// LossRecovery, Gram formulation + spatial v-conv folded into attention.
//   E  = Wq G Wk^T + rank-1 bias terms,  G = X^T X (symmetric)
//   E2 = Wq' H Wk'^T + ...,              H = X1^T Xsigma
//   out1 = X * (attn*Wv)^T + attn*bv  (spatial conv folded into M1)
// q/k/score path: 3-pass bf16 split. v/out paths: 1-pass bf16-hi.
// Rowsums folded into prep_x / outV1 epilogues (exact, deterministic).
// ===========================================================================

__device__ uint32_t g_xh[65536L * 128];                               // x hi, s-major
__device__ uint32_t g_xth[16L * 256 * 2048], g_xtl[16L * 256 * 2048]; // x^T planes
__device__ uint32_t g_xsh[16L * 256 * 2048], g_xsl[16L * 256 * 2048]; // x^T sigma-perm
__device__ uint32_t g_x1th[16L * 256 * 2048], g_x1tl[16L * 256 * 2048];
__device__ uint32_t g_wh[6 * 32768], g_wl[6 * 32768];
__device__ uint32_t g_wvth[32768];                                    // sv_w^T hi
__device__ uint32_t g_vh[16L * 4096 * 128];
__device__ uint32_t g_M1h[16L * 256 * 128];
__device__ float    g_attnP[64L * 65536];
__device__ uint32_t g_attnB[16L * 256 * 128];
__device__ uint32_t g_Gh[16L * 256 * 128], g_Gl[16L * 256 * 128];
__device__ uint32_t g_PTh[16L * 256 * 128], g_PTl[16L * 256 * 128];
__device__ float    g_sxP[32 * 4096], g_sx1P[32 * 4096];
__device__ float    g_sx[4096], g_sx1[4096], g_mb[4096];
__device__ float    g_us[4096], g_vs[4096], g_ut[4096], g_vt[4096];

#define CP16(dst, src) asm volatile("cp.async.cg.shared.global [%0], [%1], 16;\n" :: "r"(dst), "l"(src))
#define CPCOMMIT()     asm volatile("cp.async.commit_group;\n" ::: "memory")
#define CPWAIT(n)      asm volatile("cp.async.wait_group %0;\n" :: "n"(n) : "memory")

#define LDSM4(d0, d1, d2, d3, a) \
    asm volatile("ldmatrix.sync.aligned.m8n8.x4.shared.b16 {%0,%1,%2,%3}, [%4];" \
        : "=r"(d0), "=r"(d1), "=r"(d2), "=r"(d3) : "r"(a))

__device__ __forceinline__ uint32_t pack_hi(float v0, float v1) {
    uint32_t h;
    asm("cvt.rn.bf16x2.f32 %0, %1, %2;" : "=r"(h) : "f"(v1), "f"(v0));
    return h;  // lo half = v0
}
__device__ __forceinline__ void pack_pair(float v0, float v1, uint32_t& h, uint32_t& l) {
    h = pack_hi(v0, v1);
    const float h0 = __uint_as_float(h << 16);
    const float h1 = __uint_as_float(h & 0xFFFF0000u);
    l = pack_hi(v0 - h0, v1 - h1);
}

#define MMA_BF16(ac, a0, a1, a2, a3, b0, b1) \
    asm volatile("mma.sync.aligned.m16n8k16.row.col.f32.bf16.bf16.f32 " \
        "{%0,%1,%2,%3},{%4,%5,%6,%7},{%8,%9},{%0,%1,%2,%3};" \
        : "+f"((ac)[0]), "+f"((ac)[1]), "+f"((ac)[2]), "+f"((ac)[3]) \
        : "r"(a0), "r"(a1), "r"(a2), "r"(a3), "r"(b0), "r"(b1))

// ---------------------------------------------------------------------------
// NT GEMM over packed-bf16 planes. NPASS: 1 = AhBh; 3 = +AhBl+AlBh.
//  AMODE 0 plain | 2 v2-gather.
//  EMODE 0 hi-plane+bias | 2 fp32 scores | 3 gamma*(acc+bias?)+res
//        | 4 transposed planes | 5 z-batched hi plane.
//  DUAL (EMODE3): also write x1^T planes + column-sum partials.
//  SYMM: skip block (1,0).
template <int NPASS, int BPL, int AMODE, int EMODE, bool DUAL, bool SYMM>
__global__ __launch_bounds__(256, 2) void gemm(
    const uint32_t* __restrict__ aH, const uint32_t* __restrict__ aL, int aW, long aZ,
    const uint32_t* __restrict__ bH, const uint32_t* __restrict__ bL, int bW, long bZ,
    int KdimW,
    const float* __restrict__ bias, const float* __restrict__ gammaPtr,
    const float* __restrict__ res, int ldr,
    float* __restrict__ outF, uint32_t* __restrict__ outH, uint32_t* __restrict__ outL)
{
    if (SYMM && blockIdx.x == 1 && blockIdx.y == 0) return;

    extern __shared__ uint32_t sm[];
    constexpr int ALD = 20;
    constexpr int APL = (NPASS >= 2) ? 2 : 1;
    constexpr int STAGEW = (APL * 128 + BPL * 128) * ALD;
    constexpr int NSTAGE = (STAGEW > 8192) ? 2 : 3;
    const uint32_t sbB = (uint32_t)__cvta_generic_to_shared(sm);

    const int tid = threadIdx.x;
    const int wid = tid >> 5, lane = tid & 31;
    const int grp = lane >> 2, tig = lane & 3;
    const int row0 = blockIdx.x * 128, col0 = blockIdx.y * 128;
    const int z = blockIdx.z;
    int zA = z;
    long koffW = 0;
    if (EMODE == 2) { zA = z & 15; koffW = (long)(z >> 4) * KdimW; }

    constexpr int MI = 4;
    const int m_base = (wid >> 2) * 64;
    const int n_base = (wid & 3) * 32;

    float acc[MI][4][4];
#pragma unroll
    for (int mi = 0; mi < MI; mi++)
#pragma unroll
        for (int ni = 0; ni < 4; ni++)
#pragma unroll
            for (int e = 0; e < 4; e++) acc[mi][ni][e] = 0.f;

    const int ar = tid >> 1, hw = (tid & 1) * 8;
    long arow;
    long astep = 16;
    if (AMODE == 0) {
        arow = (long)zA * aZ + (long)(row0 + ar) * aW + koffW + hw;
    } else {  // v2 gather
        const int bq = z >> 3, chHi = z & 7;
        arow = ((long)(bq * 8) * 4096 + (row0 + ar)) * 128 + chHi * 16 + hw;
        astep = 4096L * 128;
    }
    const int bn = tid >> 1, hwB = (tid & 1) * 8;
    const long brow = (long)zA * bZ + (long)(col0 + bn) * bW + koffW + hwB;

    const int nCh = KdimW >> 4;
    const uint32_t ALo = 128 * ALD;
    const uint32_t BHo = APL * 128 * ALD;
    const uint32_t BLo = BHo + 128 * ALD;

    auto load_tile = [&](int kc, int s) {
        const long ka = arow + (long)kc * astep;
        const long kb = brow + (long)kc * 16;
        const uint32_t aD = sbB + (uint32_t)(s * STAGEW + ar * ALD + hw) * 4u;
        CP16(aD, aH + ka); CP16(aD + 16u, aH + ka + 4);
        if (APL == 2) {
            const uint32_t aD2 = aD + ALo * 4u;
            CP16(aD2, aL + ka); CP16(aD2 + 16u, aL + ka + 4);
        }
        const uint32_t bD = sbB + (uint32_t)(s * STAGEW + BHo + bn * ALD + hwB) * 4u;
        CP16(bD, bH + kb); CP16(bD + 16u, bH + kb + 4);
        if (BPL == 2) {
            const uint32_t bD2 = sbB + (uint32_t)(s * STAGEW + BLo + bn * ALD + hwB) * 4u;
            CP16(bD2, bL + kb); CP16(bD2 + 16u, bL + kb + 4);
        }
    };

    const int la7 = lane & 7, lg = lane >> 3;
    const uint32_t aoff = (uint32_t)(((m_base + la7 + ((lg & 1) << 3)) * ALD
                                      + ((lg >> 1) << 2)) * 4);
    const uint32_t boff = (uint32_t)(((n_base + la7 + ((lg >> 1) << 3)) * ALD
                                      + ((lg & 1) << 2)) * 4);

    auto compute = [&](int s) {
        const uint32_t stB = sbB + (uint32_t)(s * STAGEW) * 4u;
#pragma unroll
        for (int ks = 0; ks < 2; ks++) {
            const uint32_t kby = (uint32_t)(ks * 32);
            uint32_t bh[4][2], bl[4][2];
#pragma unroll
            for (int p = 0; p < 2; p++) {
                const uint32_t ba = stB + BHo * 4u + boff + (uint32_t)(p * 16 * ALD * 4) + kby;
                LDSM4(bh[2 * p][0], bh[2 * p][1], bh[2 * p + 1][0], bh[2 * p + 1][1], ba);
                if (BPL == 2) {
                    const uint32_t ba2 = stB + BLo * 4u + boff + (uint32_t)(p * 16 * ALD * 4) + kby;
                    LDSM4(bl[2 * p][0], bl[2 * p][1], bl[2 * p + 1][0], bl[2 * p + 1][1], ba2);
                }
            }
#pragma unroll
            for (int mi = 0; mi < MI; mi++) {
                const uint32_t aa = stB + aoff + (uint32_t)(mi * 16 * ALD * 4) + kby;
                uint32_t ah0, ah1, ah2, ah3;
                LDSM4(ah0, ah1, ah2, ah3, aa);
#pragma unroll
                for (int ni = 0; ni < 4; ni++)
                    MMA_BF16(acc[mi][ni], ah0, ah1, ah2, ah3, bh[ni][0], bh[ni][1]);
                if (NPASS == 3) {
#pragma unroll
                    for (int ni = 0; ni < 4; ni++)
                        MMA_BF16(acc[mi][ni], ah0, ah1, ah2, ah3, bl[ni][0], bl[ni][1]);
                }
                if (NPASS >= 2) {
                    uint32_t al0, al1, al2, al3;
                    LDSM4(al0, al1, al2, al3, aa + ALo * 4u);
#pragma unroll
                    for (int ni = 0; ni < 4; ni++)
                        MMA_BF16(acc[mi][ni], al0, al1, al2, al3, bh[ni][0], bh[ni][1]);
                }
            }
        }
    };

    load_tile(0, 0); CPCOMMIT();
    if (nCh > 1) load_tile(1, 1);
    CPCOMMIT();
    if (NSTAGE == 2) {
        for (int kc = 0; kc < nCh; kc++) {
            CPWAIT(1);
            __syncthreads();
            compute(kc & 1);
            __syncthreads();
            if (kc + 2 < nCh) { load_tile(kc + 2, kc & 1); CPCOMMIT(); }
        }
    } else {
        for (int kc = 0; kc < nCh; kc++) {
            CPWAIT(1);
            __syncthreads();
            const int ld = kc + 2;
            if (ld < nCh) load_tile(ld, ld % 3);
            CPCOMMIT();
            compute(kc % 3);
        }
    }

    // ---- epilogues ----
    if (EMODE == 4) {
        __syncthreads();
        float* sC = (float*)sm;
#pragma unroll
        for (int mi = 0; mi < MI; mi++)
#pragma unroll
            for (int ni = 0; ni < 4; ni++) {
                const int r0 = m_base + mi * 16 + grp;
                const int cb = n_base + ni * 8 + 2 * tig;
                sC[r0 * 133 + cb] = acc[mi][ni][0];
                sC[r0 * 133 + cb + 1] = acc[mi][ni][1];
                sC[(r0 + 8) * 133 + cb] = acc[mi][ni][2];
                sC[(r0 + 8) * 133 + cb + 1] = acc[mi][ni][3];
            }
        __syncthreads();
        const int p = tid & 63, colg = tid >> 6;
        for (int cp = 0; cp < 32; cp++) {
            const int col = cp * 4 + colg;
            uint32_t h, l;
            pack_pair(sC[(2 * p) * 133 + col], sC[(2 * p + 1) * 133 + col], h, l);
            const long w = ((long)(z * 256 + col0 + col)) * 128 + (row0 >> 1) + p;
            outH[w] = h; outL[w] = l;
        }
    } else if (EMODE == 3 && DUAL) {
        const float gamma = __ldg(gammaPtr);
        __syncthreads();
        float* sC = (float*)sm;
#pragma unroll
        for (int mi = 0; mi < MI; mi++)
#pragma unroll
            for (int ni = 0; ni < 4; ni++) {
                const int r0g = m_base + mi * 16 + grp;
                const int cb = n_base + ni * 8 + 2 * tig;
                const int c = col0 + cb;
#pragma unroll
                for (int half = 0; half < 2; half++) {
                    const int rl = r0g + half * 8;
                    const long rr = (long)z * 4096 + row0 + rl;
                    float a0 = acc[mi][ni][2 * half];
                    float a1 = acc[mi][ni][2 * half + 1];
                    if (bias) {
                        a0 += __ldg(&bias[z * 256 + c]);
                        a1 += __ldg(&bias[z * 256 + c + 1]);
                    }
                    float v0 = gamma * a0 + res[rr * (long)ldr + c];
                    float v1 = gamma * a1 + res[rr * (long)ldr + c + 1];
                    float2 st = {v0, v1};
                    *(float2*)(outF + rr * 256 + c) = st;
                    sC[rl * 133 + cb] = v0;
                    sC[rl * 133 + cb + 1] = v1;
                }
            }
        __syncthreads();
        const int p = tid & 63, colg = tid >> 6;
        for (int cp = 0; cp < 32; cp++) {
            const int col = cp * 4 + colg;
            uint32_t h, l;
            pack_pair(sC[(2 * p) * 133 + col], sC[(2 * p + 1) * 133 + col], h, l);
            const long w = ((long)(z * 256 + col0 + col)) * 2048 + (row0 >> 1) + p;
            outH[w] = h; outL[w] = l;
        }
        // column-sum partials of x1 tile -> g_sx1P[st][z*256+col0+col]
        {
            float* part = sC + 128 * 133;      // 256 floats scratch
            const int col = tid & 127, hf = tid >> 7;
            float s = 0.f;
#pragma unroll 4
            for (int r = hf * 64; r < hf * 64 + 64; r++) s += sC[r * 133 + col];
            part[hf * 128 + col] = s;
            __syncthreads();
            if (tid < 128)
                g_sx1P[(long)blockIdx.x * 4096 + z * 256 + col0 + tid]
                    = part[tid] + part[128 + tid];
        }
    } else {
        float gamma = 0.f;
        if (EMODE == 3) gamma = __ldg(gammaPtr);
#pragma unroll
        for (int mi = 0; mi < MI; mi++)
#pragma unroll
            for (int ni = 0; ni < 4; ni++) {
                const int r0g = m_base + mi * 16 + grp;
                const int cb = n_base + ni * 8 + 2 * tig;
                const int c = col0 + cb;
#pragma unroll
                for (int half = 0; half < 2; half++) {
                    const int r = row0 + r0g + half * 8;
                    float v0 = acc[mi][ni][2 * half];
                    float v1 = acc[mi][ni][2 * half + 1];
                    if (EMODE == 0) {
                        v0 += __ldg(&bias[c]);
                        v1 += __ldg(&bias[c + 1]);
                        outH[(long)r * 128 + (c >> 1)] = pack_hi(v0, v1);
                    } else if (EMODE == 5) {
                        outH[((long)z * 256 + r) * 128 + (c >> 1)] = pack_hi(v0, v1);
                    } else if (EMODE == 2) {
                        float2 st = {v0, v1};
                        *(float2*)(outF + (long)z * 65536 + (long)r * 256 + c) = st;
                    } else {
                        const long rr = (long)z * 4096 + r;
                        if (bias) {
                            v0 += __ldg(&bias[z * 256 + c]);
                            v1 += __ldg(&bias[z * 256 + c + 1]);
                        }
                        v0 = gamma * v0 + res[rr * (long)ldr + c];
                        v1 = gamma * v1 + res[rr * (long)ldr + c + 1];
                        float2 st = {v0, v1};
                        *(float2*)(outF + rr * 256 + c) = st;
                    }
                }
            }
    }
}

// ---------------- fused: x -> xh + xth/xtl planes + rowsum partials --------
__global__ __launch_bounds__(256) void prep_x(const float* __restrict__ x) {
    __shared__ float tile[128][65];
    __shared__ float colp[4][64];
    const int st = blockIdx.x, ct = blockIdx.y, z = blockIdx.z;
    const int t = threadIdx.x;
    const int col = t & 63, r4 = t >> 6;
    const long base = ((long)z * 4096 + st * 128) * 259 + ct * 64;
#pragma unroll
    for (int j = 0; j < 32; j++) {
        const int row = r4 + j * 4;
        tile[row][col] = x[base + (long)row * 259 + col];
    }
    __syncthreads();
#pragma unroll
    for (int k = 0; k < 16; k++) {
        const int idx = t + k * 256;
        const int row = idx >> 5, jw = idx & 31;
        g_xh[((long)z * 4096 + st * 128 + row) * 128 + ct * 32 + jw]
            = pack_hi(tile[row][2 * jw], tile[row][2 * jw + 1]);
    }
#pragma unroll
    for (int k = 0; k < 16; k++) {
        const int idx = t + k * 256;
        const int c = idx >> 6, p = idx & 63;
        uint32_t h, l;
        pack_pair(tile[2 * p][c], tile[2 * p + 1][c], h, l);
        const long w = ((long)z * 256 + ct * 64 + c) * 2048 + st * 64 + p;
        g_xth[w] = h; g_xtl[w] = l;
    }
    // rowsum partials over this block's 128 s-rows
    {
        float s = 0.f;
#pragma unroll 4
        for (int r = r4 * 32; r < r4 * 32 + 32; r++) s += tile[r][col];
        colp[r4][col] = s;
        __syncthreads();
        if (t < 64)
            g_sxP[(long)st * 4096 + z * 256 + ct * 64 + t]
                = colp[0][t] + colp[1][t] + colp[2][t] + colp[3][t];
    }
}

// ---------------- sigma-permuted x^T planes ---------------------------------
__global__ __launch_bounds__(256) void transpose_xs(const float* __restrict__ x) {
    __shared__ float tile[64][65];
    const int st = blockIdx.x, ct = blockIdx.y, z = blockIdx.z;
    const int t = threadIdx.x;
#pragma unroll
    for (int j = 0; j < 16; j++) {
        const int i = (t >> 6) + j * 4;
        const int col = t & 63;
        tile[i][col] = x[((long)(z * 4096 + i * 64 + st)) * 259 + ct * 64 + col];
    }
    __syncthreads();
#pragma unroll
    for (int j = 0; j < 8; j++) {
        const int cl = (t >> 5) + j * 8;
        const int wi = t & 31;
        uint32_t h, l;
        pack_pair(tile[2 * wi][cl], tile[2 * wi + 1][cl], h, l);
        const long w = ((long)(z * 256 + ct * 64 + cl)) * 2048 + st * 32 + wi;
        g_xsh[w] = h; g_xsl[w] = l;
    }
}

// ---------------- weights -> planes (+ sv^T hi plane) -----------------------
__global__ __launch_bounds__(256) void prep_w(const float* w0, const float* w1,
                                              const float* w2, const float* w3,
                                              const float* w4, const float* w5) {
    const int id = blockIdx.x * 256 + threadIdx.x;
    if (id < 6 * 32768) {
        const int m = id >> 15, rc = id & 32767;
        const float* w = (m == 0) ? w0 : (m == 1) ? w1 : (m == 2) ? w2
                       : (m == 3) ? w3 : (m == 4) ? w4 : w5;
        uint32_t h, l;
        pack_pair(w[rc * 2], w[rc * 2 + 1], h, l);
        g_wh[id] = h; g_wl[id] = l;
    } else {
        const int id2 = id - 6 * 32768;   // sv^T: [e][d-words]
        const int e = id2 >> 7, dw = id2 & 127;
        g_wvth[id2] = pack_hi(w2[(2 * dw) * 256 + e], w2[(2 * dw + 1) * 256 + e]);
    }
}

// ---------------- reduce 32 partials -> 4096 ---------------------------------
__global__ __launch_bounds__(256) void reduce32(const float* __restrict__ P,
                                                float* __restrict__ o) {
    const int i = blockIdx.x * 256 + threadIdx.x;
    float s = 0.f;
#pragma unroll 8
    for (int j = 0; j < 32; j++) s += P[(long)j * 4096 + i];
    o[i] = s;
}

// ---------------- matvecs ----------------------------------------------------
__global__ __launch_bounds__(256) void matvec3(const float* Wa, const float* Wb,
                                               const float* Wc, const float* sig,
                                               float* oa, float* ob, float* oc) {
    const int z = blockIdx.x, d = threadIdx.x, m = blockIdx.y;
    const float* W = (m == 0) ? Wa : (m == 1) ? Wb : Wc;
    float* o = (m == 0) ? oa : (m == 1) ? ob : oc;
    const float* w = W + (long)d * 256;
    const float* g = sig + z * 256;
    float s = 0.f;
    for (int c = 0; c < 256; c++) s += w[c] * g[c];
    o[z * 256 + d] = s;
}
__global__ __launch_bounds__(256) void matvec(const float* __restrict__ W,
                                              const float* __restrict__ sig,
                                              float* __restrict__ o) {
    const int z = blockIdx.x, d = threadIdx.x;
    const float* w = W + (long)d * 256;
    const float* g = sig + z * 256;
    float s = 0.f;
    for (int c = 0; c < 256; c++) s += w[c] * g[c];
    o[z * 256 + d] = s;
}

// ---------------- mbias: mb[z,c] = attn_row(c) . bv --------------------------
__global__ __launch_bounds__(256) void mbias_k(const uint32_t* __restrict__ attn,
                                               const float* __restrict__ bv,
                                               float* __restrict__ mb) {
    const int row = blockIdx.x * 8 + (threadIdx.x >> 5);
    const int lane = threadIdx.x & 31;
    const uint32_t* a = attn + (long)row * 128;
    float s = 0.f;
#pragma unroll 4
    for (int w = lane; w < 128; w += 32) {
        const uint32_t u = a[w];
        s += __uint_as_float(u << 16) * bv[2 * w]
           + __uint_as_float(u & 0xFFFF0000u) * bv[2 * w + 1];
    }
#pragma unroll
    for (int o = 16; o; o >>= 1) s += __shfl_xor_sync(0xffffffffu, s, o);
    if (lane == 0) mb[row] = s;
}

// ---------------- sum 4 split-K partials -> packed planes (opt. mirror) ----
template <bool MIRROR>
__global__ __launch_bounds__(256) void combine_pack(const float* __restrict__ P,
                                                    uint32_t* __restrict__ gh,
                                                    uint32_t* __restrict__ gl) {
    const long i = (long)blockIdx.x * 256 + threadIdx.x;
    const int z = (int)(i >> 15);
    const int r = (int)(i & 32767);
    const int c = r >> 7, dw = r & 127;
    float v0, v1;
    if (MIRROR && c >= 128 && dw < 64) {
        const long e0 = (long)z * 65536 + (2 * dw) * 256 + c;
        const long e1 = e0 + 256;
        v0 = P[e0] + P[e0 + 1048576] + P[e0 + 2097152] + P[e0 + 3145728];
        v1 = P[e1] + P[e1 + 1048576] + P[e1 + 2097152] + P[e1 + 3145728];
    } else {
        const long e = (long)z * 65536 + c * 256 + 2 * dw;
        v0 = P[e] + P[e + 1048576] + P[e + 2097152] + P[e + 3145728];
        v1 = P[e + 1] + P[e + 1 + 1048576] + P[e + 1 + 2097152] + P[e + 1 + 3145728];
    }
    uint32_t h, l;
    pack_pair(v0, v1, h, l);
    gh[i] = h; gl[i] = l;
}

// ---------------- softmax with rank-1 bias terms, pack (opt. permuted) -----
template <bool PERM>
__global__ __launch_bounds__(256) void softmax_rank1(
    const float* __restrict__ S, const float* __restrict__ u,
    const float* __restrict__ vvec, const float* __restrict__ bq,
    const float* __restrict__ bk, uint32_t* __restrict__ O)
{
    __shared__ float srow[8][256];
    const int wid = threadIdx.x >> 5, lane = threadIdx.x & 31;
    const int row = blockIdx.x * 8 + wid;
    const int z = row >> 8, c = row & 255;
    const float bqc = bq[c], vc = vvec[z * 256 + c];
    const float* p = S + (long)row * 256;
    float vv[8];
    float mx = -1e30f;
#pragma unroll
    for (int j = 0; j < 8; j++) {
        const int d = lane * 8 + j;
        const float bkd = bk[d];
        vv[j] = p[d] + bqc * (u[z * 256 + d] + 4096.f * bkd) + bkd * vc;
        mx = fmaxf(mx, vv[j]);
    }
#pragma unroll
    for (int o = 16; o; o >>= 1) mx = fmaxf(mx, __shfl_xor_sync(0xffffffffu, mx, o));
    float s = 0.f;
#pragma unroll
    for (int j = 0; j < 8; j++) { vv[j] = __expf(vv[j] - mx); s += vv[j]; }
#pragma unroll
    for (int o = 16; o; o >>= 1) s += __shfl_xor_sync(0xffffffffu, s, o);
    const float inv = 1.f / s;
#pragma unroll
    for (int j = 0; j < 8; j++) srow[wid][lane * 8 + j] = vv[j] * inv;
    __syncwarp();
#pragma unroll
    for (int t = 0; t < 4; t++) {
        const int m = lane * 4 + t;
        int d0 = 2 * m, d1 = 2 * m + 1;
        if (PERM) {
            d0 = ((d0 & 31) << 3) | (d0 >> 5);
            d1 = ((d1 & 31) << 3) | (d1 >> 5);
        }
        O[(long)row * 128 + m] = pack_hi(srow[wid][d0], srow[wid][d1]);
    }
}

// ---------------- launch ----------------------------------------------------
extern "C" void kernel_launch(void* const* d_in, const int* in_sizes, int n_in,
                              void* d_out, int out_size)
{
    const float* x    = (const float*)d_in[0];
    const float* sq_w = (const float*)d_in[3];
    const float* sq_b = (const float*)d_in[4];
    const float* sk_w = (const float*)d_in[5];
    const float* sk_b = (const float*)d_in[6];
    const float* sv_w = (const float*)d_in[7];
    const float* sv_b = (const float*)d_in[8];
    const float* tq_w = (const float*)d_in[9];
    const float* tq_b = (const float*)d_in[10];
    const float* tk_w = (const float*)d_in[11];
    const float* tk_b = (const float*)d_in[12];
    const float* tv_w = (const float*)d_in[13];
    const float* tv_b = (const float*)d_in[14];
    const float* s_gamma = (const float*)d_in[15];
    const float* t_gamma = (const float*)d_in[16];
    float* out = (float*)d_out;

    uint32_t *xh, *xth, *xtl, *xsh, *xsl, *x1th, *x1tl, *wh, *wl, *wvth;
    uint32_t *vh, *M1h, *attnB, *Gh, *Gl, *PTh, *PTl;
    float *attnP, *sxP, *sx1P, *sx, *sx1, *mb, *us, *vs, *ut, *vt;
    cudaGetSymbolAddress((void**)&xh, g_xh);
    cudaGetSymbolAddress((void**)&xth, g_xth);   cudaGetSymbolAddress((void**)&xtl, g_xtl);
    cudaGetSymbolAddress((void**)&xsh, g_xsh);   cudaGetSymbolAddress((void**)&xsl, g_xsl);
    cudaGetSymbolAddress((void**)&x1th, g_x1th); cudaGetSymbolAddress((void**)&x1tl, g_x1tl);
    cudaGetSymbolAddress((void**)&wh, g_wh);     cudaGetSymbolAddress((void**)&wl, g_wl);
    cudaGetSymbolAddress((void**)&wvth, g_wvth);
    cudaGetSymbolAddress((void**)&vh, g_vh);     cudaGetSymbolAddress((void**)&M1h, g_M1h);
    cudaGetSymbolAddress((void**)&attnP, g_attnP);
    cudaGetSymbolAddress((void**)&attnB, g_attnB);
    cudaGetSymbolAddress((void**)&Gh, g_Gh);     cudaGetSymbolAddress((void**)&Gl, g_Gl);
    cudaGetSymbolAddress((void**)&PTh, g_PTh);   cudaGetSymbolAddress((void**)&PTl, g_PTl);
    cudaGetSymbolAddress((void**)&sxP, g_sxP);   cudaGetSymbolAddress((void**)&sx1P, g_sx1P);
    cudaGetSymbolAddress((void**)&sx, g_sx);     cudaGetSymbolAddress((void**)&sx1, g_sx1);
    cudaGetSymbolAddress((void**)&mb, g_mb);
    cudaGetSymbolAddress((void**)&us, g_us);     cudaGetSymbolAddress((void**)&vs, g_vs);
    cudaGetSymbolAddress((void**)&ut, g_ut);     cudaGetSymbolAddress((void**)&vt, g_vt);

    auto convV = gemm<1, 1, 0, 0, false, false>;   // tv conv (1-pass hi)
    auto bigG  = gemm<3, 2, 0, 2, false, true>;    // G (symmetric, split-K=4)
    auto bigH  = gemm<3, 2, 0, 2, false, false>;   // H (split-K=4) and S GEMMs
    auto Pk    = gemm<3, 2, 0, 4, false, false>;   // G/H * Wk^T -> P^T planes
    auto m1k   = gemm<1, 1, 0, 5, false, false>;   // M1 = attn * Wv^T
    auto outV1 = gemm<1, 1, 0, 3, true, false>;    // spatial out (X*M1^T, +x1 planes)
    auto outV2 = gemm<1, 1, 2, 3, false, false>;   // temporal out (v2 gather)

    const int SMC = 3 * (128 + 128) * 20 * 4;      // 61440
    const int SMG = 2 * (256 + 256) * 20 * 4;      // 81920
    const int SMO = 70656;                         // outV1 (sC + partials)
    cudaFuncSetAttribute(convV, cudaFuncAttributeMaxDynamicSharedMemorySize, SMC);
    cudaFuncSetAttribute(bigG,  cudaFuncAttributeMaxDynamicSharedMemorySize, SMG);
    cudaFuncSetAttribute(bigH,  cudaFuncAttributeMaxDynamicSharedMemorySize, SMG);
    cudaFuncSetAttribute(Pk,    cudaFuncAttributeMaxDynamicSharedMemorySize, SMG);
    cudaFuncSetAttribute(m1k,   cudaFuncAttributeMaxDynamicSharedMemorySize, SMC);
    cudaFuncSetAttribute(outV1, cudaFuncAttributeMaxDynamicSharedMemorySize, SMO);
    cudaFuncSetAttribute(outV2, cudaFuncAttributeMaxDynamicSharedMemorySize, SMC);

    const dim3 px(32, 4, 16);
    const dim3 ts(64, 4, 16);
    const dim3 cg(512, 2, 1);
    const dim3 gg(2, 2, 64);
    const dim3 pg(2, 2, 16);
    const dim3 og(32, 2, 16);

    prep_x<<<px, 256>>>(x);
    transpose_xs<<<ts, 256>>>(x);
    prep_w<<<896, 256>>>(sq_w, sk_w, sv_w, tq_w, tk_w, tv_w);
    reduce32<<<16, 256>>>(sxP, sx);
    matvec3<<<dim3(16, 3), 256>>>(sk_w, sq_w, tk_w, sx, us, vs, ut);
    convV<<<cg, 256, SMC>>>(xh, nullptr, 128, 0, wh + 5 * 32768, nullptr, 128, 0, 128,
                            tv_b, nullptr, nullptr, 0, nullptr, vh, nullptr);

    // ---- spatial ----
    bigG<<<gg, 256, SMG>>>(xth, xtl, 2048, 524288L, xth, xtl, 2048, 524288L, 512,
                           nullptr, nullptr, nullptr, 0, attnP, nullptr, nullptr);
    combine_pack<true><<<2048, 256>>>(attnP, Gh, Gl);
    Pk<<<pg, 256, SMG>>>(Gh, Gl, 128, 32768L, wh + 1 * 32768, wl + 1 * 32768, 128, 0, 128,
                         nullptr, nullptr, nullptr, 0, nullptr, PTh, PTl);
    bigH<<<pg, 256, SMG>>>(wh + 0 * 32768, wl + 0 * 32768, 128, 0, PTh, PTl, 128, 32768L, 128,
                           nullptr, nullptr, nullptr, 0, attnP, nullptr, nullptr);
    softmax_rank1<false><<<512, 256>>>(attnP, us, vs, sq_b, sk_b, attnB);
    m1k<<<pg, 256, SMC>>>(attnB, nullptr, 128, 32768L, wvth, nullptr, 128, 0, 128,
                          nullptr, nullptr, nullptr, 0, nullptr, M1h, nullptr);
    mbias_k<<<512, 256>>>(attnB, sv_b, mb);
    outV1<<<og, 256, SMO>>>(xh, nullptr, 128, 524288L, M1h, nullptr, 128, 32768L, 128,
                            mb, s_gamma, x, 259, out, x1th, x1tl);

    // ---- temporal ----
    reduce32<<<16, 256>>>(sx1P, sx1);
    matvec<<<16, 256>>>(tq_w, sx1, vt);
    bigH<<<gg, 256, SMG>>>(x1th, x1tl, 2048, 524288L, xsh, xsl, 2048, 524288L, 512,
                           nullptr, nullptr, nullptr, 0, attnP, nullptr, nullptr);
    combine_pack<false><<<2048, 256>>>(attnP, Gh, Gl);
    Pk<<<pg, 256, SMG>>>(Gh, Gl, 128, 32768L, wh + 4 * 32768, wl + 4 * 32768, 128, 0, 128,
                         nullptr, nullptr, nullptr, 0, nullptr, PTh, PTl);
    bigH<<<pg, 256, SMG>>>(wh + 3 * 32768, wl + 3 * 32768, 128, 0, PTh, PTl, 128, 32768L, 128,
                           nullptr, nullptr, nullptr, 0, attnP, nullptr, nullptr);
    softmax_rank1<true><<<512, 256>>>(attnP, ut, vt, tq_b, tk_b, attnB);
    outV2<<<og, 256, SMC>>>(vh, nullptr, 128, 0, attnB, nullptr, 128, 32768L, 128,
                            nullptr, t_gamma, out, 256, out, nullptr, nullptr);
}

// round 15
// speedup vs baseline: 3.1135x; 1.0717x over previous
#include <cuda_runtime.h>
#include <cuda_bf16.h>
#include <cstdint>

// ===========================================================================
// LossRecovery, Gram formulation + v-conv fold + stream-fork overlap.
//   E  = Wq G Wk^T + rank-1 bias terms,  G = X^T X (symmetric)
//   E2 = Wq' H Wk'^T + ...,              H = X1^T Xsigma
//   out1 = X * (attn*Wv)^T + attn*bv
// Side stream runs transpose_xs + tv-conv under the spatial score chain.
// mbias fused into spatial softmax; rowsum reduces fused into matvecs.
// ===========================================================================

__device__ uint32_t g_xh[65536L * 128];                               // x hi, s-major
__device__ uint32_t g_xth[16L * 256 * 2048], g_xtl[16L * 256 * 2048]; // x^T planes
__device__ uint32_t g_xsh[16L * 256 * 2048], g_xsl[16L * 256 * 2048]; // x^T sigma-perm
__device__ uint32_t g_x1th[16L * 256 * 2048], g_x1tl[16L * 256 * 2048];
__device__ uint32_t g_wh[6 * 32768], g_wl[6 * 32768];
__device__ uint32_t g_wvth[32768];                                    // sv_w^T hi
__device__ uint32_t g_vh[16L * 4096 * 128];
__device__ uint32_t g_M1h[16L * 256 * 128];
__device__ float    g_attnP[64L * 65536];
__device__ uint32_t g_attnB[16L * 256 * 128];
__device__ uint32_t g_Gh[16L * 256 * 128], g_Gl[16L * 256 * 128];
__device__ uint32_t g_PTh[16L * 256 * 128], g_PTl[16L * 256 * 128];
__device__ float    g_sxP[32 * 4096], g_sx1P[32 * 4096];
__device__ float    g_mb[4096];
__device__ float    g_us[4096], g_vs[4096], g_ut[4096], g_vt[4096];

#define CP16(dst, src) asm volatile("cp.async.cg.shared.global [%0], [%1], 16;\n" :: "r"(dst), "l"(src))
#define CPCOMMIT()     asm volatile("cp.async.commit_group;\n" ::: "memory")
#define CPWAIT(n)      asm volatile("cp.async.wait_group %0;\n" :: "n"(n) : "memory")

#define LDSM4(d0, d1, d2, d3, a) \
    asm volatile("ldmatrix.sync.aligned.m8n8.x4.shared.b16 {%0,%1,%2,%3}, [%4];" \
        : "=r"(d0), "=r"(d1), "=r"(d2), "=r"(d3) : "r"(a))

__device__ __forceinline__ uint32_t pack_hi(float v0, float v1) {
    uint32_t h;
    asm("cvt.rn.bf16x2.f32 %0, %1, %2;" : "=r"(h) : "f"(v1), "f"(v0));
    return h;  // lo half = v0
}
__device__ __forceinline__ void pack_pair(float v0, float v1, uint32_t& h, uint32_t& l) {
    h = pack_hi(v0, v1);
    const float h0 = __uint_as_float(h << 16);
    const float h1 = __uint_as_float(h & 0xFFFF0000u);
    l = pack_hi(v0 - h0, v1 - h1);
}

#define MMA_BF16(ac, a0, a1, a2, a3, b0, b1) \
    asm volatile("mma.sync.aligned.m16n8k16.row.col.f32.bf16.bf16.f32 " \
        "{%0,%1,%2,%3},{%4,%5,%6,%7},{%8,%9},{%0,%1,%2,%3};" \
        : "+f"((ac)[0]), "+f"((ac)[1]), "+f"((ac)[2]), "+f"((ac)[3]) \
        : "r"(a0), "r"(a1), "r"(a2), "r"(a3), "r"(b0), "r"(b1))

// ---------------------------------------------------------------------------
// NT GEMM over packed-bf16 planes. NPASS: 1 = AhBh; 3 = +AhBl+AlBh.
//  AMODE 0 plain | 2 v2-gather.
//  EMODE 0 hi-plane+bias | 2 fp32 scores | 3 gamma*(acc+bias?)+res
//        | 4 transposed planes | 5 z-batched hi plane.
//  DUAL (EMODE3): also write x1^T planes + column-sum partials.
//  SYMM: skip block (1,0).
template <int NPASS, int BPL, int AMODE, int EMODE, bool DUAL, bool SYMM>
__global__ __launch_bounds__(256, 2) void gemm(
    const uint32_t* __restrict__ aH, const uint32_t* __restrict__ aL, int aW, long aZ,
    const uint32_t* __restrict__ bH, const uint32_t* __restrict__ bL, int bW, long bZ,
    int KdimW,
    const float* __restrict__ bias, const float* __restrict__ gammaPtr,
    const float* __restrict__ res, int ldr,
    float* __restrict__ outF, uint32_t* __restrict__ outH, uint32_t* __restrict__ outL)
{
    if (SYMM && blockIdx.x == 1 && blockIdx.y == 0) return;

    extern __shared__ uint32_t sm[];
    constexpr int ALD = 20;
    constexpr int APL = (NPASS >= 2) ? 2 : 1;
    constexpr int STAGEW = (APL * 128 + BPL * 128) * ALD;
    constexpr int NSTAGE = (STAGEW > 8192) ? 2 : 3;
    const uint32_t sbB = (uint32_t)__cvta_generic_to_shared(sm);

    const int tid = threadIdx.x;
    const int wid = tid >> 5, lane = tid & 31;
    const int grp = lane >> 2, tig = lane & 3;
    const int row0 = blockIdx.x * 128, col0 = blockIdx.y * 128;
    const int z = blockIdx.z;
    int zA = z;
    long koffW = 0;
    if (EMODE == 2) { zA = z & 15; koffW = (long)(z >> 4) * KdimW; }

    constexpr int MI = 4;
    const int m_base = (wid >> 2) * 64;
    const int n_base = (wid & 3) * 32;

    float acc[MI][4][4];
#pragma unroll
    for (int mi = 0; mi < MI; mi++)
#pragma unroll
        for (int ni = 0; ni < 4; ni++)
#pragma unroll
            for (int e = 0; e < 4; e++) acc[mi][ni][e] = 0.f;

    const int ar = tid >> 1, hw = (tid & 1) * 8;
    long arow;
    long astep = 16;
    if (AMODE == 0) {
        arow = (long)zA * aZ + (long)(row0 + ar) * aW + koffW + hw;
    } else {  // v2 gather
        const int bq = z >> 3, chHi = z & 7;
        arow = ((long)(bq * 8) * 4096 + (row0 + ar)) * 128 + chHi * 16 + hw;
        astep = 4096L * 128;
    }
    const int bn = tid >> 1, hwB = (tid & 1) * 8;
    const long brow = (long)zA * bZ + (long)(col0 + bn) * bW + koffW + hwB;

    const int nCh = KdimW >> 4;
    const uint32_t ALo = 128 * ALD;
    const uint32_t BHo = APL * 128 * ALD;
    const uint32_t BLo = BHo + 128 * ALD;

    auto load_tile = [&](int kc, int s) {
        const long ka = arow + (long)kc * astep;
        const long kb = brow + (long)kc * 16;
        const uint32_t aD = sbB + (uint32_t)(s * STAGEW + ar * ALD + hw) * 4u;
        CP16(aD, aH + ka); CP16(aD + 16u, aH + ka + 4);
        if (APL == 2) {
            const uint32_t aD2 = aD + ALo * 4u;
            CP16(aD2, aL + ka); CP16(aD2 + 16u, aL + ka + 4);
        }
        const uint32_t bD = sbB + (uint32_t)(s * STAGEW + BHo + bn * ALD + hwB) * 4u;
        CP16(bD, bH + kb); CP16(bD + 16u, bH + kb + 4);
        if (BPL == 2) {
            const uint32_t bD2 = sbB + (uint32_t)(s * STAGEW + BLo + bn * ALD + hwB) * 4u;
            CP16(bD2, bL + kb); CP16(bD2 + 16u, bL + kb + 4);
        }
    };

    const int la7 = lane & 7, lg = lane >> 3;
    const uint32_t aoff = (uint32_t)(((m_base + la7 + ((lg & 1) << 3)) * ALD
                                      + ((lg >> 1) << 2)) * 4);
    const uint32_t boff = (uint32_t)(((n_base + la7 + ((lg >> 1) << 3)) * ALD
                                      + ((lg & 1) << 2)) * 4);

    auto compute = [&](int s) {
        const uint32_t stB = sbB + (uint32_t)(s * STAGEW) * 4u;
#pragma unroll
        for (int ks = 0; ks < 2; ks++) {
            const uint32_t kby = (uint32_t)(ks * 32);
            uint32_t bh[4][2], bl[4][2];
#pragma unroll
            for (int p = 0; p < 2; p++) {
                const uint32_t ba = stB + BHo * 4u + boff + (uint32_t)(p * 16 * ALD * 4) + kby;
                LDSM4(bh[2 * p][0], bh[2 * p][1], bh[2 * p + 1][0], bh[2 * p + 1][1], ba);
                if (BPL == 2) {
                    const uint32_t ba2 = stB + BLo * 4u + boff + (uint32_t)(p * 16 * ALD * 4) + kby;
                    LDSM4(bl[2 * p][0], bl[2 * p][1], bl[2 * p + 1][0], bl[2 * p + 1][1], ba2);
                }
            }
#pragma unroll
            for (int mi = 0; mi < MI; mi++) {
                const uint32_t aa = stB + aoff + (uint32_t)(mi * 16 * ALD * 4) + kby;
                uint32_t ah0, ah1, ah2, ah3;
                LDSM4(ah0, ah1, ah2, ah3, aa);
#pragma unroll
                for (int ni = 0; ni < 4; ni++)
                    MMA_BF16(acc[mi][ni], ah0, ah1, ah2, ah3, bh[ni][0], bh[ni][1]);
                if (NPASS == 3) {
#pragma unroll
                    for (int ni = 0; ni < 4; ni++)
                        MMA_BF16(acc[mi][ni], ah0, ah1, ah2, ah3, bl[ni][0], bl[ni][1]);
                }
                if (NPASS >= 2) {
                    uint32_t al0, al1, al2, al3;
                    LDSM4(al0, al1, al2, al3, aa + ALo * 4u);
#pragma unroll
                    for (int ni = 0; ni < 4; ni++)
                        MMA_BF16(acc[mi][ni], al0, al1, al2, al3, bh[ni][0], bh[ni][1]);
                }
            }
        }
    };

    load_tile(0, 0); CPCOMMIT();
    if (nCh > 1) load_tile(1, 1);
    CPCOMMIT();
    if (NSTAGE == 2) {
        for (int kc = 0; kc < nCh; kc++) {
            CPWAIT(1);
            __syncthreads();
            compute(kc & 1);
            __syncthreads();
            if (kc + 2 < nCh) { load_tile(kc + 2, kc & 1); CPCOMMIT(); }
        }
    } else {
        for (int kc = 0; kc < nCh; kc++) {
            CPWAIT(1);
            __syncthreads();
            const int ld = kc + 2;
            if (ld < nCh) load_tile(ld, ld % 3);
            CPCOMMIT();
            compute(kc % 3);
        }
    }

    // ---- epilogues ----
    if (EMODE == 4) {
        __syncthreads();
        float* sC = (float*)sm;
#pragma unroll
        for (int mi = 0; mi < MI; mi++)
#pragma unroll
            for (int ni = 0; ni < 4; ni++) {
                const int r0 = m_base + mi * 16 + grp;
                const int cb = n_base + ni * 8 + 2 * tig;
                sC[r0 * 133 + cb] = acc[mi][ni][0];
                sC[r0 * 133 + cb + 1] = acc[mi][ni][1];
                sC[(r0 + 8) * 133 + cb] = acc[mi][ni][2];
                sC[(r0 + 8) * 133 + cb + 1] = acc[mi][ni][3];
            }
        __syncthreads();
        const int p = tid & 63, colg = tid >> 6;
        for (int cp = 0; cp < 32; cp++) {
            const int col = cp * 4 + colg;
            uint32_t h, l;
            pack_pair(sC[(2 * p) * 133 + col], sC[(2 * p + 1) * 133 + col], h, l);
            const long w = ((long)(z * 256 + col0 + col)) * 128 + (row0 >> 1) + p;
            outH[w] = h; outL[w] = l;
        }
    } else if (EMODE == 3 && DUAL) {
        const float gamma = __ldg(gammaPtr);
        __syncthreads();
        float* sC = (float*)sm;
#pragma unroll
        for (int mi = 0; mi < MI; mi++)
#pragma unroll
            for (int ni = 0; ni < 4; ni++) {
                const int r0g = m_base + mi * 16 + grp;
                const int cb = n_base + ni * 8 + 2 * tig;
                const int c = col0 + cb;
#pragma unroll
                for (int half = 0; half < 2; half++) {
                    const int rl = r0g + half * 8;
                    const long rr = (long)z * 4096 + row0 + rl;
                    float a0 = acc[mi][ni][2 * half];
                    float a1 = acc[mi][ni][2 * half + 1];
                    if (bias) {
                        a0 += __ldg(&bias[z * 256 + c]);
                        a1 += __ldg(&bias[z * 256 + c + 1]);
                    }
                    float v0 = gamma * a0 + res[rr * (long)ldr + c];
                    float v1 = gamma * a1 + res[rr * (long)ldr + c + 1];
                    float2 st = {v0, v1};
                    *(float2*)(outF + rr * 256 + c) = st;
                    sC[rl * 133 + cb] = v0;
                    sC[rl * 133 + cb + 1] = v1;
                }
            }
        __syncthreads();
        const int p = tid & 63, colg = tid >> 6;
        for (int cp = 0; cp < 32; cp++) {
            const int col = cp * 4 + colg;
            uint32_t h, l;
            pack_pair(sC[(2 * p) * 133 + col], sC[(2 * p + 1) * 133 + col], h, l);
            const long w = ((long)(z * 256 + col0 + col)) * 2048 + (row0 >> 1) + p;
            outH[w] = h; outL[w] = l;
        }
        // column-sum partials of x1 tile -> g_sx1P[st][z*256+col0+col]
        {
            float* part = sC + 128 * 133;
            const int col = tid & 127, hf = tid >> 7;
            float s = 0.f;
#pragma unroll 4
            for (int r = hf * 64; r < hf * 64 + 64; r++) s += sC[r * 133 + col];
            part[hf * 128 + col] = s;
            __syncthreads();
            if (tid < 128)
                g_sx1P[(long)blockIdx.x * 4096 + z * 256 + col0 + tid]
                    = part[tid] + part[128 + tid];
        }
    } else {
        float gamma = 0.f;
        if (EMODE == 3) gamma = __ldg(gammaPtr);
#pragma unroll
        for (int mi = 0; mi < MI; mi++)
#pragma unroll
            for (int ni = 0; ni < 4; ni++) {
                const int r0g = m_base + mi * 16 + grp;
                const int cb = n_base + ni * 8 + 2 * tig;
                const int c = col0 + cb;
#pragma unroll
                for (int half = 0; half < 2; half++) {
                    const int r = row0 + r0g + half * 8;
                    float v0 = acc[mi][ni][2 * half];
                    float v1 = acc[mi][ni][2 * half + 1];
                    if (EMODE == 0) {
                        v0 += __ldg(&bias[c]);
                        v1 += __ldg(&bias[c + 1]);
                        outH[(long)r * 128 + (c >> 1)] = pack_hi(v0, v1);
                    } else if (EMODE == 5) {
                        outH[((long)z * 256 + r) * 128 + (c >> 1)] = pack_hi(v0, v1);
                    } else if (EMODE == 2) {
                        float2 st = {v0, v1};
                        *(float2*)(outF + (long)z * 65536 + (long)r * 256 + c) = st;
                    } else {
                        const long rr = (long)z * 4096 + r;
                        if (bias) {
                            v0 += __ldg(&bias[z * 256 + c]);
                            v1 += __ldg(&bias[z * 256 + c + 1]);
                        }
                        v0 = gamma * v0 + res[rr * (long)ldr + c];
                        v1 = gamma * v1 + res[rr * (long)ldr + c + 1];
                        float2 st = {v0, v1};
                        *(float2*)(outF + rr * 256 + c) = st;
                    }
                }
            }
    }
}

// ---------------- fused: x -> xh + xth/xtl planes + rowsum partials --------
__global__ __launch_bounds__(256) void prep_x(const float* __restrict__ x) {
    __shared__ float tile[128][65];
    __shared__ float colp[4][64];
    const int st = blockIdx.x, ct = blockIdx.y, z = blockIdx.z;
    const int t = threadIdx.x;
    const int col = t & 63, r4 = t >> 6;
    const long base = ((long)z * 4096 + st * 128) * 259 + ct * 64;
#pragma unroll
    for (int j = 0; j < 32; j++) {
        const int row = r4 + j * 4;
        tile[row][col] = x[base + (long)row * 259 + col];
    }
    __syncthreads();
#pragma unroll
    for (int k = 0; k < 16; k++) {
        const int idx = t + k * 256;
        const int row = idx >> 5, jw = idx & 31;
        g_xh[((long)z * 4096 + st * 128 + row) * 128 + ct * 32 + jw]
            = pack_hi(tile[row][2 * jw], tile[row][2 * jw + 1]);
    }
#pragma unroll
    for (int k = 0; k < 16; k++) {
        const int idx = t + k * 256;
        const int c = idx >> 6, p = idx & 63;
        uint32_t h, l;
        pack_pair(tile[2 * p][c], tile[2 * p + 1][c], h, l);
        const long w = ((long)z * 256 + ct * 64 + c) * 2048 + st * 64 + p;
        g_xth[w] = h; g_xtl[w] = l;
    }
    {
        float s = 0.f;
#pragma unroll 4
        for (int r = r4 * 32; r < r4 * 32 + 32; r++) s += tile[r][col];
        colp[r4][col] = s;
        __syncthreads();
        if (t < 64)
            g_sxP[(long)st * 4096 + z * 256 + ct * 64 + t]
                = colp[0][t] + colp[1][t] + colp[2][t] + colp[3][t];
    }
}

// ---------------- sigma-permuted x^T planes ---------------------------------
__global__ __launch_bounds__(256) void transpose_xs(const float* __restrict__ x) {
    __shared__ float tile[64][65];
    const int st = blockIdx.x, ct = blockIdx.y, z = blockIdx.z;
    const int t = threadIdx.x;
#pragma unroll
    for (int j = 0; j < 16; j++) {
        const int i = (t >> 6) + j * 4;
        const int col = t & 63;
        tile[i][col] = x[((long)(z * 4096 + i * 64 + st)) * 259 + ct * 64 + col];
    }
    __syncthreads();
#pragma unroll
    for (int j = 0; j < 8; j++) {
        const int cl = (t >> 5) + j * 8;
        const int wi = t & 31;
        uint32_t h, l;
        pack_pair(tile[2 * wi][cl], tile[2 * wi + 1][cl], h, l);
        const long w = ((long)(z * 256 + ct * 64 + cl)) * 2048 + st * 32 + wi;
        g_xsh[w] = h; g_xsl[w] = l;
    }
}

// ---------------- weights -> planes (+ sv^T hi plane) -----------------------
__global__ __launch_bounds__(256) void prep_w(const float* w0, const float* w1,
                                              const float* w2, const float* w3,
                                              const float* w4, const float* w5) {
    const int id = blockIdx.x * 256 + threadIdx.x;
    if (id < 6 * 32768) {
        const int m = id >> 15, rc = id & 32767;
        const float* w = (m == 0) ? w0 : (m == 1) ? w1 : (m == 2) ? w2
                       : (m == 3) ? w3 : (m == 4) ? w4 : w5;
        uint32_t h, l;
        pack_pair(w[rc * 2], w[rc * 2 + 1], h, l);
        g_wh[id] = h; g_wl[id] = l;
    } else {
        const int id2 = id - 6 * 32768;   // sv^T: [e][d-words]
        const int e = id2 >> 7, dw = id2 & 127;
        g_wvth[id2] = pack_hi(w2[(2 * dw) * 256 + e], w2[(2 * dw + 1) * 256 + e]);
    }
}

// ---------------- matvec with fused 32-way partial reduce -------------------
__global__ __launch_bounds__(256) void matvec3r(const float* Wa, const float* Wb,
                                                const float* Wc,
                                                const float* __restrict__ P,
                                                float* oa, float* ob, float* oc) {
    __shared__ float sx[256];
    const int z = blockIdx.x, d = threadIdx.x, m = blockIdx.y;
    float s0 = 0.f;
#pragma unroll 8
    for (int j = 0; j < 32; j++) s0 += P[(long)j * 4096 + z * 256 + d];
    sx[d] = s0;
    __syncthreads();
    const float* W = (m == 0) ? Wa : (m == 1) ? Wb : Wc;
    float* o = (m == 0) ? oa : (m == 1) ? ob : oc;
    const float* w = W + (long)d * 256;
    float s = 0.f;
    for (int c = 0; c < 256; c++) s += w[c] * sx[c];
    o[z * 256 + d] = s;
}
__global__ __launch_bounds__(256) void matvecr(const float* __restrict__ W,
                                               const float* __restrict__ P,
                                               float* __restrict__ o) {
    __shared__ float sx[256];
    const int z = blockIdx.x, d = threadIdx.x;
    float s0 = 0.f;
#pragma unroll 8
    for (int j = 0; j < 32; j++) s0 += P[(long)j * 4096 + z * 256 + d];
    sx[d] = s0;
    __syncthreads();
    const float* w = W + (long)d * 256;
    float s = 0.f;
    for (int c = 0; c < 256; c++) s += w[c] * sx[c];
    o[z * 256 + d] = s;
}

// ---------------- sum 4 split-K partials -> packed planes (opt. mirror) ----
template <bool MIRROR>
__global__ __launch_bounds__(256) void combine_pack(const float* __restrict__ P,
                                                    uint32_t* __restrict__ gh,
                                                    uint32_t* __restrict__ gl) {
    const long i = (long)blockIdx.x * 256 + threadIdx.x;
    const int z = (int)(i >> 15);
    const int r = (int)(i & 32767);
    const int c = r >> 7, dw = r & 127;
    float v0, v1;
    if (MIRROR && c >= 128 && dw < 64) {
        const long e0 = (long)z * 65536 + (2 * dw) * 256 + c;
        const long e1 = e0 + 256;
        v0 = P[e0] + P[e0 + 1048576] + P[e0 + 2097152] + P[e0 + 3145728];
        v1 = P[e1] + P[e1 + 1048576] + P[e1 + 2097152] + P[e1 + 3145728];
    } else {
        const long e = (long)z * 65536 + c * 256 + 2 * dw;
        v0 = P[e] + P[e + 1048576] + P[e + 2097152] + P[e + 3145728];
        v1 = P[e + 1] + P[e + 1 + 1048576] + P[e + 1 + 2097152] + P[e + 1 + 3145728];
    }
    uint32_t h, l;
    pack_pair(v0, v1, h, l);
    gh[i] = h; gl[i] = l;
}

// ---------------- softmax with rank-1 terms, pack; opt. fused mbias --------
template <bool PERM, bool MBIAS>
__global__ __launch_bounds__(256) void softmax_rank1(
    const float* __restrict__ S, const float* __restrict__ u,
    const float* __restrict__ vvec, const float* __restrict__ bq,
    const float* __restrict__ bk, uint32_t* __restrict__ O,
    const float* __restrict__ bv, float* __restrict__ mbOut)
{
    __shared__ float srow[8][256];
    const int wid = threadIdx.x >> 5, lane = threadIdx.x & 31;
    const int row = blockIdx.x * 8 + wid;
    const int z = row >> 8, c = row & 255;
    const float bqc = bq[c], vc = vvec[z * 256 + c];
    const float* p = S + (long)row * 256;
    float vv[8];
    float mx = -1e30f;
#pragma unroll
    for (int j = 0; j < 8; j++) {
        const int d = lane * 8 + j;
        const float bkd = bk[d];
        vv[j] = p[d] + bqc * (u[z * 256 + d] + 4096.f * bkd) + bkd * vc;
        mx = fmaxf(mx, vv[j]);
    }
#pragma unroll
    for (int o = 16; o; o >>= 1) mx = fmaxf(mx, __shfl_xor_sync(0xffffffffu, mx, o));
    float s = 0.f;
#pragma unroll
    for (int j = 0; j < 8; j++) { vv[j] = __expf(vv[j] - mx); s += vv[j]; }
#pragma unroll
    for (int o = 16; o; o >>= 1) s += __shfl_xor_sync(0xffffffffu, s, o);
    const float inv = 1.f / s;
#pragma unroll
    for (int j = 0; j < 8; j++) srow[wid][lane * 8 + j] = vv[j] * inv;
    __syncwarp();
    if (MBIAS) {
        float mb = 0.f;
#pragma unroll
        for (int j = 0; j < 8; j++) {
            const int d = lane * 8 + j;
            mb += srow[wid][d] * __ldg(&bv[d]);
        }
#pragma unroll
        for (int o = 16; o; o >>= 1) mb += __shfl_xor_sync(0xffffffffu, mb, o);
        if (lane == 0) mbOut[row] = mb;
    }
#pragma unroll
    for (int t = 0; t < 4; t++) {
        const int m = lane * 4 + t;
        int d0 = 2 * m, d1 = 2 * m + 1;
        if (PERM) {
            d0 = ((d0 & 31) << 3) | (d0 >> 5);
            d1 = ((d1 & 31) << 3) | (d1 >> 5);
        }
        O[(long)row * 128 + m] = pack_hi(srow[wid][d0], srow[wid][d1]);
    }
}

// ---------------- launch ----------------------------------------------------
extern "C" void kernel_launch(void* const* d_in, const int* in_sizes, int n_in,
                              void* d_out, int out_size)
{
    const float* x    = (const float*)d_in[0];
    const float* sq_w = (const float*)d_in[3];
    const float* sq_b = (const float*)d_in[4];
    const float* sk_w = (const float*)d_in[5];
    const float* sk_b = (const float*)d_in[6];
    const float* sv_w = (const float*)d_in[7];
    const float* sv_b = (const float*)d_in[8];
    const float* tq_w = (const float*)d_in[9];
    const float* tq_b = (const float*)d_in[10];
    const float* tk_w = (const float*)d_in[11];
    const float* tk_b = (const float*)d_in[12];
    const float* tv_w = (const float*)d_in[13];
    const float* tv_b = (const float*)d_in[14];
    const float* s_gamma = (const float*)d_in[15];
    const float* t_gamma = (const float*)d_in[16];
    float* out = (float*)d_out;

    uint32_t *xh, *xth, *xtl, *xsh, *xsl, *x1th, *x1tl, *wh, *wl, *wvth;
    uint32_t *vh, *M1h, *attnB, *Gh, *Gl, *PTh, *PTl;
    float *attnP, *sxP, *sx1P, *mb, *us, *vs, *ut, *vt;
    cudaGetSymbolAddress((void**)&xh, g_xh);
    cudaGetSymbolAddress((void**)&xth, g_xth);   cudaGetSymbolAddress((void**)&xtl, g_xtl);
    cudaGetSymbolAddress((void**)&xsh, g_xsh);   cudaGetSymbolAddress((void**)&xsl, g_xsl);
    cudaGetSymbolAddress((void**)&x1th, g_x1th); cudaGetSymbolAddress((void**)&x1tl, g_x1tl);
    cudaGetSymbolAddress((void**)&wh, g_wh);     cudaGetSymbolAddress((void**)&wl, g_wl);
    cudaGetSymbolAddress((void**)&wvth, g_wvth);
    cudaGetSymbolAddress((void**)&vh, g_vh);     cudaGetSymbolAddress((void**)&M1h, g_M1h);
    cudaGetSymbolAddress((void**)&attnP, g_attnP);
    cudaGetSymbolAddress((void**)&attnB, g_attnB);
    cudaGetSymbolAddress((void**)&Gh, g_Gh);     cudaGetSymbolAddress((void**)&Gl, g_Gl);
    cudaGetSymbolAddress((void**)&PTh, g_PTh);   cudaGetSymbolAddress((void**)&PTl, g_PTl);
    cudaGetSymbolAddress((void**)&sxP, g_sxP);   cudaGetSymbolAddress((void**)&sx1P, g_sx1P);
    cudaGetSymbolAddress((void**)&mb, g_mb);
    cudaGetSymbolAddress((void**)&us, g_us);     cudaGetSymbolAddress((void**)&vs, g_vs);
    cudaGetSymbolAddress((void**)&ut, g_ut);     cudaGetSymbolAddress((void**)&vt, g_vt);

    auto convV = gemm<1, 1, 0, 0, false, false>;   // tv conv (1-pass hi)
    auto bigG  = gemm<3, 2, 0, 2, false, true>;    // G (symmetric, split-K=4)
    auto bigH  = gemm<3, 2, 0, 2, false, false>;   // H (split-K=4) and S GEMMs
    auto Pk    = gemm<3, 2, 0, 4, false, false>;   // G/H * Wk^T -> P^T planes
    auto m1k   = gemm<1, 1, 0, 5, false, false>;   // M1 = attn * Wv^T
    auto outV1 = gemm<1, 1, 0, 3, true, false>;    // spatial out (X*M1^T, +x1 planes)
    auto outV2 = gemm<1, 1, 2, 3, false, false>;   // temporal out (v2 gather)

    const int SMC = 3 * (128 + 128) * 20 * 4;      // 61440
    const int SMG = 2 * (256 + 256) * 20 * 4;      // 81920
    const int SMO = 70656;                         // outV1 (sC + partials)
    cudaFuncSetAttribute(convV, cudaFuncAttributeMaxDynamicSharedMemorySize, SMC);
    cudaFuncSetAttribute(bigG,  cudaFuncAttributeMaxDynamicSharedMemorySize, SMG);
    cudaFuncSetAttribute(bigH,  cudaFuncAttributeMaxDynamicSharedMemorySize, SMG);
    cudaFuncSetAttribute(Pk,    cudaFuncAttributeMaxDynamicSharedMemorySize, SMG);
    cudaFuncSetAttribute(m1k,   cudaFuncAttributeMaxDynamicSharedMemorySize, SMC);
    cudaFuncSetAttribute(outV1, cudaFuncAttributeMaxDynamicSharedMemorySize, SMO);
    cudaFuncSetAttribute(outV2, cudaFuncAttributeMaxDynamicSharedMemorySize, SMC);

    const dim3 px(32, 4, 16);
    const dim3 ts(64, 4, 16);
    const dim3 cg(512, 2, 1);
    const dim3 gg(2, 2, 64);
    const dim3 pg(2, 2, 16);
    const dim3 og(32, 2, 16);

    // fork resources (host-side only; created fresh per call, leaked — 2 calls total)
    cudaStream_t side;
    cudaStreamCreateWithFlags(&side, cudaStreamNonBlocking);
    cudaEvent_t e1, e2;
    cudaEventCreateWithFlags(&e1, cudaEventDisableTiming);
    cudaEventCreateWithFlags(&e2, cudaEventDisableTiming);

    prep_x<<<px, 256>>>(x);
    prep_w<<<896, 256>>>(sq_w, sk_w, sv_w, tq_w, tk_w, tv_w);
    matvec3r<<<dim3(16, 3), 256>>>(sk_w, sq_w, tk_w, sxP, us, vs, ut);

    // ---- fork: temporal prep on side stream, overlapping spatial chain ----
    cudaEventRecord(e1, 0);
    cudaStreamWaitEvent(side, e1, 0);
    transpose_xs<<<ts, 256, 0, side>>>(x);
    convV<<<cg, 256, SMC, side>>>(xh, nullptr, 128, 0, wh + 5 * 32768, nullptr, 128, 0, 128,
                                  tv_b, nullptr, nullptr, 0, nullptr, vh, nullptr);
    cudaEventRecord(e2, side);

    // ---- spatial (default stream) ----
    bigG<<<gg, 256, SMG>>>(xth, xtl, 2048, 524288L, xth, xtl, 2048, 524288L, 512,
                           nullptr, nullptr, nullptr, 0, attnP, nullptr, nullptr);
    combine_pack<true><<<2048, 256>>>(attnP, Gh, Gl);
    Pk<<<pg, 256, SMG>>>(Gh, Gl, 128, 32768L, wh + 1 * 32768, wl + 1 * 32768, 128, 0, 128,
                         nullptr, nullptr, nullptr, 0, nullptr, PTh, PTl);
    bigH<<<pg, 256, SMG>>>(wh + 0 * 32768, wl + 0 * 32768, 128, 0, PTh, PTl, 128, 32768L, 128,
                           nullptr, nullptr, nullptr, 0, attnP, nullptr, nullptr);
    softmax_rank1<false, true><<<512, 256>>>(attnP, us, vs, sq_b, sk_b, attnB, sv_b, mb);
    m1k<<<pg, 256, SMC>>>(attnB, nullptr, 128, 32768L, wvth, nullptr, 128, 0, 128,
                          nullptr, nullptr, nullptr, 0, nullptr, M1h, nullptr);
    outV1<<<og, 256, SMO>>>(xh, nullptr, 128, 524288L, M1h, nullptr, 128, 32768L, 128,
                            mb, s_gamma, x, 259, out, x1th, x1tl);

    // ---- temporal ----
    matvecr<<<16, 256>>>(tq_w, sx1P, vt);
    cudaStreamWaitEvent(0, e2, 0);   // join: needs xsh (transpose_xs) + vh (convV)
    bigH<<<gg, 256, SMG>>>(x1th, x1tl, 2048, 524288L, xsh, xsl, 2048, 524288L, 512,
                           nullptr, nullptr, nullptr, 0, attnP, nullptr, nullptr);
    combine_pack<false><<<2048, 256>>>(attnP, Gh, Gl);
    Pk<<<pg, 256, SMG>>>(Gh, Gl, 128, 32768L, wh + 4 * 32768, wl + 4 * 32768, 128, 0, 128,
                         nullptr, nullptr, nullptr, 0, nullptr, PTh, PTl);
    bigH<<<pg, 256, SMG>>>(wh + 3 * 32768, wl + 3 * 32768, 128, 0, PTh, PTl, 128, 32768L, 128,
                           nullptr, nullptr, nullptr, 0, attnP, nullptr, nullptr);
    softmax_rank1<true, false><<<512, 256>>>(attnP, ut, vt, tq_b, tk_b, attnB, nullptr, nullptr);
    outV2<<<og, 256, SMC>>>(vh, nullptr, 128, 0, attnB, nullptr, 128, 32768L, 128,
                            nullptr, t_gamma, out, 256, out, nullptr, nullptr);
}